// round 10
// baseline (speedup 1.0000x reference)
#include <cuda_runtime.h>
#include <cuda_bf16.h>
#include <cuda_fp16.h>
#include <cstdint>
#include <cstddef>

#define Bq 2
#define Lq 4096
#define Dq 2048
#define Hq 16
#define Dh 128
#define Cq 64
#define Nq (Lq / Cq)
#define KW 4
#define BLq (Bq * Lq)
#define EPSq 1e-5f

#define GNC 64                // 2 * 32 K-chunks of 64 (fp16 split-2)

// ---------------- device scratch buffers ----------------
#define BLD (BLq * Dq)
#define BHL (Bq * Hq * Lq)
#define WROWS (5 * Dq)

__device__ float g_proj[(size_t)BLq * 4 * Dq];
__device__ float g_obuf[BLD];
__device__ float g_qn[BLD];
__device__ float g_kn[BLD];
__device__ float g_vn[BLD];
__device__ float g_beta[BHL];
__device__ float g_gdec[BHL];

__device__ __half g_xh[(size_t)BLq * Dq];
__device__ __half g_whi[(size_t)WROWS * Dq];
__device__ __half g_wlo[(size_t)WROWS * Dq];

// ================= helpers =================
__device__ __forceinline__ uint32_t smem_u32(const void* p) {
    uint32_t a;
    asm("{ .reg .u64 t; cvta.to.shared.u64 t, %1; cvt.u32.u64 %0, t; }" : "=r"(a) : "l"(p));
    return a;
}
#define SWZ(x) ((x) ^ (((x) >> 3) & 0x70))

__device__ __forceinline__ void cp16(uint32_t dst, const void* src) {
    asm volatile("cp.async.cg.shared.global [%0], [%1], 16;" :: "r"(dst), "l"(src));
}
__device__ __forceinline__ void ldsm_x4(uint32_t& r0, uint32_t& r1, uint32_t& r2,
                                        uint32_t& r3, uint32_t a) {
    asm volatile("ldmatrix.sync.aligned.m8n8.x4.shared.b16 {%0,%1,%2,%3}, [%4];"
                 : "=r"(r0), "=r"(r1), "=r"(r2), "=r"(r3) : "r"(a));
}
__device__ __forceinline__ void mma16816(float* d, const uint32_t* a, const uint32_t* b) {
    asm volatile("mma.sync.aligned.m16n8k16.row.col.f32.f16.f16.f32 "
                 "{%0,%1,%2,%3}, {%4,%5,%6,%7}, {%8,%9}, {%0,%1,%2,%3};"
                 : "+f"(d[0]), "+f"(d[1]), "+f"(d[2]), "+f"(d[3])
                 : "r"(a[0]), "r"(a[1]), "r"(a[2]), "r"(a[3]), "r"(b[0]), "r"(b[1]));
}
__device__ __forceinline__ float dot4(float4 a, float4 b) {
    return a.x * b.x + a.y * b.y + a.z * b.z + a.w * b.w;
}

// ---------------- fp32 -> fp16 cast (activations), x4 vectorized ----------------
__global__ void cast_f16(const float4* __restrict__ in, __half2* __restrict__ out)
{
    size_t idx = (size_t)blockIdx.x * blockDim.x + threadIdx.x;
    float4 a = in[idx];
    out[idx * 2]     = __floats2half2_rn(a.x, a.y);
    out[idx * 2 + 1] = __floats2half2_rn(a.z, a.w);
}

// ---------------- fp32 -> fp16 hi + lo (weights), x4 vectorized ----------------
__global__ void split2_f16(const float4* __restrict__ in, __half2* __restrict__ hi,
                           __half2* __restrict__ lo)
{
    size_t idx = (size_t)blockIdx.x * blockDim.x + threadIdx.x;
    float4 a = in[idx];
    __half2 h0 = __floats2half2_rn(a.x, a.y);
    __half2 h1 = __floats2half2_rn(a.z, a.w);
    hi[idx * 2]     = h0;
    hi[idx * 2 + 1] = h1;
    lo[idx * 2]     = __floats2half2_rn(a.x - __low2float(h0),  a.y - __high2float(h0));
    lo[idx * 2 + 1] = __floats2half2_rn(a.z - __low2float(h1),  a.w - __high2float(h1));
}

// ---------------- HMMA GEMM, fp16 split-2 chunk routing --------------------
// C[M, ldc] = A[M,2048](fp16) * (Whi ⊕ Wlo)[N,2048]^T
// 256x128 CTA tile, 64x64 warp tiles (4x2 warps), BK=64, 4-stage cp.async.
#define STAGE_B 49152
#define GEMM_SMEM_BYTES (4 * STAGE_B)

__global__ __launch_bounds__(256, 1)
void hmma_gemm(const __half* __restrict__ A,
               const __half* __restrict__ Bhi, const __half* __restrict__ Blo,
               float* __restrict__ C, int ldc)
{
    extern __shared__ __align__(128) char smem[];
    const uint32_t sb = smem_u32(smem);
    const int tid = threadIdx.x;
    const int warp = tid >> 5, lane = tid & 31;
    const int wm = warp >> 1, wn = warp & 1;     // 4 x 2 warps of 64x64
    const int bm = blockIdx.y * 256, bn = blockIdx.x * 128;

    float acc[4][8][4];
#pragma unroll
    for (int i = 0; i < 4; i++)
#pragma unroll
        for (int j = 0; j < 8; j++)
#pragma unroll
            for (int r = 0; r < 4; r++) acc[i][j][r] = 0.f;

    const int lrow = tid >> 3;          // 0..31
    const int lseg = tid & 7;
    const uint32_t loff = SWZ(lrow * 128 + lseg * 16);

#define LOAD_STAGE(s, kc) do { \
        int _k0 = ((kc) & 31) * 64; \
        const __half* _Bb = ((kc) >= 32) ? Blo : Bhi; \
        uint32_t _as = sb + (s) * STAGE_B; \
        uint32_t _bs = _as + 32768; \
        const __half* _ap = A + (size_t)(bm + lrow) * Dq + _k0 + lseg * 8; \
        const __half* _bp = _Bb + (size_t)(bn + lrow) * Dq + _k0 + lseg * 8; \
        _Pragma("unroll") \
        for (int _i = 0; _i < 8; _i++) \
            cp16(_as + loff + _i * 4096, _ap + (size_t)_i * 32 * Dq); \
        _Pragma("unroll") \
        for (int _i = 0; _i < 4; _i++) \
            cp16(_bs + loff + _i * 4096, _bp + (size_t)_i * 32 * Dq); \
        asm volatile("cp.async.commit_group;" ::: "memory"); \
    } while (0)

    // A fragment addressing (ldsm x4, m16k16 per m-tile)
    const int aq = lane >> 3;
    const int am = (lane & 7) + (aq & 1) * 8;
    const int akb = (aq >> 1) * 8;
    // B fragment addressing (packed ldsm x4: two n-tiles x two k-blocks)
    const int bln = lane & 7;
    const int bsel = lane >> 3;              // 0..3
    const int bnrow = (bsel >> 1) * 8 + bln; // row offset within 16-row pair
    const int bkoff = (bsel & 1) * 8;        // k-block offset

    LOAD_STAGE(0, 0);
    LOAD_STAGE(1, 1);
    LOAD_STAGE(2, 2);

    for (int c = 0; c < GNC; c++) {
        if (c < GNC - 2) {
            asm volatile("cp.async.wait_group 2;" ::: "memory");
        } else if (c == GNC - 2) {
            asm volatile("cp.async.wait_group 1;" ::: "memory");
        } else {
            asm volatile("cp.async.wait_group 0;" ::: "memory");
        }
        __syncthreads();
        if (c + 3 < GNC) LOAD_STAGE((c + 3) & 3, c + 3);

        const uint32_t As = sb + (c & 3) * STAGE_B;
        const uint32_t Bs = As + 32768;
#pragma unroll
        for (int ks = 0; ks < 4; ks++) {
            const int k0 = ks * 16;
            uint32_t af[4][4];
#pragma unroll
            for (int mt = 0; mt < 4; mt++) {
                int m = wm * 64 + mt * 16 + am;
                ldsm_x4(af[mt][0], af[mt][1], af[mt][2], af[mt][3],
                        As + SWZ(m * 128 + (k0 + akb) * 2));
            }
            uint32_t bf[8][2];
#pragma unroll
            for (int ntp = 0; ntp < 4; ntp++) {
                int n = wn * 64 + ntp * 16 + bnrow;
                ldsm_x4(bf[2 * ntp][0], bf[2 * ntp][1],
                        bf[2 * ntp + 1][0], bf[2 * ntp + 1][1],
                        Bs + SWZ(n * 128 + (k0 + bkoff) * 2));
            }
#pragma unroll
            for (int mt = 0; mt < 4; mt++)
#pragma unroll
                for (int nt = 0; nt < 8; nt++)
                    mma16816(acc[mt][nt], af[mt], bf[nt]);
        }
    }

    const int r0 = bm + wm * 64 + (lane >> 2);
    const int c0 = bn + wn * 64 + (lane & 3) * 2;
#pragma unroll
    for (int mt = 0; mt < 4; mt++) {
#pragma unroll
        for (int nt = 0; nt < 8; nt++) {
            float2* p0 = (float2*)(C + (size_t)(r0 + mt * 16) * ldc + c0 + nt * 8);
            float2* p1 = (float2*)(C + (size_t)(r0 + mt * 16 + 8) * ldc + c0 + nt * 8);
            *p0 = make_float2(acc[mt][nt][0], acc[mt][nt][1]);
            *p1 = make_float2(acc[mt][nt][2], acc[mt][nt][3]);
        }
    }
}

// ---------------- beta / g kernel ----------------
__global__ void betag_kernel(const float* __restrict__ x,
                             const float* __restrict__ Wb,
                             const float* __restrict__ Wa,
                             const float* __restrict__ A_log,
                             const float* __restrict__ dt_bias,
                             float* __restrict__ beta,
                             float* __restrict__ gdec)
{
    const int bl = blockIdx.x;
    const int h = threadIdx.x >> 5;
    const int lane = threadIdx.x & 31;
    const float* xr = x + (size_t)bl * Dq;
    const float* wb = Wb + (size_t)h * Dq;
    const float* wa = Wa + (size_t)h * Dq;
    float sb = 0.f, sa = 0.f;
    for (int i = lane; i < Dq; i += 32) {
        float xv = xr[i];
        sb += xv * wb[i];
        sa += xv * wa[i];
    }
#pragma unroll
    for (int off = 16; off > 0; off >>= 1) {
        sb += __shfl_down_sync(0xffffffffu, sb, off);
        sa += __shfl_down_sync(0xffffffffu, sa, off);
    }
    if (lane == 0) {
        const int b = bl / Lq, l = bl % Lq;
        float bet = 1.f / (1.f + expf(-sb));
        float z = sa + dt_bias[h];
        float sp = (z > 15.f) ? z : log1pf(expf(z));
        float g = -expf(A_log[h]) * sp;
        size_t o = ((size_t)(b * Hq + h)) * Lq + l;
        beta[o] = bet;
        gdec[o] = g;
    }
}

// ---------------- causal dwconv + silu + l2 norm ----------
__global__ void conv_kernel(const float* __restrict__ proj,
                            const float* __restrict__ wq, const float* __restrict__ wk,
                            const float* __restrict__ wv,
                            float* __restrict__ oq, float* __restrict__ ok,
                            float* __restrict__ ov)
{
    const int blk = blockIdx.x;
    const int h = blk % Hq;
    const int bl = blk / Hq;
    const int l = bl % Lq;
    const int d = threadIdx.x;
    const int c = h * Dh + d;

    float aq = 0.f, ak = 0.f, av = 0.f;
#pragma unroll
    for (int j = 0; j < KW; j++) {
        int ll = l - (KW - 1) + j;
        if (ll >= 0) {
            size_t idx = ((size_t)(bl - l + ll)) * (4 * Dq) + c;
            aq += wq[c * KW + j] * proj[idx];
            ak += wk[c * KW + j] * proj[idx + Dq];
            av += wv[c * KW + j] * proj[idx + 2 * Dq];
        }
    }
    aq = aq / (1.f + expf(-aq));
    ak = ak / (1.f + expf(-ak));
    av = av / (1.f + expf(-av));

    float sq = aq * aq, sk = ak * ak;
#pragma unroll
    for (int off = 16; off > 0; off >>= 1) {
        sq += __shfl_xor_sync(0xffffffffu, sq, off);
        sk += __shfl_xor_sync(0xffffffffu, sk, off);
    }
    __shared__ float shq[4], shk[4];
    const int wid = threadIdx.x >> 5;
    if ((threadIdx.x & 31) == 0) { shq[wid] = sq; shk[wid] = sk; }
    __syncthreads();
    float sumq = shq[0] + shq[1] + shq[2] + shq[3];
    float sumk = shk[0] + shk[1] + shk[2] + shk[3];
    float invq = 1.f / fmaxf(sqrtf(sumq), 1e-12f);
    float invk = 1.f / fmaxf(sqrtf(sumk), 1e-12f);

    size_t base = (size_t)bl * Dq + c;
    oq[base] = aq * invq * 0.08838834764831845f;
    ok[base] = ak * invk;
    ov[base] = av;
}

// ---------------- chunked gated delta-rule scan (register-tiled) ----------------
#define SKT 132
#define SAT 68
#define SVT 36

#define SK_OFF  0
#define SQ_OFF  8448
#define SS_OFF  16896
#define SA_OFF  21120
#define SV_OFF  25472
#define SP_OFF  27776
#define SC_OFF  30080
#define SCAN_SMEM_FLOATS (SC_OFF + 320)
#define SCAN_SMEM_BYTES (SCAN_SMEM_FLOATS * 4)

__global__ __launch_bounds__(256, 1)
void scan_kernel(const float* __restrict__ q, const float* __restrict__ k,
                 const float* __restrict__ v, const float* __restrict__ beta,
                 const float* __restrict__ gdec, const float* __restrict__ S0,
                 float* __restrict__ o, float* __restrict__ Sout)
{
    extern __shared__ float sm[];
    float* sK = sm + SK_OFF;
    float* sQ = sm + SQ_OFF;
    float* sS = sm + SS_OFF;
    float* sA = sm + SA_OFF;
    float* sV = sm + SV_OFF;
    float* sP = sm + SP_OFF;
    float* slg = sm + SC_OFF;
    float* sgam = slg + 64;
    float* sgCr = sgam + 64;
    float* sbet = sgCr + 64;
    float* sgg = sbet + 64;

    const int bh = blockIdx.x >> 2;
    const int grp = blockIdx.x & 3;
    const int b = bh >> 4;
    const int h = bh & 15;
    const int dv0 = grp * 32;
    const int tid = threadIdx.x;
    const int t_hi = tid >> 4;
    const int t_lo = tid & 15;

    for (int idx = tid; idx < 32 * 128; idx += 256) {
        int dv = idx >> 7, dk = idx & 127;
        sS[dv * SKT + dk] = S0[((size_t)bh * 128 + dv0 + dv) * 128 + dk];
    }

    for (int n = 0; n < Nq; n++) {
        const int l0 = n * Cq;
        for (int idx = tid; idx < 64 * 128; idx += 256) {
            int i = idx >> 7, d = idx & 127;
            size_t gi = (((size_t)(b * Lq + l0 + i)) * Hq + h) * Dh + d;
            sK[i * SKT + d] = k[gi];
            sQ[i * SKT + d] = q[gi];
        }
        for (int idx = tid; idx < 64 * 32; idx += 256) {
            int i = idx >> 5, dv = idx & 31;
            sV[i * SVT + dv] = v[(((size_t)(b * Lq + l0 + i)) * Hq + h) * Dh + dv0 + dv];
        }
        if (tid < 64) {
            sbet[tid] = beta[(size_t)bh * Lq + l0 + tid];
            sgg[tid] = gdec[(size_t)bh * Lq + l0 + tid];
        }
        __syncthreads();
        if (tid == 0) {
            float c = 0.f;
            for (int i = 0; i < 64; i++) { c += sgg[i]; slg[i] = c; }
        }
        __syncthreads();
        const float lgC = slg[63];
        if (tid < 64) {
            sgam[tid] = expf(slg[tid]);
            sgCr[tid] = expf(lgC - slg[tid]);
        }
        __syncthreads();
        const float gammaC = expf(lgC);

        {
            float acc[4][4];
#pragma unroll
            for (int r = 0; r < 4; r++)
#pragma unroll
                for (int c = 0; c < 4; c++) acc[r][c] = 0.f;
            for (int d = 0; d < 128; d += 4) {
                float4 av[4], bv[4];
#pragma unroll
                for (int r = 0; r < 4; r++)
                    av[r] = *(const float4*)&sK[(t_hi + 16 * r) * SKT + d];
#pragma unroll
                for (int c = 0; c < 4; c++)
                    bv[c] = *(const float4*)&sK[(t_lo + 16 * c) * SKT + d];
#pragma unroll
                for (int r = 0; r < 4; r++)
#pragma unroll
                    for (int c = 0; c < 4; c++) acc[r][c] += dot4(av[r], bv[c]);
            }
#pragma unroll
            for (int r = 0; r < 4; r++) {
                int i = t_hi + 16 * r;
#pragma unroll
                for (int c = 0; c < 4; c++) {
                    int j = t_lo + 16 * c;
                    float val;
                    if (j < i) val = sbet[i] * expf(slg[i] - slg[j]) * acc[r][c];
                    else val = (i == j) ? 1.f : 0.f;
                    sA[i * SAT + j] = val;
                }
            }
        }
        __syncthreads();

        {
            float acc[4][2];
#pragma unroll
            for (int r = 0; r < 4; r++) { acc[r][0] = 0.f; acc[r][1] = 0.f; }
            for (int d = 0; d < 128; d += 4) {
                float4 av[4], bv[2];
#pragma unroll
                for (int r = 0; r < 4; r++)
                    av[r] = *(const float4*)&sK[(t_hi + 16 * r) * SKT + d];
                bv[0] = *(const float4*)&sS[t_lo * SKT + d];
                bv[1] = *(const float4*)&sS[(t_lo + 16) * SKT + d];
#pragma unroll
                for (int r = 0; r < 4; r++) {
                    acc[r][0] += dot4(av[r], bv[0]);
                    acc[r][1] += dot4(av[r], bv[1]);
                }
            }
#pragma unroll
            for (int r = 0; r < 4; r++) {
                int i = t_hi + 16 * r;
#pragma unroll
                for (int c = 0; c < 2; c++) {
                    int dv = t_lo + 16 * c;
                    sP[i * SVT + dv] = sbet[i] * (sV[i * SVT + dv] - sgam[i] * acc[r][c]);
                }
            }
        }
        __syncthreads();

#pragma unroll 1
        for (int blk = 0; blk < 8; blk++) {
            const int r0 = blk * 8;
            if (tid < 32) {
                const int dv = tid;
                float vals[8];
                vals[0] = sP[r0 * SVT + dv];
#pragma unroll
                for (int r = 1; r < 8; r++) {
                    float acc = sP[(r0 + r) * SVT + dv];
#pragma unroll
                    for (int m = 0; m < 8; m++)
                        if (m < r) acc -= sA[(r0 + r) * SAT + r0 + m] * vals[m];
                    vals[r] = acc;
                }
#pragma unroll
                for (int r = 1; r < 8; r++) sP[(r0 + r) * SVT + dv] = vals[r];
            }
            __syncthreads();
            const int nrem = 64 - r0 - 8;
            if (nrem > 0) {
                for (int idx = tid; idx < nrem * 32; idx += 256) {
                    int i = r0 + 8 + (idx >> 5);
                    int dv = idx & 31;
                    float acc = sP[i * SVT + dv];
#pragma unroll
                    for (int m = 0; m < 8; m++)
                        acc -= sA[i * SAT + r0 + m] * sP[(r0 + m) * SVT + dv];
                    sP[i * SVT + dv] = acc;
                }
            }
            __syncthreads();
        }

        {
            float acc[4][4];
#pragma unroll
            for (int r = 0; r < 4; r++)
#pragma unroll
                for (int c = 0; c < 4; c++) acc[r][c] = 0.f;
            for (int d = 0; d < 128; d += 4) {
                float4 av[4], bv[4];
#pragma unroll
                for (int r = 0; r < 4; r++)
                    av[r] = *(const float4*)&sQ[(t_hi + 16 * r) * SKT + d];
#pragma unroll
                for (int c = 0; c < 4; c++)
                    bv[c] = *(const float4*)&sK[(t_lo + 16 * c) * SKT + d];
#pragma unroll
                for (int r = 0; r < 4; r++)
#pragma unroll
                    for (int c = 0; c < 4; c++) acc[r][c] += dot4(av[r], bv[c]);
            }
#pragma unroll
            for (int r = 0; r < 4; r++) {
                int i = t_hi + 16 * r;
#pragma unroll
                for (int c = 0; c < 4; c++) {
                    int j = t_lo + 16 * c;
                    float val = (j <= i) ? expf(slg[i] - slg[j]) * acc[r][c] : 0.f;
                    sA[i * SAT + j] = val;
                }
            }
        }
        __syncthreads();

        {
            float acc1[4][2], acc2[4][2];
#pragma unroll
            for (int r = 0; r < 4; r++) {
                acc1[r][0] = acc1[r][1] = 0.f;
                acc2[r][0] = acc2[r][1] = 0.f;
            }
            for (int d = 0; d < 128; d += 4) {
                float4 av[4], bv[2];
#pragma unroll
                for (int r = 0; r < 4; r++)
                    av[r] = *(const float4*)&sQ[(t_hi + 16 * r) * SKT + d];
                bv[0] = *(const float4*)&sS[t_lo * SKT + d];
                bv[1] = *(const float4*)&sS[(t_lo + 16) * SKT + d];
#pragma unroll
                for (int r = 0; r < 4; r++) {
                    acc1[r][0] += dot4(av[r], bv[0]);
                    acc1[r][1] += dot4(av[r], bv[1]);
                }
            }
            for (int j = 0; j < 64; j++) {
                float b0 = sP[j * SVT + t_lo];
                float b1 = sP[j * SVT + t_lo + 16];
#pragma unroll
                for (int r = 0; r < 4; r++) {
                    float a = sA[(t_hi + 16 * r) * SAT + j];
                    acc2[r][0] += a * b0;
                    acc2[r][1] += a * b1;
                }
            }
#pragma unroll
            for (int r = 0; r < 4; r++) {
                int i = t_hi + 16 * r;
                float g = sgam[i];
                size_t go = (((size_t)(b * Lq + l0 + i)) * Hq + h) * Dh + dv0;
                o[go + t_lo] = g * acc1[r][0] + acc2[r][0];
                o[go + t_lo + 16] = g * acc1[r][1] + acc2[r][1];
            }
        }
        __syncthreads();

        {
            const int dkb = t_lo * 8;
            float acc[2][8];
#pragma unroll
            for (int r = 0; r < 2; r++)
#pragma unroll
                for (int c = 0; c < 8; c++) acc[r][c] = 0.f;
            for (int i = 0; i < 64; i++) {
                float gc = sgCr[i];
                float a0 = sP[i * SVT + t_hi] * gc;
                float a1 = sP[i * SVT + t_hi + 16] * gc;
                float4 k0 = *(const float4*)&sK[i * SKT + dkb];
                float4 k1 = *(const float4*)&sK[i * SKT + dkb + 4];
                acc[0][0] += a0 * k0.x; acc[0][1] += a0 * k0.y;
                acc[0][2] += a0 * k0.z; acc[0][3] += a0 * k0.w;
                acc[0][4] += a0 * k1.x; acc[0][5] += a0 * k1.y;
                acc[0][6] += a0 * k1.z; acc[0][7] += a0 * k1.w;
                acc[1][0] += a1 * k0.x; acc[1][1] += a1 * k0.y;
                acc[1][2] += a1 * k0.z; acc[1][3] += a1 * k0.w;
                acc[1][4] += a1 * k1.x; acc[1][5] += a1 * k1.y;
                acc[1][6] += a1 * k1.z; acc[1][7] += a1 * k1.w;
            }
#pragma unroll
            for (int r = 0; r < 2; r++) {
                int dv = t_hi + 16 * r;
#pragma unroll
                for (int c = 0; c < 8; c++) {
                    float* p = &sS[dv * SKT + dkb + c];
                    *p = gammaC * *p + acc[r][c];
                }
            }
        }
        __syncthreads();
    }

    for (int idx = tid; idx < 32 * 128; idx += 256) {
        int dv = idx >> 7, dk = idx & 127;
        Sout[((size_t)bh * 128 + dv0 + dv) * 128 + dk] = sS[dv * SKT + dk];
    }
}

// ---------------- RMSNorm + gate (silu) -> fp16 directly ----------------
__global__ void gate_kernel(const float* __restrict__ o, const float* __restrict__ proj,
                            const float* __restrict__ norm_w,
                            __half* __restrict__ oh)
{
    const size_t base = (size_t)blockIdx.x * Dh + threadIdx.x;
    const size_t row = blockIdx.x >> 4;
    const size_t inner = (size_t)(blockIdx.x & 15) * Dh + threadIdx.x;
    float ov = o[base];
    float s = ov * ov;
#pragma unroll
    for (int off = 16; off > 0; off >>= 1) s += __shfl_xor_sync(0xffffffffu, s, off);
    __shared__ float sh[4];
    const int wid = threadIdx.x >> 5;
    if ((threadIdx.x & 31) == 0) sh[wid] = s;
    __syncthreads();
    float mean = (sh[0] + sh[1] + sh[2] + sh[3]) * (1.f / 128.f);
    float rs = rsqrtf(mean + EPSq);
    float gv = proj[row * (4 * Dq) + 3 * Dq + inner];
    float sig = gv / (1.f + expf(-gv));
    float val = ov * rs * norm_w[threadIdx.x] * sig;
    oh[base] = __float2half_rn(val);
}

// ---------------- launch ----------------
extern "C" void kernel_launch(void* const* d_in, const int* in_sizes, int n_in,
                              void* d_out, int out_size)
{
    const float* x = (const float*)d_in[0];
    const float* Wq = (const float*)d_in[1];
    const float* Wk = (const float*)d_in[2];
    const float* Wv = (const float*)d_in[3];
    const float* Wb = (const float*)d_in[4];
    const float* Wa = (const float*)d_in[5];
    const float* A_log = (const float*)d_in[6];
    const float* dt_bias = (const float*)d_in[7];
    const float* conv_q = (const float*)d_in[8];
    const float* conv_k = (const float*)d_in[9];
    const float* conv_v = (const float*)d_in[10];
    const float* Wg = (const float*)d_in[11];
    const float* norm_w = (const float*)d_in[12];
    const float* Wo = (const float*)d_in[13];
    const float* S0 = (const float*)d_in[14];

    float* out = (float*)d_out;
    float* Sout = out + (size_t)BLD;

    float *proj, *obuf, *qn, *kn, *vn, *beta, *gdec;
    __half *xh, *whi, *wlo;
    cudaGetSymbolAddress((void**)&proj, g_proj);
    cudaGetSymbolAddress((void**)&obuf, g_obuf);
    cudaGetSymbolAddress((void**)&qn, g_qn);
    cudaGetSymbolAddress((void**)&kn, g_kn);
    cudaGetSymbolAddress((void**)&vn, g_vn);
    cudaGetSymbolAddress((void**)&beta, g_beta);
    cudaGetSymbolAddress((void**)&gdec, g_gdec);
    cudaGetSymbolAddress((void**)&xh, g_xh);
    cudaGetSymbolAddress((void**)&whi, g_whi);
    cudaGetSymbolAddress((void**)&wlo, g_wlo);

    cudaFuncSetAttribute(scan_kernel, cudaFuncAttributeMaxDynamicSharedMemorySize,
                         SCAN_SMEM_BYTES);
    cudaFuncSetAttribute(hmma_gemm, cudaFuncAttributeMaxDynamicSharedMemorySize,
                         GEMM_SMEM_BYTES);

    const size_t WSZ = (size_t)Dq * Dq;

    // splits (x4 vectorized)
    cast_f16<<<BLD / 1024, 256>>>((const float4*)x, (__half2*)xh);
    split2_f16<<<WSZ / 1024, 256>>>((const float4*)Wq, (__half2*)whi, (__half2*)wlo);
    split2_f16<<<WSZ / 1024, 256>>>((const float4*)Wk, (__half2*)(whi + WSZ), (__half2*)(wlo + WSZ));
    split2_f16<<<WSZ / 1024, 256>>>((const float4*)Wv, (__half2*)(whi + 2 * WSZ), (__half2*)(wlo + 2 * WSZ));
    split2_f16<<<WSZ / 1024, 256>>>((const float4*)Wg, (__half2*)(whi + 3 * WSZ), (__half2*)(wlo + 3 * WSZ));

    // merged projection GEMM: [8192, 2048] x [8192, 2048]^T -> [8192, 8192]
    dim3 pgrid(4 * Dq / 128, BLq / 256);   // (64, 32)
    hmma_gemm<<<pgrid, 256, GEMM_SMEM_BYTES>>>(xh, whi, wlo, proj, 4 * Dq);

    split2_f16<<<WSZ / 1024, 256>>>((const float4*)Wo, (__half2*)(whi + 4 * WSZ), (__half2*)(wlo + 4 * WSZ));
    betag_kernel<<<BLq, 512>>>(x, Wb, Wa, A_log, dt_bias, beta, gdec);

    conv_kernel<<<BLq * Hq, 128>>>(proj, conv_q, conv_k, conv_v, qn, kn, vn);

    scan_kernel<<<Bq * Hq * 4, 256, SCAN_SMEM_BYTES>>>(qn, kn, vn, beta, gdec, S0,
                                                       obuf, Sout);

    gate_kernel<<<BLq * Hq, 128>>>(obuf, proj, norm_w, xh);

    // output projection
    dim3 ogrid(Dq / 128, BLq / 256);       // (16, 32)
    hmma_gemm<<<ogrid, 256, GEMM_SMEM_BYTES>>>(xh, whi + 4 * WSZ, wlo + 4 * WSZ,
                                               out, Dq);
}

// round 11
// speedup vs baseline: 1.0741x; 1.0741x over previous
#include <cuda_runtime.h>
#include <cuda_bf16.h>
#include <cuda_fp16.h>
#include <cstdint>
#include <cstddef>

#define Bq 2
#define Lq 4096
#define Dq 2048
#define Hq 16
#define Dh 128
#define Cq 64
#define Nq (Lq / Cq)
#define KW 4
#define BLq (Bq * Lq)
#define EPSq 1e-5f

#define GNC 64                // 2 * 32 K-chunks of 64 (fp16 split-2)

// ---------------- device scratch buffers ----------------
#define BLD (BLq * Dq)
#define BHL (Bq * Hq * Lq)
#define WROWS (5 * Dq)

__device__ float g_proj[(size_t)BLq * 4 * Dq];
__device__ float g_obuf[BLD];
__device__ float g_qn[BLD];
__device__ float g_kn[BLD];
__device__ float g_vn[BLD];
__device__ float g_beta[BHL];
__device__ float g_gdec[BHL];

__device__ __half g_xh[(size_t)BLq * Dq];
__device__ __half g_whi[(size_t)WROWS * Dq];
__device__ __half g_wlo[(size_t)WROWS * Dq];

// ================= helpers =================
__device__ __forceinline__ uint32_t smem_u32(const void* p) {
    uint32_t a;
    asm("{ .reg .u64 t; cvta.to.shared.u64 t, %1; cvt.u32.u64 %0, t; }" : "=r"(a) : "l"(p));
    return a;
}
#define SWZ(x) ((x) ^ (((x) >> 3) & 0x70))

__device__ __forceinline__ void cp16(uint32_t dst, const void* src) {
    asm volatile("cp.async.cg.shared.global [%0], [%1], 16;" :: "r"(dst), "l"(src));
}
__device__ __forceinline__ void ldsm_x4(uint32_t& r0, uint32_t& r1, uint32_t& r2,
                                        uint32_t& r3, uint32_t a) {
    asm volatile("ldmatrix.sync.aligned.m8n8.x4.shared.b16 {%0,%1,%2,%3}, [%4];"
                 : "=r"(r0), "=r"(r1), "=r"(r2), "=r"(r3) : "r"(a));
}
__device__ __forceinline__ void mma16816(float* d, const uint32_t* a, const uint32_t* b) {
    asm volatile("mma.sync.aligned.m16n8k16.row.col.f32.f16.f16.f32 "
                 "{%0,%1,%2,%3}, {%4,%5,%6,%7}, {%8,%9}, {%0,%1,%2,%3};"
                 : "+f"(d[0]), "+f"(d[1]), "+f"(d[2]), "+f"(d[3])
                 : "r"(a[0]), "r"(a[1]), "r"(a[2]), "r"(a[3]), "r"(b[0]), "r"(b[1]));
}
__device__ __forceinline__ float dot4(float4 a, float4 b) {
    return a.x * b.x + a.y * b.y + a.z * b.z + a.w * b.w;
}

// ---------------- fp32 -> fp16 cast (activations), x4 vectorized ----------------
__global__ void cast_f16(const float4* __restrict__ in, __half2* __restrict__ out)
{
    size_t idx = (size_t)blockIdx.x * blockDim.x + threadIdx.x;
    float4 a = in[idx];
    out[idx * 2]     = __floats2half2_rn(a.x, a.y);
    out[idx * 2 + 1] = __floats2half2_rn(a.z, a.w);
}

// ---------------- fp32 -> fp16 hi + lo (weights), x4 vectorized ----------------
__global__ void split2_f16(const float4* __restrict__ in, __half2* __restrict__ hi,
                           __half2* __restrict__ lo)
{
    size_t idx = (size_t)blockIdx.x * blockDim.x + threadIdx.x;
    float4 a = in[idx];
    __half2 h0 = __floats2half2_rn(a.x, a.y);
    __half2 h1 = __floats2half2_rn(a.z, a.w);
    hi[idx * 2]     = h0;
    hi[idx * 2 + 1] = h1;
    lo[idx * 2]     = __floats2half2_rn(a.x - __low2float(h0),  a.y - __high2float(h0));
    lo[idx * 2 + 1] = __floats2half2_rn(a.z - __low2float(h1),  a.w - __high2float(h1));
}

// ---------------- HMMA GEMM, fp16 split-2 chunk routing --------------------
// C[M, ldc] = A[M,2048](fp16) * (Whi ⊕ Wlo)[N,2048]^T
// 128x128 CTA tile, 64x32 warp tiles (2x4 warps), BK=64, 3-stage, 2 CTA/SM.
#define STAGE_B 32768
#define GEMM_SMEM_BYTES (3 * STAGE_B)

__global__ __launch_bounds__(256, 2)
void hmma_gemm(const __half* __restrict__ A,
               const __half* __restrict__ Bhi, const __half* __restrict__ Blo,
               float* __restrict__ C, int ldc)
{
    extern __shared__ __align__(128) char smem[];
    const uint32_t sb = smem_u32(smem);
    const int tid = threadIdx.x;
    const int warp = tid >> 5, lane = tid & 31;
    const int wm = warp & 1, wn = warp >> 1;
    const int bm = blockIdx.y * 128, bn = blockIdx.x * 128;

    float acc[4][4][4];
#pragma unroll
    for (int i = 0; i < 4; i++)
#pragma unroll
        for (int j = 0; j < 4; j++)
#pragma unroll
            for (int r = 0; r < 4; r++) acc[i][j][r] = 0.f;

    const int lrow = tid >> 3;
    const int lseg = tid & 7;
    const uint32_t loff = SWZ(lrow * 128 + lseg * 16);

#define LOAD_STAGE(s, kc) do { \
        int _k0 = ((kc) & 31) * 64; \
        const __half* _Bb = ((kc) >= 32) ? Blo : Bhi; \
        uint32_t _as = sb + (s) * STAGE_B; \
        uint32_t _bs = _as + 16384; \
        const __half* _ap = A + (size_t)(bm + lrow) * Dq + _k0 + lseg * 8; \
        const __half* _bp = _Bb + (size_t)(bn + lrow) * Dq + _k0 + lseg * 8; \
        _Pragma("unroll") \
        for (int _i = 0; _i < 4; _i++) { \
            cp16(_as + loff + _i * 4096, _ap + (size_t)_i * 32 * Dq); \
            cp16(_bs + loff + _i * 4096, _bp + (size_t)_i * 32 * Dq); \
        } \
        asm volatile("cp.async.commit_group;" ::: "memory"); \
    } while (0)

    // A fragment addressing (ldsm x4, m16k16 per m-tile)
    const int aq = lane >> 3;
    const int am = (lane & 7) + (aq & 1) * 8;
    const int akb = (aq >> 1) * 8;
    // B fragment addressing (packed ldsm x4: two 8-row n-tiles x two k-blocks)
    const int bln = lane & 7;
    const int bsel = lane >> 3;              // 0..3
    const int bnrow = (bsel >> 1) * 8 + bln; // row offset within 16-row pair
    const int bkoff = (bsel & 1) * 8;        // k-block offset

    LOAD_STAGE(0, 0);
    LOAD_STAGE(1, 1);

    for (int c = 0; c < GNC; c++) {
        if (c == GNC - 1) {
            asm volatile("cp.async.wait_group 0;" ::: "memory");
        } else {
            asm volatile("cp.async.wait_group 1;" ::: "memory");
        }
        __syncthreads();
        if (c + 2 < GNC) LOAD_STAGE((c + 2) % 3, c + 2);

        const uint32_t As = sb + (c % 3) * STAGE_B;
        const uint32_t Bs = As + 16384;
#pragma unroll
        for (int ks = 0; ks < 4; ks++) {
            const int k0 = ks * 16;
            uint32_t af[4][4];
#pragma unroll
            for (int mt = 0; mt < 4; mt++) {
                int m = wm * 64 + mt * 16 + am;
                ldsm_x4(af[mt][0], af[mt][1], af[mt][2], af[mt][3],
                        As + SWZ(m * 128 + (k0 + akb) * 2));
            }
            uint32_t bf[4][2];
#pragma unroll
            for (int ntp = 0; ntp < 2; ntp++) {
                int n = wn * 32 + ntp * 16 + bnrow;
                ldsm_x4(bf[2 * ntp][0], bf[2 * ntp][1],
                        bf[2 * ntp + 1][0], bf[2 * ntp + 1][1],
                        Bs + SWZ(n * 128 + (k0 + bkoff) * 2));
            }
#pragma unroll
            for (int mt = 0; mt < 4; mt++)
#pragma unroll
                for (int nt = 0; nt < 4; nt++)
                    mma16816(acc[mt][nt], af[mt], bf[nt]);
        }
    }

    const int r0 = bm + wm * 64 + (lane >> 2);
    const int c0 = bn + wn * 32 + (lane & 3) * 2;
#pragma unroll
    for (int mt = 0; mt < 4; mt++) {
#pragma unroll
        for (int nt = 0; nt < 4; nt++) {
            float2* p0 = (float2*)(C + (size_t)(r0 + mt * 16) * ldc + c0 + nt * 8);
            float2* p1 = (float2*)(C + (size_t)(r0 + mt * 16 + 8) * ldc + c0 + nt * 8);
            *p0 = make_float2(acc[mt][nt][0], acc[mt][nt][1]);
            *p1 = make_float2(acc[mt][nt][2], acc[mt][nt][3]);
        }
    }
}

// ---------------- beta / g kernel ----------------
__global__ void betag_kernel(const float* __restrict__ x,
                             const float* __restrict__ Wb,
                             const float* __restrict__ Wa,
                             const float* __restrict__ A_log,
                             const float* __restrict__ dt_bias,
                             float* __restrict__ beta,
                             float* __restrict__ gdec)
{
    const int bl = blockIdx.x;
    const int h = threadIdx.x >> 5;
    const int lane = threadIdx.x & 31;
    const float* xr = x + (size_t)bl * Dq;
    const float* wb = Wb + (size_t)h * Dq;
    const float* wa = Wa + (size_t)h * Dq;
    float sb = 0.f, sa = 0.f;
    for (int i = lane; i < Dq; i += 32) {
        float xv = xr[i];
        sb += xv * wb[i];
        sa += xv * wa[i];
    }
#pragma unroll
    for (int off = 16; off > 0; off >>= 1) {
        sb += __shfl_down_sync(0xffffffffu, sb, off);
        sa += __shfl_down_sync(0xffffffffu, sa, off);
    }
    if (lane == 0) {
        const int b = bl / Lq, l = bl % Lq;
        float bet = 1.f / (1.f + expf(-sb));
        float z = sa + dt_bias[h];
        float sp = (z > 15.f) ? z : log1pf(expf(z));
        float g = -expf(A_log[h]) * sp;
        size_t o = ((size_t)(b * Hq + h)) * Lq + l;
        beta[o] = bet;
        gdec[o] = g;
    }
}

// ---------------- causal dwconv + silu + l2 norm ----------
__global__ void conv_kernel(const float* __restrict__ proj,
                            const float* __restrict__ wq, const float* __restrict__ wk,
                            const float* __restrict__ wv,
                            float* __restrict__ oq, float* __restrict__ ok,
                            float* __restrict__ ov)
{
    const int blk = blockIdx.x;
    const int h = blk % Hq;
    const int bl = blk / Hq;
    const int l = bl % Lq;
    const int d = threadIdx.x;
    const int c = h * Dh + d;

    float aq = 0.f, ak = 0.f, av = 0.f;
#pragma unroll
    for (int j = 0; j < KW; j++) {
        int ll = l - (KW - 1) + j;
        if (ll >= 0) {
            size_t idx = ((size_t)(bl - l + ll)) * (4 * Dq) + c;
            aq += wq[c * KW + j] * proj[idx];
            ak += wk[c * KW + j] * proj[idx + Dq];
            av += wv[c * KW + j] * proj[idx + 2 * Dq];
        }
    }
    aq = aq / (1.f + expf(-aq));
    ak = ak / (1.f + expf(-ak));
    av = av / (1.f + expf(-av));

    float sq = aq * aq, sk = ak * ak;
#pragma unroll
    for (int off = 16; off > 0; off >>= 1) {
        sq += __shfl_xor_sync(0xffffffffu, sq, off);
        sk += __shfl_xor_sync(0xffffffffu, sk, off);
    }
    __shared__ float shq[4], shk[4];
    const int wid = threadIdx.x >> 5;
    if ((threadIdx.x & 31) == 0) { shq[wid] = sq; shk[wid] = sk; }
    __syncthreads();
    float sumq = shq[0] + shq[1] + shq[2] + shq[3];
    float sumk = shk[0] + shk[1] + shk[2] + shk[3];
    float invq = 1.f / fmaxf(sqrtf(sumq), 1e-12f);
    float invk = 1.f / fmaxf(sqrtf(sumk), 1e-12f);

    size_t base = (size_t)bl * Dq + c;
    oq[base] = aq * invq * 0.08838834764831845f;
    ok[base] = ak * invk;
    ov[base] = av;
}

// ---------------- chunked gated delta-rule scan (register-tiled) ----------------
#define SKT 132
#define SAT 68
#define SVT 36

#define SK_OFF  0
#define SQ_OFF  8448
#define SS_OFF  16896
#define SA_OFF  21120
#define SV_OFF  25472
#define SP_OFF  27776
#define SC_OFF  30080
#define SCAN_SMEM_FLOATS (SC_OFF + 320)
#define SCAN_SMEM_BYTES (SCAN_SMEM_FLOATS * 4)

__global__ __launch_bounds__(256, 1)
void scan_kernel(const float* __restrict__ q, const float* __restrict__ k,
                 const float* __restrict__ v, const float* __restrict__ beta,
                 const float* __restrict__ gdec, const float* __restrict__ S0,
                 float* __restrict__ o, float* __restrict__ Sout)
{
    extern __shared__ float sm[];
    float* sK = sm + SK_OFF;
    float* sQ = sm + SQ_OFF;
    float* sS = sm + SS_OFF;
    float* sA = sm + SA_OFF;
    float* sV = sm + SV_OFF;
    float* sP = sm + SP_OFF;
    float* slg = sm + SC_OFF;
    float* sgam = slg + 64;
    float* sgCr = sgam + 64;
    float* sbet = sgCr + 64;
    float* sgg = sbet + 64;

    const int bh = blockIdx.x >> 2;
    const int grp = blockIdx.x & 3;
    const int b = bh >> 4;
    const int h = bh & 15;
    const int dv0 = grp * 32;
    const int tid = threadIdx.x;
    const int t_hi = tid >> 4;
    const int t_lo = tid & 15;

    for (int idx = tid; idx < 32 * 128; idx += 256) {
        int dv = idx >> 7, dk = idx & 127;
        sS[dv * SKT + dk] = S0[((size_t)bh * 128 + dv0 + dv) * 128 + dk];
    }

    for (int n = 0; n < Nq; n++) {
        const int l0 = n * Cq;
        for (int idx = tid; idx < 64 * 128; idx += 256) {
            int i = idx >> 7, d = idx & 127;
            size_t gi = (((size_t)(b * Lq + l0 + i)) * Hq + h) * Dh + d;
            sK[i * SKT + d] = k[gi];
            sQ[i * SKT + d] = q[gi];
        }
        for (int idx = tid; idx < 64 * 32; idx += 256) {
            int i = idx >> 5, dv = idx & 31;
            sV[i * SVT + dv] = v[(((size_t)(b * Lq + l0 + i)) * Hq + h) * Dh + dv0 + dv];
        }
        if (tid < 64) {
            sbet[tid] = beta[(size_t)bh * Lq + l0 + tid];
            sgg[tid] = gdec[(size_t)bh * Lq + l0 + tid];
        }
        __syncthreads();
        if (tid == 0) {
            float c = 0.f;
            for (int i = 0; i < 64; i++) { c += sgg[i]; slg[i] = c; }
        }
        __syncthreads();
        const float lgC = slg[63];
        if (tid < 64) {
            sgam[tid] = expf(slg[tid]);
            sgCr[tid] = expf(lgC - slg[tid]);
        }
        __syncthreads();
        const float gammaC = expf(lgC);

        {
            float acc[4][4];
#pragma unroll
            for (int r = 0; r < 4; r++)
#pragma unroll
                for (int c = 0; c < 4; c++) acc[r][c] = 0.f;
            for (int d = 0; d < 128; d += 4) {
                float4 av[4], bv[4];
#pragma unroll
                for (int r = 0; r < 4; r++)
                    av[r] = *(const float4*)&sK[(t_hi + 16 * r) * SKT + d];
#pragma unroll
                for (int c = 0; c < 4; c++)
                    bv[c] = *(const float4*)&sK[(t_lo + 16 * c) * SKT + d];
#pragma unroll
                for (int r = 0; r < 4; r++)
#pragma unroll
                    for (int c = 0; c < 4; c++) acc[r][c] += dot4(av[r], bv[c]);
            }
#pragma unroll
            for (int r = 0; r < 4; r++) {
                int i = t_hi + 16 * r;
#pragma unroll
                for (int c = 0; c < 4; c++) {
                    int j = t_lo + 16 * c;
                    float val;
                    if (j < i) val = sbet[i] * expf(slg[i] - slg[j]) * acc[r][c];
                    else val = (i == j) ? 1.f : 0.f;
                    sA[i * SAT + j] = val;
                }
            }
        }
        __syncthreads();

        {
            float acc[4][2];
#pragma unroll
            for (int r = 0; r < 4; r++) { acc[r][0] = 0.f; acc[r][1] = 0.f; }
            for (int d = 0; d < 128; d += 4) {
                float4 av[4], bv[2];
#pragma unroll
                for (int r = 0; r < 4; r++)
                    av[r] = *(const float4*)&sK[(t_hi + 16 * r) * SKT + d];
                bv[0] = *(const float4*)&sS[t_lo * SKT + d];
                bv[1] = *(const float4*)&sS[(t_lo + 16) * SKT + d];
#pragma unroll
                for (int r = 0; r < 4; r++) {
                    acc[r][0] += dot4(av[r], bv[0]);
                    acc[r][1] += dot4(av[r], bv[1]);
                }
            }
#pragma unroll
            for (int r = 0; r < 4; r++) {
                int i = t_hi + 16 * r;
#pragma unroll
                for (int c = 0; c < 2; c++) {
                    int dv = t_lo + 16 * c;
                    sP[i * SVT + dv] = sbet[i] * (sV[i * SVT + dv] - sgam[i] * acc[r][c]);
                }
            }
        }
        __syncthreads();

#pragma unroll 1
        for (int blk = 0; blk < 8; blk++) {
            const int r0 = blk * 8;
            if (tid < 32) {
                const int dv = tid;
                float vals[8];
                vals[0] = sP[r0 * SVT + dv];
#pragma unroll
                for (int r = 1; r < 8; r++) {
                    float acc = sP[(r0 + r) * SVT + dv];
#pragma unroll
                    for (int m = 0; m < 8; m++)
                        if (m < r) acc -= sA[(r0 + r) * SAT + r0 + m] * vals[m];
                    vals[r] = acc;
                }
#pragma unroll
                for (int r = 1; r < 8; r++) sP[(r0 + r) * SVT + dv] = vals[r];
            }
            __syncthreads();
            const int nrem = 64 - r0 - 8;
            if (nrem > 0) {
                for (int idx = tid; idx < nrem * 32; idx += 256) {
                    int i = r0 + 8 + (idx >> 5);
                    int dv = idx & 31;
                    float acc = sP[i * SVT + dv];
#pragma unroll
                    for (int m = 0; m < 8; m++)
                        acc -= sA[i * SAT + r0 + m] * sP[(r0 + m) * SVT + dv];
                    sP[i * SVT + dv] = acc;
                }
            }
            __syncthreads();
        }

        {
            float acc[4][4];
#pragma unroll
            for (int r = 0; r < 4; r++)
#pragma unroll
                for (int c = 0; c < 4; c++) acc[r][c] = 0.f;
            for (int d = 0; d < 128; d += 4) {
                float4 av[4], bv[4];
#pragma unroll
                for (int r = 0; r < 4; r++)
                    av[r] = *(const float4*)&sQ[(t_hi + 16 * r) * SKT + d];
#pragma unroll
                for (int c = 0; c < 4; c++)
                    bv[c] = *(const float4*)&sK[(t_lo + 16 * c) * SKT + d];
#pragma unroll
                for (int r = 0; r < 4; r++)
#pragma unroll
                    for (int c = 0; c < 4; c++) acc[r][c] += dot4(av[r], bv[c]);
            }
#pragma unroll
            for (int r = 0; r < 4; r++) {
                int i = t_hi + 16 * r;
#pragma unroll
                for (int c = 0; c < 4; c++) {
                    int j = t_lo + 16 * c;
                    float val = (j <= i) ? expf(slg[i] - slg[j]) * acc[r][c] : 0.f;
                    sA[i * SAT + j] = val;
                }
            }
        }
        __syncthreads();

        {
            float acc1[4][2], acc2[4][2];
#pragma unroll
            for (int r = 0; r < 4; r++) {
                acc1[r][0] = acc1[r][1] = 0.f;
                acc2[r][0] = acc2[r][1] = 0.f;
            }
            for (int d = 0; d < 128; d += 4) {
                float4 av[4], bv[2];
#pragma unroll
                for (int r = 0; r < 4; r++)
                    av[r] = *(const float4*)&sQ[(t_hi + 16 * r) * SKT + d];
                bv[0] = *(const float4*)&sS[t_lo * SKT + d];
                bv[1] = *(const float4*)&sS[(t_lo + 16) * SKT + d];
#pragma unroll
                for (int r = 0; r < 4; r++) {
                    acc1[r][0] += dot4(av[r], bv[0]);
                    acc1[r][1] += dot4(av[r], bv[1]);
                }
            }
            for (int j = 0; j < 64; j++) {
                float b0 = sP[j * SVT + t_lo];
                float b1 = sP[j * SVT + t_lo + 16];
#pragma unroll
                for (int r = 0; r < 4; r++) {
                    float a = sA[(t_hi + 16 * r) * SAT + j];
                    acc2[r][0] += a * b0;
                    acc2[r][1] += a * b1;
                }
            }
#pragma unroll
            for (int r = 0; r < 4; r++) {
                int i = t_hi + 16 * r;
                float g = sgam[i];
                size_t go = (((size_t)(b * Lq + l0 + i)) * Hq + h) * Dh + dv0;
                o[go + t_lo] = g * acc1[r][0] + acc2[r][0];
                o[go + t_lo + 16] = g * acc1[r][1] + acc2[r][1];
            }
        }
        __syncthreads();

        {
            const int dkb = t_lo * 8;
            float acc[2][8];
#pragma unroll
            for (int r = 0; r < 2; r++)
#pragma unroll
                for (int c = 0; c < 8; c++) acc[r][c] = 0.f;
            for (int i = 0; i < 64; i++) {
                float gc = sgCr[i];
                float a0 = sP[i * SVT + t_hi] * gc;
                float a1 = sP[i * SVT + t_hi + 16] * gc;
                float4 k0 = *(const float4*)&sK[i * SKT + dkb];
                float4 k1 = *(const float4*)&sK[i * SKT + dkb + 4];
                acc[0][0] += a0 * k0.x; acc[0][1] += a0 * k0.y;
                acc[0][2] += a0 * k0.z; acc[0][3] += a0 * k0.w;
                acc[0][4] += a0 * k1.x; acc[0][5] += a0 * k1.y;
                acc[0][6] += a0 * k1.z; acc[0][7] += a0 * k1.w;
                acc[1][0] += a1 * k0.x; acc[1][1] += a1 * k0.y;
                acc[1][2] += a1 * k0.z; acc[1][3] += a1 * k0.w;
                acc[1][4] += a1 * k1.x; acc[1][5] += a1 * k1.y;
                acc[1][6] += a1 * k1.z; acc[1][7] += a1 * k1.w;
            }
#pragma unroll
            for (int r = 0; r < 2; r++) {
                int dv = t_hi + 16 * r;
#pragma unroll
                for (int c = 0; c < 8; c++) {
                    float* p = &sS[dv * SKT + dkb + c];
                    *p = gammaC * *p + acc[r][c];
                }
            }
        }
        __syncthreads();
    }

    for (int idx = tid; idx < 32 * 128; idx += 256) {
        int dv = idx >> 7, dk = idx & 127;
        Sout[((size_t)bh * 128 + dv0 + dv) * 128 + dk] = sS[dv * SKT + dk];
    }
}

// ---------------- RMSNorm + gate (silu) -> fp16 directly ----------------
__global__ void gate_kernel(const float* __restrict__ o, const float* __restrict__ proj,
                            const float* __restrict__ norm_w,
                            __half* __restrict__ oh)
{
    const size_t base = (size_t)blockIdx.x * Dh + threadIdx.x;
    const size_t row = blockIdx.x >> 4;
    const size_t inner = (size_t)(blockIdx.x & 15) * Dh + threadIdx.x;
    float ov = o[base];
    float s = ov * ov;
#pragma unroll
    for (int off = 16; off > 0; off >>= 1) s += __shfl_xor_sync(0xffffffffu, s, off);
    __shared__ float sh[4];
    const int wid = threadIdx.x >> 5;
    if ((threadIdx.x & 31) == 0) sh[wid] = s;
    __syncthreads();
    float mean = (sh[0] + sh[1] + sh[2] + sh[3]) * (1.f / 128.f);
    float rs = rsqrtf(mean + EPSq);
    float gv = proj[row * (4 * Dq) + 3 * Dq + inner];
    float sig = gv / (1.f + expf(-gv));
    float val = ov * rs * norm_w[threadIdx.x] * sig;
    oh[base] = __float2half_rn(val);
}

// ---------------- launch ----------------
extern "C" void kernel_launch(void* const* d_in, const int* in_sizes, int n_in,
                              void* d_out, int out_size)
{
    const float* x = (const float*)d_in[0];
    const float* Wq = (const float*)d_in[1];
    const float* Wk = (const float*)d_in[2];
    const float* Wv = (const float*)d_in[3];
    const float* Wb = (const float*)d_in[4];
    const float* Wa = (const float*)d_in[5];
    const float* A_log = (const float*)d_in[6];
    const float* dt_bias = (const float*)d_in[7];
    const float* conv_q = (const float*)d_in[8];
    const float* conv_k = (const float*)d_in[9];
    const float* conv_v = (const float*)d_in[10];
    const float* Wg = (const float*)d_in[11];
    const float* norm_w = (const float*)d_in[12];
    const float* Wo = (const float*)d_in[13];
    const float* S0 = (const float*)d_in[14];

    float* out = (float*)d_out;
    float* Sout = out + (size_t)BLD;

    float *proj, *obuf, *qn, *kn, *vn, *beta, *gdec;
    __half *xh, *whi, *wlo;
    cudaGetSymbolAddress((void**)&proj, g_proj);
    cudaGetSymbolAddress((void**)&obuf, g_obuf);
    cudaGetSymbolAddress((void**)&qn, g_qn);
    cudaGetSymbolAddress((void**)&kn, g_kn);
    cudaGetSymbolAddress((void**)&vn, g_vn);
    cudaGetSymbolAddress((void**)&beta, g_beta);
    cudaGetSymbolAddress((void**)&gdec, g_gdec);
    cudaGetSymbolAddress((void**)&xh, g_xh);
    cudaGetSymbolAddress((void**)&whi, g_whi);
    cudaGetSymbolAddress((void**)&wlo, g_wlo);

    cudaFuncSetAttribute(scan_kernel, cudaFuncAttributeMaxDynamicSharedMemorySize,
                         SCAN_SMEM_BYTES);
    cudaFuncSetAttribute(hmma_gemm, cudaFuncAttributeMaxDynamicSharedMemorySize,
                         GEMM_SMEM_BYTES);

    const size_t WSZ = (size_t)Dq * Dq;

    // splits (x4 vectorized)
    cast_f16<<<BLD / 1024, 256>>>((const float4*)x, (__half2*)xh);
    split2_f16<<<WSZ / 1024, 256>>>((const float4*)Wq, (__half2*)whi, (__half2*)wlo);
    split2_f16<<<WSZ / 1024, 256>>>((const float4*)Wk, (__half2*)(whi + WSZ), (__half2*)(wlo + WSZ));
    split2_f16<<<WSZ / 1024, 256>>>((const float4*)Wv, (__half2*)(whi + 2 * WSZ), (__half2*)(wlo + 2 * WSZ));
    split2_f16<<<WSZ / 1024, 256>>>((const float4*)Wg, (__half2*)(whi + 3 * WSZ), (__half2*)(wlo + 3 * WSZ));

    // merged projection GEMM: [8192, 2048] x [8192, 2048]^T -> [8192, 8192]
    dim3 pgrid(4 * Dq / 128, BLq / 128);   // (64, 64)
    hmma_gemm<<<pgrid, 256, GEMM_SMEM_BYTES>>>(xh, whi, wlo, proj, 4 * Dq);

    split2_f16<<<WSZ / 1024, 256>>>((const float4*)Wo, (__half2*)(whi + 4 * WSZ), (__half2*)(wlo + 4 * WSZ));
    betag_kernel<<<BLq, 512>>>(x, Wb, Wa, A_log, dt_bias, beta, gdec);

    conv_kernel<<<BLq * Hq, 128>>>(proj, conv_q, conv_k, conv_v, qn, kn, vn);

    scan_kernel<<<Bq * Hq * 4, 256, SCAN_SMEM_BYTES>>>(qn, kn, vn, beta, gdec, S0,
                                                       obuf, Sout);

    gate_kernel<<<BLq * Hq, 128>>>(obuf, proj, norm_w, xh);

    // output projection
    dim3 ogrid(Dq / 128, BLq / 128);       // (16, 64)
    hmma_gemm<<<ogrid, 256, GEMM_SMEM_BYTES>>>(xh, whi + 4 * WSZ, wlo + 4 * WSZ,
                                               out, Dq);
}

// round 12
// speedup vs baseline: 1.1445x; 1.0656x over previous
#include <cuda_runtime.h>
#include <cuda_bf16.h>
#include <cuda_fp16.h>
#include <cstdint>
#include <cstddef>

#define Bq 2
#define Lq 4096
#define Dq 2048
#define Hq 16
#define Dh 128
#define Cq 64
#define Nq (Lq / Cq)
#define KW 4
#define BLq (Bq * Lq)
#define EPSq 1e-5f

#define GNC 64                // full split-2 chunk count (hi 0-31, lo 32-63)

// ---------------- device scratch buffers ----------------
#define BLD (BLq * Dq)
#define BHL (Bq * Hq * Lq)
#define WROWS (5 * Dq)

__device__ float g_proj[(size_t)BLq * 4 * Dq];
__device__ float g_obuf[BLD];
__device__ float g_qn[BLD];
__device__ float g_kn[BLD];
__device__ float g_vn[BLD];
__device__ float g_beta[BHL];
__device__ float g_gdec[BHL];

__device__ __half g_xh[(size_t)BLq * Dq];
__device__ __half g_whi[(size_t)WROWS * Dq];
__device__ __half g_wlo[(size_t)WROWS * Dq];

// ================= helpers =================
__device__ __forceinline__ uint32_t smem_u32(const void* p) {
    uint32_t a;
    asm("{ .reg .u64 t; cvta.to.shared.u64 t, %1; cvt.u32.u64 %0, t; }" : "=r"(a) : "l"(p));
    return a;
}
#define SWZ(x) ((x) ^ (((x) >> 3) & 0x70))

__device__ __forceinline__ void cp16(uint32_t dst, const void* src) {
    asm volatile("cp.async.cg.shared.global [%0], [%1], 16;" :: "r"(dst), "l"(src));
}
__device__ __forceinline__ void ldsm_x4(uint32_t& r0, uint32_t& r1, uint32_t& r2,
                                        uint32_t& r3, uint32_t a) {
    asm volatile("ldmatrix.sync.aligned.m8n8.x4.shared.b16 {%0,%1,%2,%3}, [%4];"
                 : "=r"(r0), "=r"(r1), "=r"(r2), "=r"(r3) : "r"(a));
}
__device__ __forceinline__ void mma16816(float* d, const uint32_t* a, const uint32_t* b) {
    asm volatile("mma.sync.aligned.m16n8k16.row.col.f32.f16.f16.f32 "
                 "{%0,%1,%2,%3}, {%4,%5,%6,%7}, {%8,%9}, {%0,%1,%2,%3};"
                 : "+f"(d[0]), "+f"(d[1]), "+f"(d[2]), "+f"(d[3])
                 : "r"(a[0]), "r"(a[1]), "r"(a[2]), "r"(a[3]), "r"(b[0]), "r"(b[1]));
}
__device__ __forceinline__ float dot4(float4 a, float4 b) {
    return a.x * b.x + a.y * b.y + a.z * b.z + a.w * b.w;
}

// ---------------- fp32 -> fp16 cast (activations), x4 vectorized ----------------
__global__ void cast_f16(const float4* __restrict__ in, __half2* __restrict__ out)
{
    size_t idx = (size_t)blockIdx.x * blockDim.x + threadIdx.x;
    float4 a = in[idx];
    out[idx * 2]     = __floats2half2_rn(a.x, a.y);
    out[idx * 2 + 1] = __floats2half2_rn(a.z, a.w);
}

// ---------------- batched fp32 -> fp16 hi+lo for 4 weights ----------------
struct W4 { const float4* w0; const float4* w1; const float4* w2; const float4* w3; };

#define WBLK ((Dq * Dq) / 1024)    // blocks per weight

__global__ void split4_f16(W4 ws, __half2* __restrict__ hi, __half2* __restrict__ lo)
{
    int which = blockIdx.x / WBLK;
    int blk = blockIdx.x % WBLK;
    const float4* in = (which == 0) ? ws.w0 : (which == 1) ? ws.w1
                       : (which == 2) ? ws.w2 : ws.w3;
    size_t idx = (size_t)blk * blockDim.x + threadIdx.x;     // float4 units within matrix
    size_t base = (size_t)which * ((size_t)Dq * Dq / 2);     // half2 units
    float4 a = in[idx];
    __half2 h0 = __floats2half2_rn(a.x, a.y);
    __half2 h1 = __floats2half2_rn(a.z, a.w);
    hi[base + idx * 2]     = h0;
    hi[base + idx * 2 + 1] = h1;
    lo[base + idx * 2]     = __floats2half2_rn(a.x - __low2float(h0), a.y - __high2float(h0));
    lo[base + idx * 2 + 1] = __floats2half2_rn(a.z - __low2float(h1), a.w - __high2float(h1));
}

// ---------------- single-weight split (Wo) ----------------
__global__ void split2_f16(const float4* __restrict__ in, __half2* __restrict__ hi,
                           __half2* __restrict__ lo)
{
    size_t idx = (size_t)blockIdx.x * blockDim.x + threadIdx.x;
    float4 a = in[idx];
    __half2 h0 = __floats2half2_rn(a.x, a.y);
    __half2 h1 = __floats2half2_rn(a.z, a.w);
    hi[idx * 2]     = h0;
    hi[idx * 2 + 1] = h1;
    lo[idx * 2]     = __floats2half2_rn(a.x - __low2float(h0),  a.y - __high2float(h0));
    lo[idx * 2 + 1] = __floats2half2_rn(a.z - __low2float(h1),  a.w - __high2float(h1));
}

// ---------------- HMMA GEMM, fp16 split-2 with per-region lo routing -----------
// C[M, ldc] = A[M,2048](fp16) * (Whi [⊕ Wlo])[N,2048]^T
// lomask bit r: N-region [r*2048,(r+1)*2048) includes the lo correction chunks.
#define STAGE_B 32768
#define GEMM_SMEM_BYTES (3 * STAGE_B)

__global__ __launch_bounds__(256, 2)
void hmma_gemm(const __half* __restrict__ A,
               const __half* __restrict__ Bhi, const __half* __restrict__ Blo,
               float* __restrict__ C, int ldc, int lomask)
{
    extern __shared__ __align__(128) char smem[];
    const uint32_t sb = smem_u32(smem);
    const int tid = threadIdx.x;
    const int warp = tid >> 5, lane = tid & 31;
    const int wm = warp & 1, wn = warp >> 1;
    const int bm = blockIdx.y * 128, bn = blockIdx.x * 128;
    const int nc = ((lomask >> (bn >> 11)) & 1) ? GNC : 32;

    float acc[4][4][4];
#pragma unroll
    for (int i = 0; i < 4; i++)
#pragma unroll
        for (int j = 0; j < 4; j++)
#pragma unroll
            for (int r = 0; r < 4; r++) acc[i][j][r] = 0.f;

    const int lrow = tid >> 3;
    const int lseg = tid & 7;
    const uint32_t loff = SWZ(lrow * 128 + lseg * 16);

#define LOAD_STAGE(s, kc) do { \
        int _k0 = ((kc) & 31) * 64; \
        const __half* _Bb = ((kc) >= 32) ? Blo : Bhi; \
        uint32_t _as = sb + (s) * STAGE_B; \
        uint32_t _bs = _as + 16384; \
        const __half* _ap = A + (size_t)(bm + lrow) * Dq + _k0 + lseg * 8; \
        const __half* _bp = _Bb + (size_t)(bn + lrow) * Dq + _k0 + lseg * 8; \
        _Pragma("unroll") \
        for (int _i = 0; _i < 4; _i++) { \
            cp16(_as + loff + _i * 4096, _ap + (size_t)_i * 32 * Dq); \
            cp16(_bs + loff + _i * 4096, _bp + (size_t)_i * 32 * Dq); \
        } \
        asm volatile("cp.async.commit_group;" ::: "memory"); \
    } while (0)

    // A fragment addressing (ldsm x4, m16k16 per m-tile)
    const int aq = lane >> 3;
    const int am = (lane & 7) + (aq & 1) * 8;
    const int akb = (aq >> 1) * 8;
    // B fragment addressing (packed ldsm x4: two 8-row n-tiles x two k-blocks)
    const int bln = lane & 7;
    const int bsel = lane >> 3;
    const int bnrow = (bsel >> 1) * 8 + bln;
    const int bkoff = (bsel & 1) * 8;

    LOAD_STAGE(0, 0);
    LOAD_STAGE(1, 1);

    for (int c = 0; c < nc; c++) {
        if (c == nc - 1) {
            asm volatile("cp.async.wait_group 0;" ::: "memory");
        } else {
            asm volatile("cp.async.wait_group 1;" ::: "memory");
        }
        __syncthreads();
        if (c + 2 < nc) LOAD_STAGE((c + 2) % 3, c + 2);

        const uint32_t As = sb + (c % 3) * STAGE_B;
        const uint32_t Bs = As + 16384;
#pragma unroll
        for (int ks = 0; ks < 4; ks++) {
            const int k0 = ks * 16;
            uint32_t af[4][4];
#pragma unroll
            for (int mt = 0; mt < 4; mt++) {
                int m = wm * 64 + mt * 16 + am;
                ldsm_x4(af[mt][0], af[mt][1], af[mt][2], af[mt][3],
                        As + SWZ(m * 128 + (k0 + akb) * 2));
            }
            uint32_t bf[4][2];
#pragma unroll
            for (int ntp = 0; ntp < 2; ntp++) {
                int n = wn * 32 + ntp * 16 + bnrow;
                ldsm_x4(bf[2 * ntp][0], bf[2 * ntp][1],
                        bf[2 * ntp + 1][0], bf[2 * ntp + 1][1],
                        Bs + SWZ(n * 128 + (k0 + bkoff) * 2));
            }
#pragma unroll
            for (int mt = 0; mt < 4; mt++)
#pragma unroll
                for (int nt = 0; nt < 4; nt++)
                    mma16816(acc[mt][nt], af[mt], bf[nt]);
        }
    }

    const int r0 = bm + wm * 64 + (lane >> 2);
    const int c0 = bn + wn * 32 + (lane & 3) * 2;
#pragma unroll
    for (int mt = 0; mt < 4; mt++) {
#pragma unroll
        for (int nt = 0; nt < 4; nt++) {
            float2* p0 = (float2*)(C + (size_t)(r0 + mt * 16) * ldc + c0 + nt * 8);
            float2* p1 = (float2*)(C + (size_t)(r0 + mt * 16 + 8) * ldc + c0 + nt * 8);
            *p0 = make_float2(acc[mt][nt][0], acc[mt][nt][1]);
            *p1 = make_float2(acc[mt][nt][2], acc[mt][nt][3]);
        }
    }
}

// ---------------- beta / g kernel ----------------
__global__ void betag_kernel(const float* __restrict__ x,
                             const float* __restrict__ Wb,
                             const float* __restrict__ Wa,
                             const float* __restrict__ A_log,
                             const float* __restrict__ dt_bias,
                             float* __restrict__ beta,
                             float* __restrict__ gdec)
{
    const int bl = blockIdx.x;
    const int h = threadIdx.x >> 5;
    const int lane = threadIdx.x & 31;
    const float* xr = x + (size_t)bl * Dq;
    const float* wb = Wb + (size_t)h * Dq;
    const float* wa = Wa + (size_t)h * Dq;
    float sb = 0.f, sa = 0.f;
    for (int i = lane; i < Dq; i += 32) {
        float xv = xr[i];
        sb += xv * wb[i];
        sa += xv * wa[i];
    }
#pragma unroll
    for (int off = 16; off > 0; off >>= 1) {
        sb += __shfl_down_sync(0xffffffffu, sb, off);
        sa += __shfl_down_sync(0xffffffffu, sa, off);
    }
    if (lane == 0) {
        const int b = bl / Lq, l = bl % Lq;
        float bet = 1.f / (1.f + expf(-sb));
        float z = sa + dt_bias[h];
        float sp = (z > 15.f) ? z : log1pf(expf(z));
        float g = -expf(A_log[h]) * sp;
        size_t o = ((size_t)(b * Hq + h)) * Lq + l;
        beta[o] = bet;
        gdec[o] = g;
    }
}

// ---------------- causal dwconv + silu + l2 norm, 8 timesteps/block ------------
// grid = (BLq/8) * Hq, 128 threads
__global__ void conv_kernel(const float* __restrict__ proj,
                            const float* __restrict__ wq, const float* __restrict__ wk,
                            const float* __restrict__ wv,
                            float* __restrict__ oq, float* __restrict__ ok,
                            float* __restrict__ ov)
{
    const int blk = blockIdx.x;
    const int h = blk % Hq;
    const int bl8 = blk / Hq;
    const int bl0 = bl8 * 8;
    const int l0 = bl0 % Lq;
    const int d = threadIdx.x;
    const int c = h * Dh + d;
    const int wid = threadIdx.x >> 5;
    const int lane = threadIdx.x & 31;

    const float wq0 = wq[c * KW], wq1 = wq[c * KW + 1], wq2 = wq[c * KW + 2], wq3 = wq[c * KW + 3];
    const float wk0 = wk[c * KW], wk1 = wk[c * KW + 1], wk2 = wk[c * KW + 2], wk3 = wk[c * KW + 3];
    const float wv0 = wv[c * KW], wv1 = wv[c * KW + 1], wv2 = wv[c * KW + 2], wv3 = wv[c * KW + 3];

    float xq0 = 0.f, xq1 = 0.f, xq2 = 0.f;
    float xk0 = 0.f, xk1 = 0.f, xk2 = 0.f;
    float xv0 = 0.f, xv1 = 0.f, xv2 = 0.f;
#pragma unroll
    for (int j = 0; j < 3; j++) {
        int ll = l0 - 3 + j;
        if (ll >= 0) {
            size_t idx = (size_t)(bl0 - l0 + ll) * (4 * Dq) + c;
            float q_ = proj[idx], k_ = proj[idx + Dq], v_ = proj[idx + 2 * Dq];
            if (j == 0) { xq0 = q_; xk0 = k_; xv0 = v_; }
            else if (j == 1) { xq1 = q_; xk1 = k_; xv1 = v_; }
            else { xq2 = q_; xk2 = k_; xv2 = v_; }
        }
    }

    __shared__ float shq[4], shk[4];
#pragma unroll 1
    for (int s = 0; s < 8; s++) {
        size_t idx = (size_t)(bl0 + s) * (4 * Dq) + c;
        float xq3 = proj[idx], xk3 = proj[idx + Dq], xv3 = proj[idx + 2 * Dq];

        float aq = wq0 * xq0 + wq1 * xq1 + wq2 * xq2 + wq3 * xq3;
        float ak = wk0 * xk0 + wk1 * xk1 + wk2 * xk2 + wk3 * xk3;
        float av = wv0 * xv0 + wv1 * xv1 + wv2 * xv2 + wv3 * xv3;
        aq = aq / (1.f + expf(-aq));
        ak = ak / (1.f + expf(-ak));
        av = av / (1.f + expf(-av));

        float sq = aq * aq, sk = ak * ak;
#pragma unroll
        for (int off = 16; off > 0; off >>= 1) {
            sq += __shfl_xor_sync(0xffffffffu, sq, off);
            sk += __shfl_xor_sync(0xffffffffu, sk, off);
        }
        __syncthreads();   // protect sh from previous iteration's readers
        if (lane == 0) { shq[wid] = sq; shk[wid] = sk; }
        __syncthreads();
        float sumq = shq[0] + shq[1] + shq[2] + shq[3];
        float sumk = shk[0] + shk[1] + shk[2] + shk[3];
        float invq = 1.f / fmaxf(sqrtf(sumq), 1e-12f);
        float invk = 1.f / fmaxf(sqrtf(sumk), 1e-12f);

        size_t base = (size_t)(bl0 + s) * Dq + c;
        oq[base] = aq * invq * 0.08838834764831845f;
        ok[base] = ak * invk;
        ov[base] = av;

        xq0 = xq1; xq1 = xq2; xq2 = xq3;
        xk0 = xk1; xk1 = xk2; xk2 = xk3;
        xv0 = xv1; xv1 = xv2; xv2 = xv3;
    }
}

// ---------------- chunked gated delta-rule scan (register-tiled) ----------------
#define SKT 132
#define SAT 68
#define SVT 36

#define SK_OFF  0
#define SQ_OFF  8448
#define SS_OFF  16896
#define SA_OFF  21120
#define SV_OFF  25472
#define SP_OFF  27776
#define SC_OFF  30080
#define SCAN_SMEM_FLOATS (SC_OFF + 320)
#define SCAN_SMEM_BYTES (SCAN_SMEM_FLOATS * 4)

__global__ __launch_bounds__(256, 1)
void scan_kernel(const float* __restrict__ q, const float* __restrict__ k,
                 const float* __restrict__ v, const float* __restrict__ beta,
                 const float* __restrict__ gdec, const float* __restrict__ S0,
                 float* __restrict__ o, float* __restrict__ Sout)
{
    extern __shared__ float sm[];
    float* sK = sm + SK_OFF;
    float* sQ = sm + SQ_OFF;
    float* sS = sm + SS_OFF;
    float* sA = sm + SA_OFF;
    float* sV = sm + SV_OFF;
    float* sP = sm + SP_OFF;
    float* slg = sm + SC_OFF;
    float* sgam = slg + 64;
    float* sgCr = sgam + 64;
    float* sbet = sgCr + 64;
    float* sgg = sbet + 64;

    const int bh = blockIdx.x >> 2;
    const int grp = blockIdx.x & 3;
    const int b = bh >> 4;
    const int h = bh & 15;
    const int dv0 = grp * 32;
    const int tid = threadIdx.x;
    const int t_hi = tid >> 4;
    const int t_lo = tid & 15;

    for (int idx = tid; idx < 32 * 128; idx += 256) {
        int dv = idx >> 7, dk = idx & 127;
        sS[dv * SKT + dk] = S0[((size_t)bh * 128 + dv0 + dv) * 128 + dk];
    }

    for (int n = 0; n < Nq; n++) {
        const int l0 = n * Cq;
        for (int idx = tid; idx < 64 * 128; idx += 256) {
            int i = idx >> 7, d = idx & 127;
            size_t gi = (((size_t)(b * Lq + l0 + i)) * Hq + h) * Dh + d;
            sK[i * SKT + d] = k[gi];
            sQ[i * SKT + d] = q[gi];
        }
        for (int idx = tid; idx < 64 * 32; idx += 256) {
            int i = idx >> 5, dv = idx & 31;
            sV[i * SVT + dv] = v[(((size_t)(b * Lq + l0 + i)) * Hq + h) * Dh + dv0 + dv];
        }
        if (tid < 64) {
            sbet[tid] = beta[(size_t)bh * Lq + l0 + tid];
            sgg[tid] = gdec[(size_t)bh * Lq + l0 + tid];
        }
        __syncthreads();
        // warp-parallel inclusive cumsum of sgg -> slg (2 warps + offset)
        if (tid < 64) {
            float vv = sgg[tid];
#pragma unroll
            for (int oo = 1; oo < 32; oo <<= 1) {
                float t = __shfl_up_sync(0xffffffffu, vv, oo);
                if ((tid & 31) >= oo) vv += t;
            }
            slg[tid] = vv;
        }
        __syncthreads();
        if (tid >= 32 && tid < 64) slg[tid] += slg[31];
        __syncthreads();
        const float lgC = slg[63];
        if (tid < 64) {
            sgam[tid] = expf(slg[tid]);
            sgCr[tid] = expf(lgC - slg[tid]);
        }
        __syncthreads();
        const float gammaC = expf(lgC);

        {
            float acc[4][4];
#pragma unroll
            for (int r = 0; r < 4; r++)
#pragma unroll
                for (int c = 0; c < 4; c++) acc[r][c] = 0.f;
            for (int d = 0; d < 128; d += 4) {
                float4 av[4], bv[4];
#pragma unroll
                for (int r = 0; r < 4; r++)
                    av[r] = *(const float4*)&sK[(t_hi + 16 * r) * SKT + d];
#pragma unroll
                for (int c = 0; c < 4; c++)
                    bv[c] = *(const float4*)&sK[(t_lo + 16 * c) * SKT + d];
#pragma unroll
                for (int r = 0; r < 4; r++)
#pragma unroll
                    for (int c = 0; c < 4; c++) acc[r][c] += dot4(av[r], bv[c]);
            }
#pragma unroll
            for (int r = 0; r < 4; r++) {
                int i = t_hi + 16 * r;
#pragma unroll
                for (int c = 0; c < 4; c++) {
                    int j = t_lo + 16 * c;
                    float val;
                    if (j < i) val = sbet[i] * expf(slg[i] - slg[j]) * acc[r][c];
                    else val = (i == j) ? 1.f : 0.f;
                    sA[i * SAT + j] = val;
                }
            }
        }
        __syncthreads();

        {
            float acc[4][2];
#pragma unroll
            for (int r = 0; r < 4; r++) { acc[r][0] = 0.f; acc[r][1] = 0.f; }
            for (int d = 0; d < 128; d += 4) {
                float4 av[4], bv[2];
#pragma unroll
                for (int r = 0; r < 4; r++)
                    av[r] = *(const float4*)&sK[(t_hi + 16 * r) * SKT + d];
                bv[0] = *(const float4*)&sS[t_lo * SKT + d];
                bv[1] = *(const float4*)&sS[(t_lo + 16) * SKT + d];
#pragma unroll
                for (int r = 0; r < 4; r++) {
                    acc[r][0] += dot4(av[r], bv[0]);
                    acc[r][1] += dot4(av[r], bv[1]);
                }
            }
#pragma unroll
            for (int r = 0; r < 4; r++) {
                int i = t_hi + 16 * r;
#pragma unroll
                for (int c = 0; c < 2; c++) {
                    int dv = t_lo + 16 * c;
                    sP[i * SVT + dv] = sbet[i] * (sV[i * SVT + dv] - sgam[i] * acc[r][c]);
                }
            }
        }
        __syncthreads();

#pragma unroll 1
        for (int blk = 0; blk < 8; blk++) {
            const int r0 = blk * 8;
            if (tid < 32) {
                const int dv = tid;
                float vals[8];
                vals[0] = sP[r0 * SVT + dv];
#pragma unroll
                for (int r = 1; r < 8; r++) {
                    float acc = sP[(r0 + r) * SVT + dv];
#pragma unroll
                    for (int m = 0; m < 8; m++)
                        if (m < r) acc -= sA[(r0 + r) * SAT + r0 + m] * vals[m];
                    vals[r] = acc;
                }
#pragma unroll
                for (int r = 1; r < 8; r++) sP[(r0 + r) * SVT + dv] = vals[r];
            }
            __syncthreads();
            const int nrem = 64 - r0 - 8;
            if (nrem > 0) {
                for (int idx = tid; idx < nrem * 32; idx += 256) {
                    int i = r0 + 8 + (idx >> 5);
                    int dv = idx & 31;
                    float acc = sP[i * SVT + dv];
#pragma unroll
                    for (int m = 0; m < 8; m++)
                        acc -= sA[i * SAT + r0 + m] * sP[(r0 + m) * SVT + dv];
                    sP[i * SVT + dv] = acc;
                }
            }
            __syncthreads();
        }

        {
            float acc[4][4];
#pragma unroll
            for (int r = 0; r < 4; r++)
#pragma unroll
                for (int c = 0; c < 4; c++) acc[r][c] = 0.f;
            for (int d = 0; d < 128; d += 4) {
                float4 av[4], bv[4];
#pragma unroll
                for (int r = 0; r < 4; r++)
                    av[r] = *(const float4*)&sQ[(t_hi + 16 * r) * SKT + d];
#pragma unroll
                for (int c = 0; c < 4; c++)
                    bv[c] = *(const float4*)&sK[(t_lo + 16 * c) * SKT + d];
#pragma unroll
                for (int r = 0; r < 4; r++)
#pragma unroll
                    for (int c = 0; c < 4; c++) acc[r][c] += dot4(av[r], bv[c]);
            }
#pragma unroll
            for (int r = 0; r < 4; r++) {
                int i = t_hi + 16 * r;
#pragma unroll
                for (int c = 0; c < 4; c++) {
                    int j = t_lo + 16 * c;
                    float val = (j <= i) ? expf(slg[i] - slg[j]) * acc[r][c] : 0.f;
                    sA[i * SAT + j] = val;
                }
            }
        }
        __syncthreads();

        {
            float acc1[4][2], acc2[4][2];
#pragma unroll
            for (int r = 0; r < 4; r++) {
                acc1[r][0] = acc1[r][1] = 0.f;
                acc2[r][0] = acc2[r][1] = 0.f;
            }
            for (int d = 0; d < 128; d += 4) {
                float4 av[4], bv[2];
#pragma unroll
                for (int r = 0; r < 4; r++)
                    av[r] = *(const float4*)&sQ[(t_hi + 16 * r) * SKT + d];
                bv[0] = *(const float4*)&sS[t_lo * SKT + d];
                bv[1] = *(const float4*)&sS[(t_lo + 16) * SKT + d];
#pragma unroll
                for (int r = 0; r < 4; r++) {
                    acc1[r][0] += dot4(av[r], bv[0]);
                    acc1[r][1] += dot4(av[r], bv[1]);
                }
            }
            for (int j = 0; j < 64; j++) {
                float b0 = sP[j * SVT + t_lo];
                float b1 = sP[j * SVT + t_lo + 16];
#pragma unroll
                for (int r = 0; r < 4; r++) {
                    float a = sA[(t_hi + 16 * r) * SAT + j];
                    acc2[r][0] += a * b0;
                    acc2[r][1] += a * b1;
                }
            }
#pragma unroll
            for (int r = 0; r < 4; r++) {
                int i = t_hi + 16 * r;
                float g = sgam[i];
                size_t go = (((size_t)(b * Lq + l0 + i)) * Hq + h) * Dh + dv0;
                o[go + t_lo] = g * acc1[r][0] + acc2[r][0];
                o[go + t_lo + 16] = g * acc1[r][1] + acc2[r][1];
            }
        }
        __syncthreads();

        {
            const int dkb = t_lo * 8;
            float acc[2][8];
#pragma unroll
            for (int r = 0; r < 2; r++)
#pragma unroll
                for (int c = 0; c < 8; c++) acc[r][c] = 0.f;
            for (int i = 0; i < 64; i++) {
                float gc = sgCr[i];
                float a0 = sP[i * SVT + t_hi] * gc;
                float a1 = sP[i * SVT + t_hi + 16] * gc;
                float4 k0 = *(const float4*)&sK[i * SKT + dkb];
                float4 k1 = *(const float4*)&sK[i * SKT + dkb + 4];
                acc[0][0] += a0 * k0.x; acc[0][1] += a0 * k0.y;
                acc[0][2] += a0 * k0.z; acc[0][3] += a0 * k0.w;
                acc[0][4] += a0 * k1.x; acc[0][5] += a0 * k1.y;
                acc[0][6] += a0 * k1.z; acc[0][7] += a0 * k1.w;
                acc[1][0] += a1 * k0.x; acc[1][1] += a1 * k0.y;
                acc[1][2] += a1 * k0.z; acc[1][3] += a1 * k0.w;
                acc[1][4] += a1 * k1.x; acc[1][5] += a1 * k1.y;
                acc[1][6] += a1 * k1.z; acc[1][7] += a1 * k1.w;
            }
#pragma unroll
            for (int r = 0; r < 2; r++) {
                int dv = t_hi + 16 * r;
#pragma unroll
                for (int c = 0; c < 8; c++) {
                    float* p = &sS[dv * SKT + dkb + c];
                    *p = gammaC * *p + acc[r][c];
                }
            }
        }
        __syncthreads();
    }

    for (int idx = tid; idx < 32 * 128; idx += 256) {
        int dv = idx >> 7, dk = idx & 127;
        Sout[((size_t)bh * 128 + dv0 + dv) * 128 + dk] = sS[dv * SKT + dk];
    }
}

// ---------------- RMSNorm + gate (silu) -> fp16 directly ----------------
__global__ void gate_kernel(const float* __restrict__ o, const float* __restrict__ proj,
                            const float* __restrict__ norm_w,
                            __half* __restrict__ oh)
{
    const size_t base = (size_t)blockIdx.x * Dh + threadIdx.x;
    const size_t row = blockIdx.x >> 4;
    const size_t inner = (size_t)(blockIdx.x & 15) * Dh + threadIdx.x;
    float ov = o[base];
    float s = ov * ov;
#pragma unroll
    for (int off = 16; off > 0; off >>= 1) s += __shfl_xor_sync(0xffffffffu, s, off);
    __shared__ float sh[4];
    const int wid = threadIdx.x >> 5;
    if ((threadIdx.x & 31) == 0) sh[wid] = s;
    __syncthreads();
    float mean = (sh[0] + sh[1] + sh[2] + sh[3]) * (1.f / 128.f);
    float rs = rsqrtf(mean + EPSq);
    float gv = proj[row * (4 * Dq) + 3 * Dq + inner];
    float sig = gv / (1.f + expf(-gv));
    float val = ov * rs * norm_w[threadIdx.x] * sig;
    oh[base] = __float2half_rn(val);
}

// ---------------- launch ----------------
extern "C" void kernel_launch(void* const* d_in, const int* in_sizes, int n_in,
                              void* d_out, int out_size)
{
    const float* x = (const float*)d_in[0];
    const float* Wq = (const float*)d_in[1];
    const float* Wk = (const float*)d_in[2];
    const float* Wv = (const float*)d_in[3];
    const float* Wb = (const float*)d_in[4];
    const float* Wa = (const float*)d_in[5];
    const float* A_log = (const float*)d_in[6];
    const float* dt_bias = (const float*)d_in[7];
    const float* conv_q = (const float*)d_in[8];
    const float* conv_k = (const float*)d_in[9];
    const float* conv_v = (const float*)d_in[10];
    const float* Wg = (const float*)d_in[11];
    const float* norm_w = (const float*)d_in[12];
    const float* Wo = (const float*)d_in[13];
    const float* S0 = (const float*)d_in[14];

    float* out = (float*)d_out;
    float* Sout = out + (size_t)BLD;

    float *proj, *obuf, *qn, *kn, *vn, *beta, *gdec;
    __half *xh, *whi, *wlo;
    cudaGetSymbolAddress((void**)&proj, g_proj);
    cudaGetSymbolAddress((void**)&obuf, g_obuf);
    cudaGetSymbolAddress((void**)&qn, g_qn);
    cudaGetSymbolAddress((void**)&kn, g_kn);
    cudaGetSymbolAddress((void**)&vn, g_vn);
    cudaGetSymbolAddress((void**)&beta, g_beta);
    cudaGetSymbolAddress((void**)&gdec, g_gdec);
    cudaGetSymbolAddress((void**)&xh, g_xh);
    cudaGetSymbolAddress((void**)&whi, g_whi);
    cudaGetSymbolAddress((void**)&wlo, g_wlo);

    cudaFuncSetAttribute(scan_kernel, cudaFuncAttributeMaxDynamicSharedMemorySize,
                         SCAN_SMEM_BYTES);
    cudaFuncSetAttribute(hmma_gemm, cudaFuncAttributeMaxDynamicSharedMemorySize,
                         GEMM_SMEM_BYTES);

    const size_t WSZ = (size_t)Dq * Dq;

    // activations cast + batched weight splits
    cast_f16<<<BLD / 1024, 256>>>((const float4*)x, (__half2*)xh);
    W4 w4 = { (const float4*)Wq, (const float4*)Wk, (const float4*)Wv, (const float4*)Wg };
    split4_f16<<<4 * WBLK, 256>>>(w4, (__half2*)whi, (__half2*)wlo);

    // merged projection GEMM: lo correction only for Wk (region 1) and Wv (region 2)
    dim3 pgrid(4 * Dq / 128, BLq / 128);   // (64, 64)
    hmma_gemm<<<pgrid, 256, GEMM_SMEM_BYTES>>>(xh, whi, wlo, proj, 4 * Dq, 0b0110);

    betag_kernel<<<BLq, 512>>>(x, Wb, Wa, A_log, dt_bias, beta, gdec);

    conv_kernel<<<(BLq / 8) * Hq, 128>>>(proj, conv_q, conv_k, conv_v, qn, kn, vn);

    scan_kernel<<<Bq * Hq * 4, 256, SCAN_SMEM_BYTES>>>(qn, kn, vn, beta, gdec, S0,
                                                       obuf, Sout);

    gate_kernel<<<BLq * Hq, 128>>>(obuf, proj, norm_w, xh);

    // Wo split + output projection (with lo)
    split2_f16<<<WSZ / 1024, 256>>>((const float4*)Wo, (__half2*)(whi + 4 * WSZ),
                                    (__half2*)(wlo + 4 * WSZ));
    dim3 ogrid(Dq / 128, BLq / 128);       // (16, 64)
    hmma_gemm<<<ogrid, 256, GEMM_SMEM_BYTES>>>(xh, whi + 4 * WSZ, wlo + 4 * WSZ,
                                               out, Dq, 0b1);
}

// round 13
// speedup vs baseline: 1.1519x; 1.0064x over previous
#include <cuda_runtime.h>
#include <cuda_bf16.h>
#include <cuda_fp16.h>
#include <cstdint>
#include <cstddef>

#define Bq 2
#define Lq 4096
#define Dq 2048
#define Hq 16
#define Dh 128
#define Cq 64
#define Nq (Lq / Cq)
#define KW 4
#define BLq (Bq * Lq)
#define EPSq 1e-5f

#define GNC 64                // full split-2 chunk count (hi 0-31, lo 32-63)

// ---------------- device scratch buffers ----------------
#define BLD (BLq * Dq)
#define BHL (Bq * Hq * Lq)
#define WROWS (5 * Dq)

__device__ float g_proj[(size_t)BLq * 4 * Dq];
__device__ float g_obuf[BLD];
__device__ float g_qn[BLD];
__device__ float g_kn[BLD];
__device__ float g_vn[BLD];
__device__ float g_beta[BHL];
__device__ float g_gdec[BHL];

__device__ __half g_xh[(size_t)BLq * Dq];
__device__ __half g_whi[(size_t)WROWS * Dq];
__device__ __half g_wlo[(size_t)WROWS * Dq];

// ================= helpers =================
__device__ __forceinline__ uint32_t smem_u32(const void* p) {
    uint32_t a;
    asm("{ .reg .u64 t; cvta.to.shared.u64 t, %1; cvt.u32.u64 %0, t; }" : "=r"(a) : "l"(p));
    return a;
}
#define SWZ(x) ((x) ^ (((x) >> 3) & 0x70))

__device__ __forceinline__ void cp16(uint32_t dst, const void* src) {
    asm volatile("cp.async.cg.shared.global [%0], [%1], 16;" :: "r"(dst), "l"(src));
}
__device__ __forceinline__ void ldsm_x4(uint32_t& r0, uint32_t& r1, uint32_t& r2,
                                        uint32_t& r3, uint32_t a) {
    asm volatile("ldmatrix.sync.aligned.m8n8.x4.shared.b16 {%0,%1,%2,%3}, [%4];"
                 : "=r"(r0), "=r"(r1), "=r"(r2), "=r"(r3) : "r"(a));
}
__device__ __forceinline__ void mma16816(float* d, const uint32_t* a, const uint32_t* b) {
    asm volatile("mma.sync.aligned.m16n8k16.row.col.f32.f16.f16.f32 "
                 "{%0,%1,%2,%3}, {%4,%5,%6,%7}, {%8,%9}, {%0,%1,%2,%3};"
                 : "+f"(d[0]), "+f"(d[1]), "+f"(d[2]), "+f"(d[3])
                 : "r"(a[0]), "r"(a[1]), "r"(a[2]), "r"(a[3]), "r"(b[0]), "r"(b[1]));
}
__device__ __forceinline__ float dot4(float4 a, float4 b) {
    return a.x * b.x + a.y * b.y + a.z * b.z + a.w * b.w;
}

// ---------------- fp32 -> fp16 cast (activations), x4 vectorized ----------------
__global__ void cast_f16(const float4* __restrict__ in, __half2* __restrict__ out)
{
    size_t idx = (size_t)blockIdx.x * blockDim.x + threadIdx.x;
    float4 a = in[idx];
    out[idx * 2]     = __floats2half2_rn(a.x, a.y);
    out[idx * 2 + 1] = __floats2half2_rn(a.z, a.w);
}

// ---------------- batched fp32 -> fp16 hi+lo for 4 weights ----------------
struct W4 { const float4* w0; const float4* w1; const float4* w2; const float4* w3; };

#define WBLK ((Dq * Dq) / 1024)    // blocks per weight

__global__ void split4_f16(W4 ws, __half2* __restrict__ hi, __half2* __restrict__ lo)
{
    int which = blockIdx.x / WBLK;
    int blk = blockIdx.x % WBLK;
    const float4* in = (which == 0) ? ws.w0 : (which == 1) ? ws.w1
                       : (which == 2) ? ws.w2 : ws.w3;
    size_t idx = (size_t)blk * blockDim.x + threadIdx.x;
    size_t base = (size_t)which * ((size_t)Dq * Dq / 2);
    float4 a = in[idx];
    __half2 h0 = __floats2half2_rn(a.x, a.y);
    __half2 h1 = __floats2half2_rn(a.z, a.w);
    hi[base + idx * 2]     = h0;
    hi[base + idx * 2 + 1] = h1;
    lo[base + idx * 2]     = __floats2half2_rn(a.x - __low2float(h0), a.y - __high2float(h0));
    lo[base + idx * 2 + 1] = __floats2half2_rn(a.z - __low2float(h1), a.w - __high2float(h1));
}

// ---------------- single-weight split (Wo) ----------------
__global__ void split2_f16(const float4* __restrict__ in, __half2* __restrict__ hi,
                           __half2* __restrict__ lo)
{
    size_t idx = (size_t)blockIdx.x * blockDim.x + threadIdx.x;
    float4 a = in[idx];
    __half2 h0 = __floats2half2_rn(a.x, a.y);
    __half2 h1 = __floats2half2_rn(a.z, a.w);
    hi[idx * 2]     = h0;
    hi[idx * 2 + 1] = h1;
    lo[idx * 2]     = __floats2half2_rn(a.x - __low2float(h0),  a.y - __high2float(h0));
    lo[idx * 2 + 1] = __floats2half2_rn(a.z - __low2float(h1),  a.w - __high2float(h1));
}

// ---------------- HMMA GEMM, fp16 split-2 with per-region lo routing -----------
// C[M, ldc] = A[M,2048](fp16) * (Whi [⊕ Wlo])[N,2048]^T
// lomask bit r: N-region [r*2048,(r+1)*2048) includes the lo correction chunks.
// Grid: x = M tiles, y = N tiles (so waves are homogeneous in chunk count).
#define STAGE_B 32768
#define GEMM_SMEM_BYTES (3 * STAGE_B)

__global__ __launch_bounds__(256, 2)
void hmma_gemm(const __half* __restrict__ A,
               const __half* __restrict__ Bhi, const __half* __restrict__ Blo,
               float* __restrict__ C, int ldc, int lomask)
{
    extern __shared__ __align__(128) char smem[];
    const uint32_t sb = smem_u32(smem);
    const int tid = threadIdx.x;
    const int warp = tid >> 5, lane = tid & 31;
    const int wm = warp & 1, wn = warp >> 1;
    const int bm = blockIdx.x * 128, bn = blockIdx.y * 128;
    const int nc = ((lomask >> (bn >> 11)) & 1) ? GNC : 32;

    float acc[4][4][4];
#pragma unroll
    for (int i = 0; i < 4; i++)
#pragma unroll
        for (int j = 0; j < 4; j++)
#pragma unroll
            for (int r = 0; r < 4; r++) acc[i][j][r] = 0.f;

    const int lrow = tid >> 3;
    const int lseg = tid & 7;
    const uint32_t loff = SWZ(lrow * 128 + lseg * 16);

#define LOAD_STAGE(s, kc) do { \
        int _k0 = ((kc) & 31) * 64; \
        const __half* _Bb = ((kc) >= 32) ? Blo : Bhi; \
        uint32_t _as = sb + (s) * STAGE_B; \
        uint32_t _bs = _as + 16384; \
        const __half* _ap = A + (size_t)(bm + lrow) * Dq + _k0 + lseg * 8; \
        const __half* _bp = _Bb + (size_t)(bn + lrow) * Dq + _k0 + lseg * 8; \
        _Pragma("unroll") \
        for (int _i = 0; _i < 4; _i++) { \
            cp16(_as + loff + _i * 4096, _ap + (size_t)_i * 32 * Dq); \
            cp16(_bs + loff + _i * 4096, _bp + (size_t)_i * 32 * Dq); \
        } \
        asm volatile("cp.async.commit_group;" ::: "memory"); \
    } while (0)

    // A fragment addressing (ldsm x4, m16k16 per m-tile)
    const int aq = lane >> 3;
    const int am = (lane & 7) + (aq & 1) * 8;
    const int akb = (aq >> 1) * 8;
    // B fragment addressing (packed ldsm x4: two 8-row n-tiles x two k-blocks)
    const int bln = lane & 7;
    const int bsel = lane >> 3;
    const int bnrow = (bsel >> 1) * 8 + bln;
    const int bkoff = (bsel & 1) * 8;

    LOAD_STAGE(0, 0);
    LOAD_STAGE(1, 1);

    for (int c = 0; c < nc; c++) {
        if (c == nc - 1) {
            asm volatile("cp.async.wait_group 0;" ::: "memory");
        } else {
            asm volatile("cp.async.wait_group 1;" ::: "memory");
        }
        __syncthreads();
        if (c + 2 < nc) LOAD_STAGE((c + 2) % 3, c + 2);

        const uint32_t As = sb + (c % 3) * STAGE_B;
        const uint32_t Bs = As + 16384;
#pragma unroll
        for (int ks = 0; ks < 4; ks++) {
            const int k0 = ks * 16;
            uint32_t af[4][4];
#pragma unroll
            for (int mt = 0; mt < 4; mt++) {
                int m = wm * 64 + mt * 16 + am;
                ldsm_x4(af[mt][0], af[mt][1], af[mt][2], af[mt][3],
                        As + SWZ(m * 128 + (k0 + akb) * 2));
            }
            uint32_t bf[4][2];
#pragma unroll
            for (int ntp = 0; ntp < 2; ntp++) {
                int n = wn * 32 + ntp * 16 + bnrow;
                ldsm_x4(bf[2 * ntp][0], bf[2 * ntp][1],
                        bf[2 * ntp + 1][0], bf[2 * ntp + 1][1],
                        Bs + SWZ(n * 128 + (k0 + bkoff) * 2));
            }
#pragma unroll
            for (int mt = 0; mt < 4; mt++)
#pragma unroll
                for (int nt = 0; nt < 4; nt++)
                    mma16816(acc[mt][nt], af[mt], bf[nt]);
        }
    }

    const int r0 = bm + wm * 64 + (lane >> 2);
    const int c0 = bn + wn * 32 + (lane & 3) * 2;
#pragma unroll
    for (int mt = 0; mt < 4; mt++) {
#pragma unroll
        for (int nt = 0; nt < 4; nt++) {
            float2* p0 = (float2*)(C + (size_t)(r0 + mt * 16) * ldc + c0 + nt * 8);
            float2* p1 = (float2*)(C + (size_t)(r0 + mt * 16 + 8) * ldc + c0 + nt * 8);
            *p0 = make_float2(acc[mt][nt][0], acc[mt][nt][1]);
            *p1 = make_float2(acc[mt][nt][2], acc[mt][nt][3]);
        }
    }
}

// ---------------- beta / g kernel (float4 vectorized) ----------------
__global__ void betag_kernel(const float* __restrict__ x,
                             const float* __restrict__ Wb,
                             const float* __restrict__ Wa,
                             const float* __restrict__ A_log,
                             const float* __restrict__ dt_bias,
                             float* __restrict__ beta,
                             float* __restrict__ gdec)
{
    const int bl = blockIdx.x;
    const int h = threadIdx.x >> 5;
    const int lane = threadIdx.x & 31;
    const float4* xr = (const float4*)(x + (size_t)bl * Dq);
    const float4* wb = (const float4*)(Wb + (size_t)h * Dq);
    const float4* wa = (const float4*)(Wa + (size_t)h * Dq);
    float sb = 0.f, sa = 0.f;
#pragma unroll 4
    for (int i = lane; i < Dq / 4; i += 32) {
        float4 xv = xr[i];
        sb += dot4(xv, wb[i]);
        sa += dot4(xv, wa[i]);
    }
#pragma unroll
    for (int off = 16; off > 0; off >>= 1) {
        sb += __shfl_down_sync(0xffffffffu, sb, off);
        sa += __shfl_down_sync(0xffffffffu, sa, off);
    }
    if (lane == 0) {
        const int b = bl / Lq, l = bl % Lq;
        float bet = 1.f / (1.f + expf(-sb));
        float z = sa + dt_bias[h];
        float sp = (z > 15.f) ? z : log1pf(expf(z));
        float g = -expf(A_log[h]) * sp;
        size_t o = ((size_t)(b * Hq + h)) * Lq + l;
        beta[o] = bet;
        gdec[o] = g;
    }
}

// ---------------- causal dwconv + silu + l2 norm, 8 timesteps/block ------------
__global__ void conv_kernel(const float* __restrict__ proj,
                            const float* __restrict__ wq, const float* __restrict__ wk,
                            const float* __restrict__ wv,
                            float* __restrict__ oq, float* __restrict__ ok,
                            float* __restrict__ ov)
{
    const int blk = blockIdx.x;
    const int h = blk % Hq;
    const int bl8 = blk / Hq;
    const int bl0 = bl8 * 8;
    const int l0 = bl0 % Lq;
    const int d = threadIdx.x;
    const int c = h * Dh + d;
    const int wid = threadIdx.x >> 5;
    const int lane = threadIdx.x & 31;

    const float wq0 = wq[c * KW], wq1 = wq[c * KW + 1], wq2 = wq[c * KW + 2], wq3 = wq[c * KW + 3];
    const float wk0 = wk[c * KW], wk1 = wk[c * KW + 1], wk2 = wk[c * KW + 2], wk3 = wk[c * KW + 3];
    const float wv0 = wv[c * KW], wv1 = wv[c * KW + 1], wv2 = wv[c * KW + 2], wv3 = wv[c * KW + 3];

    float xq0 = 0.f, xq1 = 0.f, xq2 = 0.f;
    float xk0 = 0.f, xk1 = 0.f, xk2 = 0.f;
    float xv0 = 0.f, xv1 = 0.f, xv2 = 0.f;
#pragma unroll
    for (int j = 0; j < 3; j++) {
        int ll = l0 - 3 + j;
        if (ll >= 0) {
            size_t idx = (size_t)(bl0 - l0 + ll) * (4 * Dq) + c;
            float q_ = proj[idx], k_ = proj[idx + Dq], v_ = proj[idx + 2 * Dq];
            if (j == 0) { xq0 = q_; xk0 = k_; xv0 = v_; }
            else if (j == 1) { xq1 = q_; xk1 = k_; xv1 = v_; }
            else { xq2 = q_; xk2 = k_; xv2 = v_; }
        }
    }

    __shared__ float shq[4], shk[4];
#pragma unroll 1
    for (int s = 0; s < 8; s++) {
        size_t idx = (size_t)(bl0 + s) * (4 * Dq) + c;
        float xq3 = proj[idx], xk3 = proj[idx + Dq], xv3 = proj[idx + 2 * Dq];

        float aq = wq0 * xq0 + wq1 * xq1 + wq2 * xq2 + wq3 * xq3;
        float ak = wk0 * xk0 + wk1 * xk1 + wk2 * xk2 + wk3 * xk3;
        float av = wv0 * xv0 + wv1 * xv1 + wv2 * xv2 + wv3 * xv3;
        aq = aq / (1.f + expf(-aq));
        ak = ak / (1.f + expf(-ak));
        av = av / (1.f + expf(-av));

        float sq = aq * aq, sk = ak * ak;
#pragma unroll
        for (int off = 16; off > 0; off >>= 1) {
            sq += __shfl_xor_sync(0xffffffffu, sq, off);
            sk += __shfl_xor_sync(0xffffffffu, sk, off);
        }
        __syncthreads();
        if (lane == 0) { shq[wid] = sq; shk[wid] = sk; }
        __syncthreads();
        float sumq = shq[0] + shq[1] + shq[2] + shq[3];
        float sumk = shk[0] + shk[1] + shk[2] + shk[3];
        float invq = 1.f / fmaxf(sqrtf(sumq), 1e-12f);
        float invk = 1.f / fmaxf(sqrtf(sumk), 1e-12f);

        size_t base = (size_t)(bl0 + s) * Dq + c;
        oq[base] = aq * invq * 0.08838834764831845f;
        ok[base] = ak * invk;
        ov[base] = av;

        xq0 = xq1; xq1 = xq2; xq2 = xq3;
        xk0 = xk1; xk1 = xk2; xk2 = xk3;
        xv0 = xv1; xv1 = xv2; xv2 = xv3;
    }
}

// ---------------- chunked gated delta-rule scan (register-tiled) ----------------
#define SKT 132
#define SAT 68
#define SVT 36

#define SK_OFF  0
#define SQ_OFF  8448
#define SS_OFF  16896
#define SA_OFF  21120
#define SV_OFF  25472
#define SP_OFF  27776
#define SC_OFF  30080
#define SCAN_SMEM_FLOATS (SC_OFF + 320)
#define SCAN_SMEM_BYTES (SCAN_SMEM_FLOATS * 4)

__global__ __launch_bounds__(256, 1)
void scan_kernel(const float* __restrict__ q, const float* __restrict__ k,
                 const float* __restrict__ v, const float* __restrict__ beta,
                 const float* __restrict__ gdec, const float* __restrict__ S0,
                 float* __restrict__ o, float* __restrict__ Sout)
{
    extern __shared__ float sm[];
    float* sK = sm + SK_OFF;
    float* sQ = sm + SQ_OFF;
    float* sS = sm + SS_OFF;
    float* sA = sm + SA_OFF;
    float* sV = sm + SV_OFF;
    float* sP = sm + SP_OFF;
    float* slg = sm + SC_OFF;
    float* sgam = slg + 64;
    float* sgCr = sgam + 64;
    float* sbet = sgCr + 64;
    float* sgg = sbet + 64;

    const int bh = blockIdx.x >> 2;
    const int grp = blockIdx.x & 3;
    const int b = bh >> 4;
    const int h = bh & 15;
    const int dv0 = grp * 32;
    const int tid = threadIdx.x;
    const int t_hi = tid >> 4;
    const int t_lo = tid & 15;

    for (int idx = tid; idx < 32 * 128; idx += 256) {
        int dv = idx >> 7, dk = idx & 127;
        sS[dv * SKT + dk] = S0[((size_t)bh * 128 + dv0 + dv) * 128 + dk];
    }

    for (int n = 0; n < Nq; n++) {
        const int l0 = n * Cq;
        for (int idx = tid; idx < 64 * 128; idx += 256) {
            int i = idx >> 7, d = idx & 127;
            size_t gi = (((size_t)(b * Lq + l0 + i)) * Hq + h) * Dh + d;
            sK[i * SKT + d] = k[gi];
            sQ[i * SKT + d] = q[gi];
        }
        for (int idx = tid; idx < 64 * 32; idx += 256) {
            int i = idx >> 5, dv = idx & 31;
            sV[i * SVT + dv] = v[(((size_t)(b * Lq + l0 + i)) * Hq + h) * Dh + dv0 + dv];
        }
        if (tid < 64) {
            sbet[tid] = beta[(size_t)bh * Lq + l0 + tid];
            sgg[tid] = gdec[(size_t)bh * Lq + l0 + tid];
        }
        __syncthreads();
        if (tid < 64) {
            float vv = sgg[tid];
#pragma unroll
            for (int oo = 1; oo < 32; oo <<= 1) {
                float t = __shfl_up_sync(0xffffffffu, vv, oo);
                if ((tid & 31) >= oo) vv += t;
            }
            slg[tid] = vv;
        }
        __syncthreads();
        if (tid >= 32 && tid < 64) slg[tid] += slg[31];
        __syncthreads();
        const float lgC = slg[63];
        if (tid < 64) {
            sgam[tid] = expf(slg[tid]);
            sgCr[tid] = expf(lgC - slg[tid]);
        }
        __syncthreads();
        const float gammaC = expf(lgC);

        {
            float acc[4][4];
#pragma unroll
            for (int r = 0; r < 4; r++)
#pragma unroll
                for (int c = 0; c < 4; c++) acc[r][c] = 0.f;
            for (int d = 0; d < 128; d += 4) {
                float4 av[4], bv[4];
#pragma unroll
                for (int r = 0; r < 4; r++)
                    av[r] = *(const float4*)&sK[(t_hi + 16 * r) * SKT + d];
#pragma unroll
                for (int c = 0; c < 4; c++)
                    bv[c] = *(const float4*)&sK[(t_lo + 16 * c) * SKT + d];
#pragma unroll
                for (int r = 0; r < 4; r++)
#pragma unroll
                    for (int c = 0; c < 4; c++) acc[r][c] += dot4(av[r], bv[c]);
            }
#pragma unroll
            for (int r = 0; r < 4; r++) {
                int i = t_hi + 16 * r;
#pragma unroll
                for (int c = 0; c < 4; c++) {
                    int j = t_lo + 16 * c;
                    float val;
                    if (j < i) val = sbet[i] * expf(slg[i] - slg[j]) * acc[r][c];
                    else val = (i == j) ? 1.f : 0.f;
                    sA[i * SAT + j] = val;
                }
            }
        }
        __syncthreads();

        {
            float acc[4][2];
#pragma unroll
            for (int r = 0; r < 4; r++) { acc[r][0] = 0.f; acc[r][1] = 0.f; }
            for (int d = 0; d < 128; d += 4) {
                float4 av[4], bv[2];
#pragma unroll
                for (int r = 0; r < 4; r++)
                    av[r] = *(const float4*)&sK[(t_hi + 16 * r) * SKT + d];
                bv[0] = *(const float4*)&sS[t_lo * SKT + d];
                bv[1] = *(const float4*)&sS[(t_lo + 16) * SKT + d];
#pragma unroll
                for (int r = 0; r < 4; r++) {
                    acc[r][0] += dot4(av[r], bv[0]);
                    acc[r][1] += dot4(av[r], bv[1]);
                }
            }
#pragma unroll
            for (int r = 0; r < 4; r++) {
                int i = t_hi + 16 * r;
#pragma unroll
                for (int c = 0; c < 2; c++) {
                    int dv = t_lo + 16 * c;
                    sP[i * SVT + dv] = sbet[i] * (sV[i * SVT + dv] - sgam[i] * acc[r][c]);
                }
            }
        }
        __syncthreads();

#pragma unroll 1
        for (int blk = 0; blk < 8; blk++) {
            const int r0 = blk * 8;
            if (tid < 32) {
                const int dv = tid;
                float vals[8];
                vals[0] = sP[r0 * SVT + dv];
#pragma unroll
                for (int r = 1; r < 8; r++) {
                    float acc = sP[(r0 + r) * SVT + dv];
#pragma unroll
                    for (int m = 0; m < 8; m++)
                        if (m < r) acc -= sA[(r0 + r) * SAT + r0 + m] * vals[m];
                    vals[r] = acc;
                }
#pragma unroll
                for (int r = 1; r < 8; r++) sP[(r0 + r) * SVT + dv] = vals[r];
            }
            __syncthreads();
            const int nrem = 64 - r0 - 8;
            if (nrem > 0) {
                for (int idx = tid; idx < nrem * 32; idx += 256) {
                    int i = r0 + 8 + (idx >> 5);
                    int dv = idx & 31;
                    float acc = sP[i * SVT + dv];
#pragma unroll
                    for (int m = 0; m < 8; m++)
                        acc -= sA[i * SAT + r0 + m] * sP[(r0 + m) * SVT + dv];
                    sP[i * SVT + dv] = acc;
                }
            }
            __syncthreads();
        }

        {
            float acc[4][4];
#pragma unroll
            for (int r = 0; r < 4; r++)
#pragma unroll
                for (int c = 0; c < 4; c++) acc[r][c] = 0.f;
            for (int d = 0; d < 128; d += 4) {
                float4 av[4], bv[4];
#pragma unroll
                for (int r = 0; r < 4; r++)
                    av[r] = *(const float4*)&sQ[(t_hi + 16 * r) * SKT + d];
#pragma unroll
                for (int c = 0; c < 4; c++)
                    bv[c] = *(const float4*)&sK[(t_lo + 16 * c) * SKT + d];
#pragma unroll
                for (int r = 0; r < 4; r++)
#pragma unroll
                    for (int c = 0; c < 4; c++) acc[r][c] += dot4(av[r], bv[c]);
            }
#pragma unroll
            for (int r = 0; r < 4; r++) {
                int i = t_hi + 16 * r;
#pragma unroll
                for (int c = 0; c < 4; c++) {
                    int j = t_lo + 16 * c;
                    float val = (j <= i) ? expf(slg[i] - slg[j]) * acc[r][c] : 0.f;
                    sA[i * SAT + j] = val;
                }
            }
        }
        __syncthreads();

        {
            float acc1[4][2], acc2[4][2];
#pragma unroll
            for (int r = 0; r < 4; r++) {
                acc1[r][0] = acc1[r][1] = 0.f;
                acc2[r][0] = acc2[r][1] = 0.f;
            }
            for (int d = 0; d < 128; d += 4) {
                float4 av[4], bv[2];
#pragma unroll
                for (int r = 0; r < 4; r++)
                    av[r] = *(const float4*)&sQ[(t_hi + 16 * r) * SKT + d];
                bv[0] = *(const float4*)&sS[t_lo * SKT + d];
                bv[1] = *(const float4*)&sS[(t_lo + 16) * SKT + d];
#pragma unroll
                for (int r = 0; r < 4; r++) {
                    acc1[r][0] += dot4(av[r], bv[0]);
                    acc1[r][1] += dot4(av[r], bv[1]);
                }
            }
            for (int j = 0; j < 64; j++) {
                float b0 = sP[j * SVT + t_lo];
                float b1 = sP[j * SVT + t_lo + 16];
#pragma unroll
                for (int r = 0; r < 4; r++) {
                    float a = sA[(t_hi + 16 * r) * SAT + j];
                    acc2[r][0] += a * b0;
                    acc2[r][1] += a * b1;
                }
            }
#pragma unroll
            for (int r = 0; r < 4; r++) {
                int i = t_hi + 16 * r;
                float g = sgam[i];
                size_t go = (((size_t)(b * Lq + l0 + i)) * Hq + h) * Dh + dv0;
                o[go + t_lo] = g * acc1[r][0] + acc2[r][0];
                o[go + t_lo + 16] = g * acc1[r][1] + acc2[r][1];
            }
        }
        __syncthreads();

        {
            const int dkb = t_lo * 8;
            float acc[2][8];
#pragma unroll
            for (int r = 0; r < 2; r++)
#pragma unroll
                for (int c = 0; c < 8; c++) acc[r][c] = 0.f;
            for (int i = 0; i < 64; i++) {
                float gc = sgCr[i];
                float a0 = sP[i * SVT + t_hi] * gc;
                float a1 = sP[i * SVT + t_hi + 16] * gc;
                float4 k0 = *(const float4*)&sK[i * SKT + dkb];
                float4 k1 = *(const float4*)&sK[i * SKT + dkb + 4];
                acc[0][0] += a0 * k0.x; acc[0][1] += a0 * k0.y;
                acc[0][2] += a0 * k0.z; acc[0][3] += a0 * k0.w;
                acc[0][4] += a0 * k1.x; acc[0][5] += a0 * k1.y;
                acc[0][6] += a0 * k1.z; acc[0][7] += a0 * k1.w;
                acc[1][0] += a1 * k0.x; acc[1][1] += a1 * k0.y;
                acc[1][2] += a1 * k0.z; acc[1][3] += a1 * k0.w;
                acc[1][4] += a1 * k1.x; acc[1][5] += a1 * k1.y;
                acc[1][6] += a1 * k1.z; acc[1][7] += a1 * k1.w;
            }
#pragma unroll
            for (int r = 0; r < 2; r++) {
                int dv = t_hi + 16 * r;
#pragma unroll
                for (int c = 0; c < 8; c++) {
                    float* p = &sS[dv * SKT + dkb + c];
                    *p = gammaC * *p + acc[r][c];
                }
            }
        }
        __syncthreads();
    }

    for (int idx = tid; idx < 32 * 128; idx += 256) {
        int dv = idx >> 7, dk = idx & 127;
        Sout[((size_t)bh * 128 + dv0 + dv) * 128 + dk] = sS[dv * SKT + dk];
    }
}

// ---------------- RMSNorm + gate (silu) -> fp16 directly ----------------
__global__ void gate_kernel(const float* __restrict__ o, const float* __restrict__ proj,
                            const float* __restrict__ norm_w,
                            __half* __restrict__ oh)
{
    const size_t base = (size_t)blockIdx.x * Dh + threadIdx.x;
    const size_t row = blockIdx.x >> 4;
    const size_t inner = (size_t)(blockIdx.x & 15) * Dh + threadIdx.x;
    float ov = o[base];
    float s = ov * ov;
#pragma unroll
    for (int off = 16; off > 0; off >>= 1) s += __shfl_xor_sync(0xffffffffu, s, off);
    __shared__ float sh[4];
    const int wid = threadIdx.x >> 5;
    if ((threadIdx.x & 31) == 0) sh[wid] = s;
    __syncthreads();
    float mean = (sh[0] + sh[1] + sh[2] + sh[3]) * (1.f / 128.f);
    float rs = rsqrtf(mean + EPSq);
    float gv = proj[row * (4 * Dq) + 3 * Dq + inner];
    float sig = gv / (1.f + expf(-gv));
    float val = ov * rs * norm_w[threadIdx.x] * sig;
    oh[base] = __float2half_rn(val);
}

// ---------------- launch ----------------
extern "C" void kernel_launch(void* const* d_in, const int* in_sizes, int n_in,
                              void* d_out, int out_size)
{
    const float* x = (const float*)d_in[0];
    const float* Wq = (const float*)d_in[1];
    const float* Wk = (const float*)d_in[2];
    const float* Wv = (const float*)d_in[3];
    const float* Wb = (const float*)d_in[4];
    const float* Wa = (const float*)d_in[5];
    const float* A_log = (const float*)d_in[6];
    const float* dt_bias = (const float*)d_in[7];
    const float* conv_q = (const float*)d_in[8];
    const float* conv_k = (const float*)d_in[9];
    const float* conv_v = (const float*)d_in[10];
    const float* Wg = (const float*)d_in[11];
    const float* norm_w = (const float*)d_in[12];
    const float* Wo = (const float*)d_in[13];
    const float* S0 = (const float*)d_in[14];

    float* out = (float*)d_out;
    float* Sout = out + (size_t)BLD;

    float *proj, *obuf, *qn, *kn, *vn, *beta, *gdec;
    __half *xh, *whi, *wlo;
    cudaGetSymbolAddress((void**)&proj, g_proj);
    cudaGetSymbolAddress((void**)&obuf, g_obuf);
    cudaGetSymbolAddress((void**)&qn, g_qn);
    cudaGetSymbolAddress((void**)&kn, g_kn);
    cudaGetSymbolAddress((void**)&vn, g_vn);
    cudaGetSymbolAddress((void**)&beta, g_beta);
    cudaGetSymbolAddress((void**)&gdec, g_gdec);
    cudaGetSymbolAddress((void**)&xh, g_xh);
    cudaGetSymbolAddress((void**)&whi, g_whi);
    cudaGetSymbolAddress((void**)&wlo, g_wlo);

    cudaFuncSetAttribute(scan_kernel, cudaFuncAttributeMaxDynamicSharedMemorySize,
                         SCAN_SMEM_BYTES);
    cudaFuncSetAttribute(hmma_gemm, cudaFuncAttributeMaxDynamicSharedMemorySize,
                         GEMM_SMEM_BYTES);

    const size_t WSZ = (size_t)Dq * Dq;

    // activations cast + batched weight splits
    cast_f16<<<BLD / 1024, 256>>>((const float4*)x, (__half2*)xh);
    W4 w4 = { (const float4*)Wq, (const float4*)Wk, (const float4*)Wv, (const float4*)Wg };
    split4_f16<<<4 * WBLK, 256>>>(w4, (__half2*)whi, (__half2*)wlo);

    // merged projection GEMM (grid: x=M tiles, y=N tiles for homogeneous waves)
    dim3 pgrid(BLq / 128, 4 * Dq / 128);   // (64, 64)
    hmma_gemm<<<pgrid, 256, GEMM_SMEM_BYTES>>>(xh, whi, wlo, proj, 4 * Dq, 0b0110);

    betag_kernel<<<BLq, 512>>>(x, Wb, Wa, A_log, dt_bias, beta, gdec);

    conv_kernel<<<(BLq / 8) * Hq, 128>>>(proj, conv_q, conv_k, conv_v, qn, kn, vn);

    scan_kernel<<<Bq * Hq * 4, 256, SCAN_SMEM_BYTES>>>(qn, kn, vn, beta, gdec, S0,
                                                       obuf, Sout);

    gate_kernel<<<BLq * Hq, 128>>>(obuf, proj, norm_w, xh);

    // Wo split + output projection (with lo)
    split2_f16<<<WSZ / 1024, 256>>>((const float4*)Wo, (__half2*)(whi + 4 * WSZ),
                                    (__half2*)(wlo + 4 * WSZ));
    dim3 ogrid(BLq / 128, Dq / 128);       // (64, 16)
    hmma_gemm<<<ogrid, 256, GEMM_SMEM_BYTES>>>(xh, whi + 4 * WSZ, wlo + 4 * WSZ,
                                               out, Dq, 0b1);
}

// round 14
// speedup vs baseline: 1.2163x; 1.0559x over previous
#include <cuda_runtime.h>
#include <cuda_bf16.h>
#include <cuda_fp16.h>
#include <cstdint>
#include <cstddef>

#define Bq 2
#define Lq 4096
#define Dq 2048
#define Hq 16
#define Dh 128
#define Cq 64
#define Nq (Lq / Cq)
#define KW 4
#define BLq (Bq * Lq)
#define EPSq 1e-5f

#define GNC 64                // full split-2 chunk count (hi 0-31, lo 32-63)

// ---------------- device scratch buffers ----------------
#define BLD (BLq * Dq)
#define BHL (Bq * Hq * Lq)
#define WROWS (5 * Dq)

__device__ float g_proj[(size_t)BLq * 4 * Dq];
__device__ float g_obuf[BLD];
__device__ float g_qn[BLD];
__device__ float g_kn[BLD];
__device__ float g_vn[BLD];
__device__ float g_beta[BHL];
__device__ float g_gdec[BHL];

__device__ __half g_xh[(size_t)BLq * Dq];
__device__ __half g_whi[(size_t)WROWS * Dq];
__device__ __half g_wlo[(size_t)WROWS * Dq];

// ================= helpers =================
__device__ __forceinline__ uint32_t smem_u32(const void* p) {
    uint32_t a;
    asm("{ .reg .u64 t; cvta.to.shared.u64 t, %1; cvt.u32.u64 %0, t; }" : "=r"(a) : "l"(p));
    return a;
}
#define SWZ(x) ((x) ^ (((x) >> 3) & 0x70))

__device__ __forceinline__ void cp16(uint32_t dst, const void* src) {
    asm volatile("cp.async.cg.shared.global [%0], [%1], 16;" :: "r"(dst), "l"(src));
}
__device__ __forceinline__ void ldsm_x4(uint32_t& r0, uint32_t& r1, uint32_t& r2,
                                        uint32_t& r3, uint32_t a) {
    asm volatile("ldmatrix.sync.aligned.m8n8.x4.shared.b16 {%0,%1,%2,%3}, [%4];"
                 : "=r"(r0), "=r"(r1), "=r"(r2), "=r"(r3) : "r"(a));
}
__device__ __forceinline__ void mma16816(float* d, const uint32_t* a, const uint32_t* b) {
    asm volatile("mma.sync.aligned.m16n8k16.row.col.f32.f16.f16.f32 "
                 "{%0,%1,%2,%3}, {%4,%5,%6,%7}, {%8,%9}, {%0,%1,%2,%3};"
                 : "+f"(d[0]), "+f"(d[1]), "+f"(d[2]), "+f"(d[3])
                 : "r"(a[0]), "r"(a[1]), "r"(a[2]), "r"(a[3]), "r"(b[0]), "r"(b[1]));
}
__device__ __forceinline__ float dot4(float4 a, float4 b) {
    return a.x * b.x + a.y * b.y + a.z * b.z + a.w * b.w;
}

// ---------------- fp32 -> fp16 cast, x4 vectorized ----------------
__global__ void cast_f16(const float4* __restrict__ in, __half2* __restrict__ out)
{
    size_t idx = (size_t)blockIdx.x * blockDim.x + threadIdx.x;
    float4 a = in[idx];
    out[idx * 2]     = __floats2half2_rn(a.x, a.y);
    out[idx * 2 + 1] = __floats2half2_rn(a.z, a.w);
}

// ---------------- batched fp32 -> fp16 hi+lo for 4 weights ----------------
struct W4 { const float4* w0; const float4* w1; const float4* w2; const float4* w3; };

#define WBLK ((Dq * Dq) / 1024)

__global__ void split4_f16(W4 ws, __half2* __restrict__ hi, __half2* __restrict__ lo)
{
    int which = blockIdx.x / WBLK;
    int blk = blockIdx.x % WBLK;
    const float4* in = (which == 0) ? ws.w0 : (which == 1) ? ws.w1
                       : (which == 2) ? ws.w2 : ws.w3;
    size_t idx = (size_t)blk * blockDim.x + threadIdx.x;
    size_t base = (size_t)which * ((size_t)Dq * Dq / 2);
    float4 a = in[idx];
    __half2 h0 = __floats2half2_rn(a.x, a.y);
    __half2 h1 = __floats2half2_rn(a.z, a.w);
    hi[base + idx * 2]     = h0;
    hi[base + idx * 2 + 1] = h1;
    lo[base + idx * 2]     = __floats2half2_rn(a.x - __low2float(h0), a.y - __high2float(h0));
    lo[base + idx * 2 + 1] = __floats2half2_rn(a.z - __low2float(h1), a.w - __high2float(h1));
}

// ---------------- HMMA GEMM, fp16 split-2 with per-region lo routing -----------
#define STAGE_B 32768
#define GEMM_SMEM_BYTES (3 * STAGE_B)

__global__ __launch_bounds__(256, 2)
void hmma_gemm(const __half* __restrict__ A,
               const __half* __restrict__ Bhi, const __half* __restrict__ Blo,
               float* __restrict__ C, int ldc, int lomask)
{
    extern __shared__ __align__(128) char smem[];
    const uint32_t sb = smem_u32(smem);
    const int tid = threadIdx.x;
    const int warp = tid >> 5, lane = tid & 31;
    const int wm = warp & 1, wn = warp >> 1;
    const int bm = blockIdx.x * 128, bn = blockIdx.y * 128;
    const int nc = ((lomask >> (bn >> 11)) & 1) ? GNC : 32;

    float acc[4][4][4];
#pragma unroll
    for (int i = 0; i < 4; i++)
#pragma unroll
        for (int j = 0; j < 4; j++)
#pragma unroll
            for (int r = 0; r < 4; r++) acc[i][j][r] = 0.f;

    const int lrow = tid >> 3;
    const int lseg = tid & 7;
    const uint32_t loff = SWZ(lrow * 128 + lseg * 16);

#define LOAD_STAGE(s, kc) do { \
        int _k0 = ((kc) & 31) * 64; \
        const __half* _Bb = ((kc) >= 32) ? Blo : Bhi; \
        uint32_t _as = sb + (s) * STAGE_B; \
        uint32_t _bs = _as + 16384; \
        const __half* _ap = A + (size_t)(bm + lrow) * Dq + _k0 + lseg * 8; \
        const __half* _bp = _Bb + (size_t)(bn + lrow) * Dq + _k0 + lseg * 8; \
        _Pragma("unroll") \
        for (int _i = 0; _i < 4; _i++) { \
            cp16(_as + loff + _i * 4096, _ap + (size_t)_i * 32 * Dq); \
            cp16(_bs + loff + _i * 4096, _bp + (size_t)_i * 32 * Dq); \
        } \
        asm volatile("cp.async.commit_group;" ::: "memory"); \
    } while (0)

    const int aq = lane >> 3;
    const int am = (lane & 7) + (aq & 1) * 8;
    const int akb = (aq >> 1) * 8;
    const int bln = lane & 7;
    const int bsel = lane >> 3;
    const int bnrow = (bsel >> 1) * 8 + bln;
    const int bkoff = (bsel & 1) * 8;

    LOAD_STAGE(0, 0);
    LOAD_STAGE(1, 1);

    for (int c = 0; c < nc; c++) {
        if (c == nc - 1) {
            asm volatile("cp.async.wait_group 0;" ::: "memory");
        } else {
            asm volatile("cp.async.wait_group 1;" ::: "memory");
        }
        __syncthreads();
        if (c + 2 < nc) LOAD_STAGE((c + 2) % 3, c + 2);

        const uint32_t As = sb + (c % 3) * STAGE_B;
        const uint32_t Bs = As + 16384;
#pragma unroll
        for (int ks = 0; ks < 4; ks++) {
            const int k0 = ks * 16;
            uint32_t af[4][4];
#pragma unroll
            for (int mt = 0; mt < 4; mt++) {
                int m = wm * 64 + mt * 16 + am;
                ldsm_x4(af[mt][0], af[mt][1], af[mt][2], af[mt][3],
                        As + SWZ(m * 128 + (k0 + akb) * 2));
            }
            uint32_t bf[4][2];
#pragma unroll
            for (int ntp = 0; ntp < 2; ntp++) {
                int n = wn * 32 + ntp * 16 + bnrow;
                ldsm_x4(bf[2 * ntp][0], bf[2 * ntp][1],
                        bf[2 * ntp + 1][0], bf[2 * ntp + 1][1],
                        Bs + SWZ(n * 128 + (k0 + bkoff) * 2));
            }
#pragma unroll
            for (int mt = 0; mt < 4; mt++)
#pragma unroll
                for (int nt = 0; nt < 4; nt++)
                    mma16816(acc[mt][nt], af[mt], bf[nt]);
        }
    }

    const int r0 = bm + wm * 64 + (lane >> 2);
    const int c0 = bn + wn * 32 + (lane & 3) * 2;
#pragma unroll
    for (int mt = 0; mt < 4; mt++) {
#pragma unroll
        for (int nt = 0; nt < 4; nt++) {
            float2* p0 = (float2*)(C + (size_t)(r0 + mt * 16) * ldc + c0 + nt * 8);
            float2* p1 = (float2*)(C + (size_t)(r0 + mt * 16 + 8) * ldc + c0 + nt * 8);
            *p0 = make_float2(acc[mt][nt][0], acc[mt][nt][1]);
            *p1 = make_float2(acc[mt][nt][2], acc[mt][nt][3]);
        }
    }
}

// ---------------- beta / g as a tiled mini-GEMM + fused epilogue ----------------
// grid = BLq/32 blocks, 256 threads. Each block: 32 x-rows x 32 outputs (16 Wb + 16 Wa).
#define BGK 128
__global__ __launch_bounds__(256)
void betag_gemm(const float* __restrict__ x,
                const float* __restrict__ Wb,
                const float* __restrict__ Wa,
                const float* __restrict__ A_log,
                const float* __restrict__ dt_bias,
                float* __restrict__ beta,
                float* __restrict__ gdec)
{
    __shared__ float xs[32 * (BGK + 4)];
    __shared__ float wsm[32 * (BGK + 4)];
    const int tid = threadIdx.x;
    const int rows32 = blockIdx.x * 32;
    const int t_hi = tid >> 4;    // row pair selector 0..15
    const int t_lo = tid & 15;    // col pair selector 0..15

    float acc[2][2] = {{0.f, 0.f}, {0.f, 0.f}};

    for (int k0 = 0; k0 < Dq; k0 += BGK) {
        // load x chunk [32][BGK] and weight chunk [32][BGK] (rows 0-15 Wb, 16-31 Wa)
        for (int idx = tid; idx < 32 * (BGK / 4); idx += 256) {
            int row = idx / (BGK / 4);
            int col4 = idx % (BGK / 4);
            *(float4*)&xs[row * (BGK + 4) + col4 * 4] =
                *(const float4*)&x[(size_t)(rows32 + row) * Dq + k0 + col4 * 4];
            const float* wsrc = (row < 16) ? (Wb + (size_t)row * Dq)
                                           : (Wa + (size_t)(row - 16) * Dq);
            *(float4*)&wsm[row * (BGK + 4) + col4 * 4] =
                *(const float4*)&wsrc[k0 + col4 * 4];
        }
        __syncthreads();
#pragma unroll 4
        for (int d = 0; d < BGK; d += 4) {
            float4 a0 = *(const float4*)&xs[t_hi * (BGK + 4) + d];
            float4 a1 = *(const float4*)&xs[(t_hi + 16) * (BGK + 4) + d];
            float4 b0 = *(const float4*)&wsm[t_lo * (BGK + 4) + d];
            float4 b1 = *(const float4*)&wsm[(t_lo + 16) * (BGK + 4) + d];
            acc[0][0] += dot4(a0, b0);
            acc[0][1] += dot4(a0, b1);
            acc[1][0] += dot4(a1, b0);
            acc[1][1] += dot4(a1, b1);
        }
        __syncthreads();
    }

    // epilogue: col t_lo -> beta head t_lo ; col t_lo+16 -> gdec head t_lo
    const float dtb = dt_bias[t_lo];
    const float al = expf(A_log[t_lo]);
#pragma unroll
    for (int r = 0; r < 2; r++) {
        int grow = rows32 + t_hi + 16 * r;
        int b = grow >> 12;            // / Lq
        int l = grow & (Lq - 1);
        float sb = acc[r][0];
        float sa = acc[r][1];
        beta[((size_t)(b * Hq + t_lo)) * Lq + l] = 1.f / (1.f + expf(-sb));
        float z = sa + dtb;
        float sp = (z > 15.f) ? z : log1pf(expf(z));
        gdec[((size_t)(b * Hq + t_lo)) * Lq + l] = -al * sp;
    }
}

// ---------------- causal dwconv + silu + l2 norm, 8 timesteps/block ------------
__global__ void conv_kernel(const float* __restrict__ proj,
                            const float* __restrict__ wq, const float* __restrict__ wk,
                            const float* __restrict__ wv,
                            float* __restrict__ oq, float* __restrict__ ok,
                            float* __restrict__ ov)
{
    const int blk = blockIdx.x;
    const int h = blk % Hq;
    const int bl8 = blk / Hq;
    const int bl0 = bl8 * 8;
    const int l0 = bl0 % Lq;
    const int d = threadIdx.x;
    const int c = h * Dh + d;
    const int wid = threadIdx.x >> 5;
    const int lane = threadIdx.x & 31;

    const float wq0 = wq[c * KW], wq1 = wq[c * KW + 1], wq2 = wq[c * KW + 2], wq3 = wq[c * KW + 3];
    const float wk0 = wk[c * KW], wk1 = wk[c * KW + 1], wk2 = wk[c * KW + 2], wk3 = wk[c * KW + 3];
    const float wv0 = wv[c * KW], wv1 = wv[c * KW + 1], wv2 = wv[c * KW + 2], wv3 = wv[c * KW + 3];

    float xq0 = 0.f, xq1 = 0.f, xq2 = 0.f;
    float xk0 = 0.f, xk1 = 0.f, xk2 = 0.f;
    float xv0 = 0.f, xv1 = 0.f, xv2 = 0.f;
#pragma unroll
    for (int j = 0; j < 3; j++) {
        int ll = l0 - 3 + j;
        if (ll >= 0) {
            size_t idx = (size_t)(bl0 - l0 + ll) * (4 * Dq) + c;
            float q_ = proj[idx], k_ = proj[idx + Dq], v_ = proj[idx + 2 * Dq];
            if (j == 0) { xq0 = q_; xk0 = k_; xv0 = v_; }
            else if (j == 1) { xq1 = q_; xk1 = k_; xv1 = v_; }
            else { xq2 = q_; xk2 = k_; xv2 = v_; }
        }
    }

    __shared__ float shq[4], shk[4];
#pragma unroll 1
    for (int s = 0; s < 8; s++) {
        size_t idx = (size_t)(bl0 + s) * (4 * Dq) + c;
        float xq3 = proj[idx], xk3 = proj[idx + Dq], xv3 = proj[idx + 2 * Dq];

        float aq = wq0 * xq0 + wq1 * xq1 + wq2 * xq2 + wq3 * xq3;
        float ak = wk0 * xk0 + wk1 * xk1 + wk2 * xk2 + wk3 * xk3;
        float av = wv0 * xv0 + wv1 * xv1 + wv2 * xv2 + wv3 * xv3;
        aq = aq / (1.f + expf(-aq));
        ak = ak / (1.f + expf(-ak));
        av = av / (1.f + expf(-av));

        float sq = aq * aq, sk = ak * ak;
#pragma unroll
        for (int off = 16; off > 0; off >>= 1) {
            sq += __shfl_xor_sync(0xffffffffu, sq, off);
            sk += __shfl_xor_sync(0xffffffffu, sk, off);
        }
        __syncthreads();
        if (lane == 0) { shq[wid] = sq; shk[wid] = sk; }
        __syncthreads();
        float sumq = shq[0] + shq[1] + shq[2] + shq[3];
        float sumk = shk[0] + shk[1] + shk[2] + shk[3];
        float invq = 1.f / fmaxf(sqrtf(sumq), 1e-12f);
        float invk = 1.f / fmaxf(sqrtf(sumk), 1e-12f);

        size_t base = (size_t)(bl0 + s) * Dq + c;
        oq[base] = aq * invq * 0.08838834764831845f;
        ok[base] = ak * invk;
        ov[base] = av;

        xq0 = xq1; xq1 = xq2; xq2 = xq3;
        xk0 = xk1; xk1 = xk2; xk2 = xk3;
        xv0 = xv1; xv1 = xv2; xv2 = xv3;
    }
}

// ---------------- chunked gated delta-rule scan (register-tiled) ----------------
#define SKT 132
#define SAT 68
#define SVT 36

#define SK_OFF  0
#define SQ_OFF  8448
#define SS_OFF  16896
#define SA_OFF  21120
#define SV_OFF  25472
#define SP_OFF  27776
#define SC_OFF  30080
#define SCAN_SMEM_FLOATS (SC_OFF + 320)
#define SCAN_SMEM_BYTES (SCAN_SMEM_FLOATS * 4)

__global__ __launch_bounds__(256, 1)
void scan_kernel(const float* __restrict__ q, const float* __restrict__ k,
                 const float* __restrict__ v, const float* __restrict__ beta,
                 const float* __restrict__ gdec, const float* __restrict__ S0,
                 float* __restrict__ o, float* __restrict__ Sout)
{
    extern __shared__ float sm[];
    float* sK = sm + SK_OFF;
    float* sQ = sm + SQ_OFF;
    float* sS = sm + SS_OFF;
    float* sA = sm + SA_OFF;
    float* sV = sm + SV_OFF;
    float* sP = sm + SP_OFF;
    float* slg = sm + SC_OFF;
    float* sgam = slg + 64;
    float* sgCr = sgam + 64;
    float* sbet = sgCr + 64;
    float* sgg = sbet + 64;

    const int bh = blockIdx.x >> 2;
    const int grp = blockIdx.x & 3;
    const int b = bh >> 4;
    const int h = bh & 15;
    const int dv0 = grp * 32;
    const int tid = threadIdx.x;
    const int t_hi = tid >> 4;
    const int t_lo = tid & 15;

    for (int idx = tid; idx < 32 * 128; idx += 256) {
        int dv = idx >> 7, dk = idx & 127;
        sS[dv * SKT + dk] = S0[((size_t)bh * 128 + dv0 + dv) * 128 + dk];
    }

    for (int n = 0; n < Nq; n++) {
        const int l0 = n * Cq;
        for (int idx = tid; idx < 64 * 128; idx += 256) {
            int i = idx >> 7, d = idx & 127;
            size_t gi = (((size_t)(b * Lq + l0 + i)) * Hq + h) * Dh + d;
            sK[i * SKT + d] = k[gi];
            sQ[i * SKT + d] = q[gi];
        }
        for (int idx = tid; idx < 64 * 32; idx += 256) {
            int i = idx >> 5, dv = idx & 31;
            sV[i * SVT + dv] = v[(((size_t)(b * Lq + l0 + i)) * Hq + h) * Dh + dv0 + dv];
        }
        if (tid < 64) {
            sbet[tid] = beta[(size_t)bh * Lq + l0 + tid];
            sgg[tid] = gdec[(size_t)bh * Lq + l0 + tid];
        }
        __syncthreads();
        if (tid < 64) {
            float vv = sgg[tid];
#pragma unroll
            for (int oo = 1; oo < 32; oo <<= 1) {
                float t = __shfl_up_sync(0xffffffffu, vv, oo);
                if ((tid & 31) >= oo) vv += t;
            }
            slg[tid] = vv;
        }
        __syncthreads();
        if (tid >= 32 && tid < 64) slg[tid] += slg[31];
        __syncthreads();
        const float lgC = slg[63];
        if (tid < 64) {
            sgam[tid] = expf(slg[tid]);
            sgCr[tid] = expf(lgC - slg[tid]);
        }
        __syncthreads();
        const float gammaC = expf(lgC);

        {
            float acc[4][4];
#pragma unroll
            for (int r = 0; r < 4; r++)
#pragma unroll
                for (int c = 0; c < 4; c++) acc[r][c] = 0.f;
            for (int d = 0; d < 128; d += 4) {
                float4 av[4], bv[4];
#pragma unroll
                for (int r = 0; r < 4; r++)
                    av[r] = *(const float4*)&sK[(t_hi + 16 * r) * SKT + d];
#pragma unroll
                for (int c = 0; c < 4; c++)
                    bv[c] = *(const float4*)&sK[(t_lo + 16 * c) * SKT + d];
#pragma unroll
                for (int r = 0; r < 4; r++)
#pragma unroll
                    for (int c = 0; c < 4; c++) acc[r][c] += dot4(av[r], bv[c]);
            }
#pragma unroll
            for (int r = 0; r < 4; r++) {
                int i = t_hi + 16 * r;
#pragma unroll
                for (int c = 0; c < 4; c++) {
                    int j = t_lo + 16 * c;
                    float val;
                    if (j < i) val = sbet[i] * expf(slg[i] - slg[j]) * acc[r][c];
                    else val = (i == j) ? 1.f : 0.f;
                    sA[i * SAT + j] = val;
                }
            }
        }
        __syncthreads();

        {
            float acc[4][2];
#pragma unroll
            for (int r = 0; r < 4; r++) { acc[r][0] = 0.f; acc[r][1] = 0.f; }
            for (int d = 0; d < 128; d += 4) {
                float4 av[4], bv[2];
#pragma unroll
                for (int r = 0; r < 4; r++)
                    av[r] = *(const float4*)&sK[(t_hi + 16 * r) * SKT + d];
                bv[0] = *(const float4*)&sS[t_lo * SKT + d];
                bv[1] = *(const float4*)&sS[(t_lo + 16) * SKT + d];
#pragma unroll
                for (int r = 0; r < 4; r++) {
                    acc[r][0] += dot4(av[r], bv[0]);
                    acc[r][1] += dot4(av[r], bv[1]);
                }
            }
#pragma unroll
            for (int r = 0; r < 4; r++) {
                int i = t_hi + 16 * r;
#pragma unroll
                for (int c = 0; c < 2; c++) {
                    int dv = t_lo + 16 * c;
                    sP[i * SVT + dv] = sbet[i] * (sV[i * SVT + dv] - sgam[i] * acc[r][c]);
                }
            }
        }
        __syncthreads();

#pragma unroll 1
        for (int blk = 0; blk < 8; blk++) {
            const int r0 = blk * 8;
            if (tid < 32) {
                const int dv = tid;
                float vals[8];
                vals[0] = sP[r0 * SVT + dv];
#pragma unroll
                for (int r = 1; r < 8; r++) {
                    float acc = sP[(r0 + r) * SVT + dv];
#pragma unroll
                    for (int m = 0; m < 8; m++)
                        if (m < r) acc -= sA[(r0 + r) * SAT + r0 + m] * vals[m];
                    vals[r] = acc;
                }
#pragma unroll
                for (int r = 1; r < 8; r++) sP[(r0 + r) * SVT + dv] = vals[r];
            }
            __syncthreads();
            const int nrem = 64 - r0 - 8;
            if (nrem > 0) {
                for (int idx = tid; idx < nrem * 32; idx += 256) {
                    int i = r0 + 8 + (idx >> 5);
                    int dv = idx & 31;
                    float acc = sP[i * SVT + dv];
#pragma unroll
                    for (int m = 0; m < 8; m++)
                        acc -= sA[i * SAT + r0 + m] * sP[(r0 + m) * SVT + dv];
                    sP[i * SVT + dv] = acc;
                }
            }
            __syncthreads();
        }

        {
            float acc[4][4];
#pragma unroll
            for (int r = 0; r < 4; r++)
#pragma unroll
                for (int c = 0; c < 4; c++) acc[r][c] = 0.f;
            for (int d = 0; d < 128; d += 4) {
                float4 av[4], bv[4];
#pragma unroll
                for (int r = 0; r < 4; r++)
                    av[r] = *(const float4*)&sQ[(t_hi + 16 * r) * SKT + d];
#pragma unroll
                for (int c = 0; c < 4; c++)
                    bv[c] = *(const float4*)&sK[(t_lo + 16 * c) * SKT + d];
#pragma unroll
                for (int r = 0; r < 4; r++)
#pragma unroll
                    for (int c = 0; c < 4; c++) acc[r][c] += dot4(av[r], bv[c]);
            }
#pragma unroll
            for (int r = 0; r < 4; r++) {
                int i = t_hi + 16 * r;
#pragma unroll
                for (int c = 0; c < 4; c++) {
                    int j = t_lo + 16 * c;
                    float val = (j <= i) ? expf(slg[i] - slg[j]) * acc[r][c] : 0.f;
                    sA[i * SAT + j] = val;
                }
            }
        }
        __syncthreads();

        {
            float acc1[4][2], acc2[4][2];
#pragma unroll
            for (int r = 0; r < 4; r++) {
                acc1[r][0] = acc1[r][1] = 0.f;
                acc2[r][0] = acc2[r][1] = 0.f;
            }
            for (int d = 0; d < 128; d += 4) {
                float4 av[4], bv[2];
#pragma unroll
                for (int r = 0; r < 4; r++)
                    av[r] = *(const float4*)&sQ[(t_hi + 16 * r) * SKT + d];
                bv[0] = *(const float4*)&sS[t_lo * SKT + d];
                bv[1] = *(const float4*)&sS[(t_lo + 16) * SKT + d];
#pragma unroll
                for (int r = 0; r < 4; r++) {
                    acc1[r][0] += dot4(av[r], bv[0]);
                    acc1[r][1] += dot4(av[r], bv[1]);
                }
            }
            for (int j = 0; j < 64; j++) {
                float b0 = sP[j * SVT + t_lo];
                float b1 = sP[j * SVT + t_lo + 16];
#pragma unroll
                for (int r = 0; r < 4; r++) {
                    float a = sA[(t_hi + 16 * r) * SAT + j];
                    acc2[r][0] += a * b0;
                    acc2[r][1] += a * b1;
                }
            }
#pragma unroll
            for (int r = 0; r < 4; r++) {
                int i = t_hi + 16 * r;
                float g = sgam[i];
                size_t go = (((size_t)(b * Lq + l0 + i)) * Hq + h) * Dh + dv0;
                o[go + t_lo] = g * acc1[r][0] + acc2[r][0];
                o[go + t_lo + 16] = g * acc1[r][1] + acc2[r][1];
            }
        }
        __syncthreads();

        {
            const int dkb = t_lo * 8;
            float acc[2][8];
#pragma unroll
            for (int r = 0; r < 2; r++)
#pragma unroll
                for (int c = 0; c < 8; c++) acc[r][c] = 0.f;
            for (int i = 0; i < 64; i++) {
                float gc = sgCr[i];
                float a0 = sP[i * SVT + t_hi] * gc;
                float a1 = sP[i * SVT + t_hi + 16] * gc;
                float4 k0 = *(const float4*)&sK[i * SKT + dkb];
                float4 k1 = *(const float4*)&sK[i * SKT + dkb + 4];
                acc[0][0] += a0 * k0.x; acc[0][1] += a0 * k0.y;
                acc[0][2] += a0 * k0.z; acc[0][3] += a0 * k0.w;
                acc[0][4] += a0 * k1.x; acc[0][5] += a0 * k1.y;
                acc[0][6] += a0 * k1.z; acc[0][7] += a0 * k1.w;
                acc[1][0] += a1 * k0.x; acc[1][1] += a1 * k0.y;
                acc[1][2] += a1 * k0.z; acc[1][3] += a1 * k0.w;
                acc[1][4] += a1 * k1.x; acc[1][5] += a1 * k1.y;
                acc[1][6] += a1 * k1.z; acc[1][7] += a1 * k1.w;
            }
#pragma unroll
            for (int r = 0; r < 2; r++) {
                int dv = t_hi + 16 * r;
#pragma unroll
                for (int c = 0; c < 8; c++) {
                    float* p = &sS[dv * SKT + dkb + c];
                    *p = gammaC * *p + acc[r][c];
                }
            }
        }
        __syncthreads();
    }

    for (int idx = tid; idx < 32 * 128; idx += 256) {
        int dv = idx >> 7, dk = idx & 127;
        Sout[((size_t)bh * 128 + dv0 + dv) * 128 + dk] = sS[dv * SKT + dk];
    }
}

// ---------------- RMSNorm + gate (silu) -> fp16 directly ----------------
__global__ void gate_kernel(const float* __restrict__ o, const float* __restrict__ proj,
                            const float* __restrict__ norm_w,
                            __half* __restrict__ oh)
{
    const size_t base = (size_t)blockIdx.x * Dh + threadIdx.x;
    const size_t row = blockIdx.x >> 4;
    const size_t inner = (size_t)(blockIdx.x & 15) * Dh + threadIdx.x;
    float ov = o[base];
    float s = ov * ov;
#pragma unroll
    for (int off = 16; off > 0; off >>= 1) s += __shfl_xor_sync(0xffffffffu, s, off);
    __shared__ float sh[4];
    const int wid = threadIdx.x >> 5;
    if ((threadIdx.x & 31) == 0) sh[wid] = s;
    __syncthreads();
    float mean = (sh[0] + sh[1] + sh[2] + sh[3]) * (1.f / 128.f);
    float rs = rsqrtf(mean + EPSq);
    float gv = proj[row * (4 * Dq) + 3 * Dq + inner];
    float sig = gv / (1.f + expf(-gv));
    float val = ov * rs * norm_w[threadIdx.x] * sig;
    oh[base] = __float2half_rn(val);
}

// ---------------- launch ----------------
extern "C" void kernel_launch(void* const* d_in, const int* in_sizes, int n_in,
                              void* d_out, int out_size)
{
    const float* x = (const float*)d_in[0];
    const float* Wq = (const float*)d_in[1];
    const float* Wk = (const float*)d_in[2];
    const float* Wv = (const float*)d_in[3];
    const float* Wb = (const float*)d_in[4];
    const float* Wa = (const float*)d_in[5];
    const float* A_log = (const float*)d_in[6];
    const float* dt_bias = (const float*)d_in[7];
    const float* conv_q = (const float*)d_in[8];
    const float* conv_k = (const float*)d_in[9];
    const float* conv_v = (const float*)d_in[10];
    const float* Wg = (const float*)d_in[11];
    const float* norm_w = (const float*)d_in[12];
    const float* Wo = (const float*)d_in[13];
    const float* S0 = (const float*)d_in[14];

    float* out = (float*)d_out;
    float* Sout = out + (size_t)BLD;

    float *proj, *obuf, *qn, *kn, *vn, *beta, *gdec;
    __half *xh, *whi, *wlo;
    cudaGetSymbolAddress((void**)&proj, g_proj);
    cudaGetSymbolAddress((void**)&obuf, g_obuf);
    cudaGetSymbolAddress((void**)&qn, g_qn);
    cudaGetSymbolAddress((void**)&kn, g_kn);
    cudaGetSymbolAddress((void**)&vn, g_vn);
    cudaGetSymbolAddress((void**)&beta, g_beta);
    cudaGetSymbolAddress((void**)&gdec, g_gdec);
    cudaGetSymbolAddress((void**)&xh, g_xh);
    cudaGetSymbolAddress((void**)&whi, g_whi);
    cudaGetSymbolAddress((void**)&wlo, g_wlo);

    cudaFuncSetAttribute(scan_kernel, cudaFuncAttributeMaxDynamicSharedMemorySize,
                         SCAN_SMEM_BYTES);
    cudaFuncSetAttribute(hmma_gemm, cudaFuncAttributeMaxDynamicSharedMemorySize,
                         GEMM_SMEM_BYTES);

    const size_t WSZ = (size_t)Dq * Dq;

    // activations cast + batched weight splits
    cast_f16<<<BLD / 1024, 256>>>((const float4*)x, (__half2*)xh);
    W4 w4 = { (const float4*)Wq, (const float4*)Wk, (const float4*)Wv, (const float4*)Wg };
    split4_f16<<<4 * WBLK, 256>>>(w4, (__half2*)whi, (__half2*)wlo);

    // merged projection GEMM (lo for Wk region 1 and Wv region 2)
    dim3 pgrid(BLq / 128, 4 * Dq / 128);   // (64, 64)
    hmma_gemm<<<pgrid, 256, GEMM_SMEM_BYTES>>>(xh, whi, wlo, proj, 4 * Dq, 0b0110);

    betag_gemm<<<BLq / 32, 256>>>(x, Wb, Wa, A_log, dt_bias, beta, gdec);

    conv_kernel<<<(BLq / 8) * Hq, 128>>>(proj, conv_q, conv_k, conv_v, qn, kn, vn);

    scan_kernel<<<Bq * Hq * 4, 256, SCAN_SMEM_BYTES>>>(qn, kn, vn, beta, gdec, S0,
                                                       obuf, Sout);

    gate_kernel<<<BLq * Hq, 128>>>(obuf, proj, norm_w, xh);

    // Wo: fp16 hi only (no lo correction) + output projection
    cast_f16<<<WSZ / 1024, 256>>>((const float4*)Wo, (__half2*)(whi + 4 * WSZ));
    dim3 ogrid(BLq / 128, Dq / 128);       // (64, 16)
    hmma_gemm<<<ogrid, 256, GEMM_SMEM_BYTES>>>(xh, whi + 4 * WSZ, whi + 4 * WSZ,
                                               out, Dq, 0);
}

// round 15
// speedup vs baseline: 1.2383x; 1.0181x over previous
#include <cuda_runtime.h>
#include <cuda_bf16.h>
#include <cuda_fp16.h>
#include <cstdint>
#include <cstddef>

#define Bq 2
#define Lq 4096
#define Dq 2048
#define Hq 16
#define Dh 128
#define Cq 64
#define Nq (Lq / Cq)
#define KW 4
#define BLq (Bq * Lq)
#define EPSq 1e-5f

#define GNC 64

// ---------------- device scratch buffers ----------------
#define BLD (BLq * Dq)
#define BHL (Bq * Hq * Lq)
#define WROWS (5 * Dq)
#define NBH (Bq * Hq)          // 32
#define NCHK (NBH * Nq)        // 2048 (bh, chunk) pairs

__device__ float g_proj[(size_t)BLq * 4 * Dq];
__device__ float g_obuf[BLD];
__device__ float g_qn[BLD];
__device__ float g_kn[BLD];
__device__ float g_vn[BLD];
__device__ float g_beta[BHL];
__device__ float g_gdec[BHL];

__device__ float g_Tg[(size_t)NCHK * 4096];    // T * diag(beta*gamma), lower
__device__ float g_At[(size_t)NCHK * 4096];    // attn matrix
__device__ float g_Tv[(size_t)NCHK * 8192];    // T @ (beta*V), [i][dv]
__device__ float g_Gams[(size_t)NCHK * 128];   // [0..63] gamma, [64..127] gCr
__device__ float g_GamC[NCHK];

__device__ __half g_xh[(size_t)BLq * Dq];
__device__ __half g_whi[(size_t)WROWS * Dq];
__device__ __half g_wlo[(size_t)WROWS * Dq];

// ================= helpers =================
__device__ __forceinline__ uint32_t smem_u32(const void* p) {
    uint32_t a;
    asm("{ .reg .u64 t; cvta.to.shared.u64 t, %1; cvt.u32.u64 %0, t; }" : "=r"(a) : "l"(p));
    return a;
}
#define SWZ(x) ((x) ^ (((x) >> 3) & 0x70))

__device__ __forceinline__ void cp16(uint32_t dst, const void* src) {
    asm volatile("cp.async.cg.shared.global [%0], [%1], 16;" :: "r"(dst), "l"(src));
}
__device__ __forceinline__ void ldsm_x4(uint32_t& r0, uint32_t& r1, uint32_t& r2,
                                        uint32_t& r3, uint32_t a) {
    asm volatile("ldmatrix.sync.aligned.m8n8.x4.shared.b16 {%0,%1,%2,%3}, [%4];"
                 : "=r"(r0), "=r"(r1), "=r"(r2), "=r"(r3) : "r"(a));
}
__device__ __forceinline__ void mma16816(float* d, const uint32_t* a, const uint32_t* b) {
    asm volatile("mma.sync.aligned.m16n8k16.row.col.f32.f16.f16.f32 "
                 "{%0,%1,%2,%3}, {%4,%5,%6,%7}, {%8,%9}, {%0,%1,%2,%3};"
                 : "+f"(d[0]), "+f"(d[1]), "+f"(d[2]), "+f"(d[3])
                 : "r"(a[0]), "r"(a[1]), "r"(a[2]), "r"(a[3]), "r"(b[0]), "r"(b[1]));
}
__device__ __forceinline__ float dot4(float4 a, float4 b) {
    return a.x * b.x + a.y * b.y + a.z * b.z + a.w * b.w;
}

// ---------------- fp32 -> fp16 cast ----------------
__global__ void cast_f16(const float4* __restrict__ in, __half2* __restrict__ out)
{
    size_t idx = (size_t)blockIdx.x * blockDim.x + threadIdx.x;
    float4 a = in[idx];
    out[idx * 2]     = __floats2half2_rn(a.x, a.y);
    out[idx * 2 + 1] = __floats2half2_rn(a.z, a.w);
}

// ---------------- batched fp32 -> fp16 hi+lo for 4 weights ----------------
struct W4 { const float4* w0; const float4* w1; const float4* w2; const float4* w3; };

#define WBLK ((Dq * Dq) / 1024)

__global__ void split4_f16(W4 ws, __half2* __restrict__ hi, __half2* __restrict__ lo)
{
    int which = blockIdx.x / WBLK;
    int blk = blockIdx.x % WBLK;
    const float4* in = (which == 0) ? ws.w0 : (which == 1) ? ws.w1
                       : (which == 2) ? ws.w2 : ws.w3;
    size_t idx = (size_t)blk * blockDim.x + threadIdx.x;
    size_t base = (size_t)which * ((size_t)Dq * Dq / 2);
    float4 a = in[idx];
    __half2 h0 = __floats2half2_rn(a.x, a.y);
    __half2 h1 = __floats2half2_rn(a.z, a.w);
    hi[base + idx * 2]     = h0;
    hi[base + idx * 2 + 1] = h1;
    lo[base + idx * 2]     = __floats2half2_rn(a.x - __low2float(h0), a.y - __high2float(h0));
    lo[base + idx * 2 + 1] = __floats2half2_rn(a.z - __low2float(h1), a.w - __high2float(h1));
}

// ---------------- HMMA GEMM (unchanged from R14) -----------
#define STAGE_B 32768
#define GEMM_SMEM_BYTES (3 * STAGE_B)

__global__ __launch_bounds__(256, 2)
void hmma_gemm(const __half* __restrict__ A,
               const __half* __restrict__ Bhi, const __half* __restrict__ Blo,
               float* __restrict__ C, int ldc, int lomask)
{
    extern __shared__ __align__(128) char smem[];
    const uint32_t sb = smem_u32(smem);
    const int tid = threadIdx.x;
    const int warp = tid >> 5, lane = tid & 31;
    const int wm = warp & 1, wn = warp >> 1;
    const int bm = blockIdx.x * 128, bn = blockIdx.y * 128;
    const int nc = ((lomask >> (bn >> 11)) & 1) ? GNC : 32;

    float acc[4][4][4];
#pragma unroll
    for (int i = 0; i < 4; i++)
#pragma unroll
        for (int j = 0; j < 4; j++)
#pragma unroll
            for (int r = 0; r < 4; r++) acc[i][j][r] = 0.f;

    const int lrow = tid >> 3;
    const int lseg = tid & 7;
    const uint32_t loff = SWZ(lrow * 128 + lseg * 16);

#define LOAD_STAGE(s, kc) do { \
        int _k0 = ((kc) & 31) * 64; \
        const __half* _Bb = ((kc) >= 32) ? Blo : Bhi; \
        uint32_t _as = sb + (s) * STAGE_B; \
        uint32_t _bs = _as + 16384; \
        const __half* _ap = A + (size_t)(bm + lrow) * Dq + _k0 + lseg * 8; \
        const __half* _bp = _Bb + (size_t)(bn + lrow) * Dq + _k0 + lseg * 8; \
        _Pragma("unroll") \
        for (int _i = 0; _i < 4; _i++) { \
            cp16(_as + loff + _i * 4096, _ap + (size_t)_i * 32 * Dq); \
            cp16(_bs + loff + _i * 4096, _bp + (size_t)_i * 32 * Dq); \
        } \
        asm volatile("cp.async.commit_group;" ::: "memory"); \
    } while (0)

    const int aq = lane >> 3;
    const int am = (lane & 7) + (aq & 1) * 8;
    const int akb = (aq >> 1) * 8;
    const int bln = lane & 7;
    const int bsel = lane >> 3;
    const int bnrow = (bsel >> 1) * 8 + bln;
    const int bkoff = (bsel & 1) * 8;

    LOAD_STAGE(0, 0);
    LOAD_STAGE(1, 1);

    for (int c = 0; c < nc; c++) {
        if (c == nc - 1) {
            asm volatile("cp.async.wait_group 0;" ::: "memory");
        } else {
            asm volatile("cp.async.wait_group 1;" ::: "memory");
        }
        __syncthreads();
        if (c + 2 < nc) LOAD_STAGE((c + 2) % 3, c + 2);

        const uint32_t As = sb + (c % 3) * STAGE_B;
        const uint32_t Bs = As + 16384;
#pragma unroll
        for (int ks = 0; ks < 4; ks++) {
            const int k0 = ks * 16;
            uint32_t af[4][4];
#pragma unroll
            for (int mt = 0; mt < 4; mt++) {
                int m = wm * 64 + mt * 16 + am;
                ldsm_x4(af[mt][0], af[mt][1], af[mt][2], af[mt][3],
                        As + SWZ(m * 128 + (k0 + akb) * 2));
            }
            uint32_t bf[4][2];
#pragma unroll
            for (int ntp = 0; ntp < 2; ntp++) {
                int n = wn * 32 + ntp * 16 + bnrow;
                ldsm_x4(bf[2 * ntp][0], bf[2 * ntp][1],
                        bf[2 * ntp + 1][0], bf[2 * ntp + 1][1],
                        Bs + SWZ(n * 128 + (k0 + bkoff) * 2));
            }
#pragma unroll
            for (int mt = 0; mt < 4; mt++)
#pragma unroll
                for (int nt = 0; nt < 4; nt++)
                    mma16816(acc[mt][nt], af[mt], bf[nt]);
        }
    }

    const int r0 = bm + wm * 64 + (lane >> 2);
    const int c0 = bn + wn * 32 + (lane & 3) * 2;
#pragma unroll
    for (int mt = 0; mt < 4; mt++) {
#pragma unroll
        for (int nt = 0; nt < 4; nt++) {
            float2* p0 = (float2*)(C + (size_t)(r0 + mt * 16) * ldc + c0 + nt * 8);
            float2* p1 = (float2*)(C + (size_t)(r0 + mt * 16 + 8) * ldc + c0 + nt * 8);
            *p0 = make_float2(acc[mt][nt][0], acc[mt][nt][1]);
            *p1 = make_float2(acc[mt][nt][2], acc[mt][nt][3]);
        }
    }
}

// ---------------- beta / g mini-GEMM (unchanged) ----------------
#define BGK 128
__global__ __launch_bounds__(256)
void betag_gemm(const float* __restrict__ x,
                const float* __restrict__ Wb,
                const float* __restrict__ Wa,
                const float* __restrict__ A_log,
                const float* __restrict__ dt_bias,
                float* __restrict__ beta,
                float* __restrict__ gdec)
{
    __shared__ float xs[32 * (BGK + 4)];
    __shared__ float wsm[32 * (BGK + 4)];
    const int tid = threadIdx.x;
    const int rows32 = blockIdx.x * 32;
    const int t_hi = tid >> 4;
    const int t_lo = tid & 15;

    float acc[2][2] = {{0.f, 0.f}, {0.f, 0.f}};

    for (int k0 = 0; k0 < Dq; k0 += BGK) {
        for (int idx = tid; idx < 32 * (BGK / 4); idx += 256) {
            int row = idx / (BGK / 4);
            int col4 = idx % (BGK / 4);
            *(float4*)&xs[row * (BGK + 4) + col4 * 4] =
                *(const float4*)&x[(size_t)(rows32 + row) * Dq + k0 + col4 * 4];
            const float* wsrc = (row < 16) ? (Wb + (size_t)row * Dq)
                                           : (Wa + (size_t)(row - 16) * Dq);
            *(float4*)&wsm[row * (BGK + 4) + col4 * 4] =
                *(const float4*)&wsrc[k0 + col4 * 4];
        }
        __syncthreads();
#pragma unroll 4
        for (int d = 0; d < BGK; d += 4) {
            float4 a0 = *(const float4*)&xs[t_hi * (BGK + 4) + d];
            float4 a1 = *(const float4*)&xs[(t_hi + 16) * (BGK + 4) + d];
            float4 b0 = *(const float4*)&wsm[t_lo * (BGK + 4) + d];
            float4 b1 = *(const float4*)&wsm[(t_lo + 16) * (BGK + 4) + d];
            acc[0][0] += dot4(a0, b0);
            acc[0][1] += dot4(a0, b1);
            acc[1][0] += dot4(a1, b0);
            acc[1][1] += dot4(a1, b1);
        }
        __syncthreads();
    }

    const float dtb = dt_bias[t_lo];
    const float al = expf(A_log[t_lo]);
#pragma unroll
    for (int r = 0; r < 2; r++) {
        int grow = rows32 + t_hi + 16 * r;
        int b = grow >> 12;
        int l = grow & (Lq - 1);
        float sb = acc[r][0];
        float sa = acc[r][1];
        beta[((size_t)(b * Hq + t_lo)) * Lq + l] = 1.f / (1.f + expf(-sb));
        float z = sa + dtb;
        float sp = (z > 15.f) ? z : log1pf(expf(z));
        gdec[((size_t)(b * Hq + t_lo)) * Lq + l] = -al * sp;
    }
}

// ---------------- conv (unchanged) ------------
__global__ void conv_kernel(const float* __restrict__ proj,
                            const float* __restrict__ wq, const float* __restrict__ wk,
                            const float* __restrict__ wv,
                            float* __restrict__ oq, float* __restrict__ ok,
                            float* __restrict__ ov)
{
    const int blk = blockIdx.x;
    const int h = blk % Hq;
    const int bl8 = blk / Hq;
    const int bl0 = bl8 * 8;
    const int l0 = bl0 % Lq;
    const int d = threadIdx.x;
    const int c = h * Dh + d;
    const int wid = threadIdx.x >> 5;
    const int lane = threadIdx.x & 31;

    const float wq0 = wq[c * KW], wq1 = wq[c * KW + 1], wq2 = wq[c * KW + 2], wq3 = wq[c * KW + 3];
    const float wk0 = wk[c * KW], wk1 = wk[c * KW + 1], wk2 = wk[c * KW + 2], wk3 = wk[c * KW + 3];
    const float wv0 = wv[c * KW], wv1 = wv[c * KW + 1], wv2 = wv[c * KW + 2], wv3 = wv[c * KW + 3];

    float xq0 = 0.f, xq1 = 0.f, xq2 = 0.f;
    float xk0 = 0.f, xk1 = 0.f, xk2 = 0.f;
    float xv0 = 0.f, xv1 = 0.f, xv2 = 0.f;
#pragma unroll
    for (int j = 0; j < 3; j++) {
        int ll = l0 - 3 + j;
        if (ll >= 0) {
            size_t idx = (size_t)(bl0 - l0 + ll) * (4 * Dq) + c;
            float q_ = proj[idx], k_ = proj[idx + Dq], v_ = proj[idx + 2 * Dq];
            if (j == 0) { xq0 = q_; xk0 = k_; xv0 = v_; }
            else if (j == 1) { xq1 = q_; xk1 = k_; xv1 = v_; }
            else { xq2 = q_; xk2 = k_; xv2 = v_; }
        }
    }

    __shared__ float shq[4], shk[4];
#pragma unroll 1
    for (int s = 0; s < 8; s++) {
        size_t idx = (size_t)(bl0 + s) * (4 * Dq) + c;
        float xq3 = proj[idx], xk3 = proj[idx + Dq], xv3 = proj[idx + 2 * Dq];

        float aq = wq0 * xq0 + wq1 * xq1 + wq2 * xq2 + wq3 * xq3;
        float ak = wk0 * xk0 + wk1 * xk1 + wk2 * xk2 + wk3 * xk3;
        float av = wv0 * xv0 + wv1 * xv1 + wv2 * xv2 + wv3 * xv3;
        aq = aq / (1.f + expf(-aq));
        ak = ak / (1.f + expf(-ak));
        av = av / (1.f + expf(-av));

        float sq = aq * aq, sk = ak * ak;
#pragma unroll
        for (int off = 16; off > 0; off >>= 1) {
            sq += __shfl_xor_sync(0xffffffffu, sq, off);
            sk += __shfl_xor_sync(0xffffffffu, sk, off);
        }
        __syncthreads();
        if (lane == 0) { shq[wid] = sq; shk[wid] = sk; }
        __syncthreads();
        float sumq = shq[0] + shq[1] + shq[2] + shq[3];
        float sumk = shk[0] + shk[1] + shk[2] + shk[3];
        float invq = 1.f / fmaxf(sqrtf(sumq), 1e-12f);
        float invk = 1.f / fmaxf(sqrtf(sumk), 1e-12f);

        size_t base = (size_t)(bl0 + s) * Dq + c;
        oq[base] = aq * invq * 0.08838834764831845f;
        ok[base] = ak * invk;
        ov[base] = av;

        xq0 = xq1; xq1 = xq2; xq2 = xq3;
        xk0 = xk1; xk1 = xk2; xk2 = xk3;
        xv0 = xv1; xv1 = xv2; xv2 = xv3;
    }
}

// ============ chunk prep: state-independent per-(bh,chunk) work ============
// grid = NCHK (2048), 256 threads. Computes Tg, attn, Tv, gamma arrays.
#define PKT 132
#define PK_K   0
#define PK_Q   8448
#define PK_A   16896
#define PK_T   21248
#define PK_C   25600
#define PREP_SMEM_FLOATS (PK_C + 320)
#define PREP_SMEM_BYTES (PREP_SMEM_FLOATS * 4)

__global__ __launch_bounds__(256, 1)
void prep_kernel(const float* __restrict__ q, const float* __restrict__ k,
                 const float* __restrict__ v, const float* __restrict__ beta,
                 const float* __restrict__ gdec,
                 float* __restrict__ Tg, float* __restrict__ At,
                 float* __restrict__ Tv, float* __restrict__ Gams,
                 float* __restrict__ GamC)
{
    extern __shared__ float sm[];
    float* sK = sm + PK_K;      // [64][PKT]
    float* sQ = sm + PK_Q;      // [64][PKT]  (later reused for V)
    float* sA = sm + PK_A;      // [64][68]
    float* sT = sm + PK_T;      // [64][68]
    float* slg = sm + PK_C;
    float* sgam = slg + 64;
    float* sbet = sgam + 64;
    float* sgg = sbet + 64;

    const int bhn = blockIdx.x;
    const int bh = bhn >> 6;
    const int n = bhn & 63;
    const int b = bh >> 4;
    const int h = bh & 15;
    const int l0 = n * Cq;
    const int tid = threadIdx.x;
    const int t_hi = tid >> 4;
    const int t_lo = tid & 15;

    for (int idx = tid; idx < 64 * 128; idx += 256) {
        int i = idx >> 7, d = idx & 127;
        size_t gi = (((size_t)(b * Lq + l0 + i)) * Hq + h) * Dh + d;
        sK[i * PKT + d] = k[gi];
        sQ[i * PKT + d] = q[gi];
    }
    if (tid < 64) {
        sbet[tid] = beta[(size_t)bh * Lq + l0 + tid];
        sgg[tid] = gdec[(size_t)bh * Lq + l0 + tid];
    }
    __syncthreads();
    // cumsum
    if (tid < 64) {
        float vv = sgg[tid];
#pragma unroll
        for (int oo = 1; oo < 32; oo <<= 1) {
            float t = __shfl_up_sync(0xffffffffu, vv, oo);
            if ((tid & 31) >= oo) vv += t;
        }
        slg[tid] = vv;
    }
    __syncthreads();
    if (tid >= 32 && tid < 64) slg[tid] += slg[31];
    __syncthreads();
    const float lgC = slg[63];
    if (tid < 64) {
        float gam = expf(slg[tid]);
        sgam[tid] = gam;
        Gams[(size_t)bhn * 128 + tid] = gam;
        Gams[(size_t)bhn * 128 + 64 + tid] = expf(lgC - slg[tid]);
    }
    if (tid == 0) GamC[bhn] = expf(lgC);
    __syncthreads();

    // A = I + beta_i exp(lg_i - lg_j) K_i.K_j (strict lower)
    {
        float acc[4][4];
#pragma unroll
        for (int r = 0; r < 4; r++)
#pragma unroll
            for (int c = 0; c < 4; c++) acc[r][c] = 0.f;
        for (int d = 0; d < 128; d += 4) {
            float4 av[4], bv[4];
#pragma unroll
            for (int r = 0; r < 4; r++)
                av[r] = *(const float4*)&sK[(t_hi + 16 * r) * PKT + d];
#pragma unroll
            for (int c = 0; c < 4; c++)
                bv[c] = *(const float4*)&sK[(t_lo + 16 * c) * PKT + d];
#pragma unroll
            for (int r = 0; r < 4; r++)
#pragma unroll
                for (int c = 0; c < 4; c++) acc[r][c] += dot4(av[r], bv[c]);
        }
#pragma unroll
        for (int r = 0; r < 4; r++) {
            int i = t_hi + 16 * r;
#pragma unroll
            for (int c = 0; c < 4; c++) {
                int j = t_lo + 16 * c;
                float val;
                if (j < i) val = sbet[i] * expf(slg[i] - slg[j]) * acc[r][c];
                else val = (i == j) ? 1.f : 0.f;
                sA[i * 68 + j] = val;
            }
        }
    }

    // attn = exp(lg_i - lg_j) Q_i.K_j (j <= i) -> global directly
    {
        float acc[4][4];
#pragma unroll
        for (int r = 0; r < 4; r++)
#pragma unroll
            for (int c = 0; c < 4; c++) acc[r][c] = 0.f;
        for (int d = 0; d < 128; d += 4) {
            float4 av[4], bv[4];
#pragma unroll
            for (int r = 0; r < 4; r++)
                av[r] = *(const float4*)&sQ[(t_hi + 16 * r) * PKT + d];
#pragma unroll
            for (int c = 0; c < 4; c++)
                bv[c] = *(const float4*)&sK[(t_lo + 16 * c) * PKT + d];
#pragma unroll
            for (int r = 0; r < 4; r++)
#pragma unroll
                for (int c = 0; c < 4; c++) acc[r][c] += dot4(av[r], bv[c]);
        }
        float* dstA = At + (size_t)bhn * 4096;
#pragma unroll
        for (int r = 0; r < 4; r++) {
            int i = t_hi + 16 * r;
#pragma unroll
            for (int c = 0; c < 4; c++) {
                int j = t_lo + 16 * c;
                dstA[i * 64 + j] = (j <= i) ? expf(slg[i] - slg[j]) * acc[r][c] : 0.f;
            }
        }
    }
    __syncthreads();

    // T = A^{-1} column-parallel forward substitution (zeros above diag)
    if (tid < 64) {
        const int j = tid;
        for (int i = 0; i < 64; i++) {
            float s;
            if (i < j) s = 0.f;
            else if (i == j) s = 1.f;
            else {
                s = 0.f;
                for (int m = j; m < i; m++) s -= sA[i * 68 + m] * sT[m * 68 + j];
            }
            sT[i * 68 + j] = s;
        }
    }
    __syncthreads();

    // scale columns by beta[j] (Tb), write Tg = Tb * gamma[j]; load V over sQ
    for (int idx = tid; idx < 4096; idx += 256) {
        int i = idx >> 6, j = idx & 63;
        float tb = sT[i * 68 + j] * sbet[j];
        sT[i * 68 + j] = tb;
        Tg[(size_t)bhn * 4096 + idx] = tb * sgam[j];
    }
    for (int idx = tid; idx < 64 * 128; idx += 256) {
        int i = idx >> 7, d = idx & 127;
        sQ[i * PKT + d] = v[(((size_t)(b * Lq + l0 + i)) * Hq + h) * Dh + d];
    }
    __syncthreads();

    // Tv = Tb @ V : [64][128]
    {
        float acc[4][8];
#pragma unroll
        for (int r = 0; r < 4; r++)
#pragma unroll
            for (int c = 0; c < 8; c++) acc[r][c] = 0.f;
        for (int j = 0; j < 64; j++) {
            float a[4];
#pragma unroll
            for (int r = 0; r < 4; r++) a[r] = sT[(t_hi + 16 * r) * 68 + j];
#pragma unroll
            for (int c = 0; c < 8; c++) {
                float bvv = sQ[j * PKT + t_lo + 16 * c];
#pragma unroll
                for (int r = 0; r < 4; r++) acc[r][c] += a[r] * bvv;
            }
        }
        float* dstT = Tv + (size_t)bhn * 8192;
#pragma unroll
        for (int r = 0; r < 4; r++) {
            int i = t_hi + 16 * r;
#pragma unroll
            for (int c = 0; c < 8; c++)
                dstT[i * 128 + t_lo + 16 * c] = acc[r][c];
        }
    }
}

// ============ sequential scan: state-dependent work only ============
#define SKT 132
#define SS_K   0
#define SS_Q   8448
#define SS_S   16896
#define SS_TG  21120
#define SS_AT  25472
#define SS_TV  29824
#define SS_MID 32128
#define SS_KS  34432
#define SS_C   36736
#define SCAN_SMEM_FLOATS (SS_C + 192)
#define SCAN_SMEM_BYTES (SCAN_SMEM_FLOATS * 4)

__global__ __launch_bounds__(256, 1)
void scan_kernel(const float* __restrict__ q, const float* __restrict__ k,
                 const float* __restrict__ Tg, const float* __restrict__ At,
                 const float* __restrict__ Tv, const float* __restrict__ Gams,
                 const float* __restrict__ GamC, const float* __restrict__ S0,
                 float* __restrict__ o, float* __restrict__ Sout)
{
    extern __shared__ float sm[];
    float* sK = sm + SS_K;       // [64][SKT]
    float* sQ = sm + SS_Q;       // [64][SKT]
    float* sS = sm + SS_S;       // [32][SKT]
    float* sTg = sm + SS_TG;     // [64][68]
    float* sAt = sm + SS_AT;     // [64][68]
    float* sTv = sm + SS_TV;     // [64][36]
    float* sMid = sm + SS_MID;   // [64][36]
    float* sKS = sm + SS_KS;     // [64][36]
    float* sgam = sm + SS_C;
    float* sgCr = sgam + 64;

    const int bh = blockIdx.x >> 2;
    const int grp = blockIdx.x & 3;
    const int b = bh >> 4;
    const int h = bh & 15;
    const int dv0 = grp * 32;
    const int tid = threadIdx.x;
    const int t_hi = tid >> 4;
    const int t_lo = tid & 15;

    for (int idx = tid; idx < 32 * 128; idx += 256) {
        int dv = idx >> 7, dk = idx & 127;
        sS[dv * SKT + dk] = S0[((size_t)bh * 128 + dv0 + dv) * 128 + dk];
    }

    for (int n = 0; n < Nq; n++) {
        const int l0 = n * Cq;
        const int bhn = bh * Nq + n;
        for (int idx = tid; idx < 64 * 128; idx += 256) {
            int i = idx >> 7, d = idx & 127;
            size_t gi = (((size_t)(b * Lq + l0 + i)) * Hq + h) * Dh + d;
            sK[i * SKT + d] = k[gi];
            sQ[i * SKT + d] = q[gi];
        }
        for (int idx = tid; idx < 4096; idx += 256) {
            int i = idx >> 6, j = idx & 63;
            sTg[i * 68 + j] = Tg[(size_t)bhn * 4096 + idx];
            sAt[i * 68 + j] = At[(size_t)bhn * 4096 + idx];
        }
        for (int idx = tid; idx < 64 * 32; idx += 256) {
            int i = idx >> 5, dv = idx & 31;
            sTv[i * 36 + dv] = Tv[(size_t)bhn * 8192 + i * 128 + dv0 + dv];
        }
        if (tid < 64) {
            sgam[tid] = Gams[(size_t)bhn * 128 + tid];
            sgCr[tid] = Gams[(size_t)bhn * 128 + 64 + tid];
        }
        const float gammaC = GamC[bhn];
        __syncthreads();

        // KS[i][dv] = K_i . S_dv
        {
            float acc[4][2];
#pragma unroll
            for (int r = 0; r < 4; r++) { acc[r][0] = 0.f; acc[r][1] = 0.f; }
            for (int d = 0; d < 128; d += 4) {
                float4 av[4], bv[2];
#pragma unroll
                for (int r = 0; r < 4; r++)
                    av[r] = *(const float4*)&sK[(t_hi + 16 * r) * SKT + d];
                bv[0] = *(const float4*)&sS[t_lo * SKT + d];
                bv[1] = *(const float4*)&sS[(t_lo + 16) * SKT + d];
#pragma unroll
                for (int r = 0; r < 4; r++) {
                    acc[r][0] += dot4(av[r], bv[0]);
                    acc[r][1] += dot4(av[r], bv[1]);
                }
            }
#pragma unroll
            for (int r = 0; r < 4; r++) {
                int i = t_hi + 16 * r;
                sKS[i * 36 + t_lo] = acc[r][0];
                sKS[i * 36 + t_lo + 16] = acc[r][1];
            }
        }
        __syncthreads();

        // mid = Tv - Tg @ KS
        {
            float acc[4][2];
#pragma unroll
            for (int r = 0; r < 4; r++) { acc[r][0] = 0.f; acc[r][1] = 0.f; }
            for (int j = 0; j < 64; j++) {
                float b0 = sKS[j * 36 + t_lo];
                float b1 = sKS[j * 36 + t_lo + 16];
#pragma unroll
                for (int r = 0; r < 4; r++) {
                    float a = sTg[(t_hi + 16 * r) * 68 + j];
                    acc[r][0] += a * b0;
                    acc[r][1] += a * b1;
                }
            }
#pragma unroll
            for (int r = 0; r < 4; r++) {
                int i = t_hi + 16 * r;
                sMid[i * 36 + t_lo] = sTv[i * 36 + t_lo] - acc[r][0];
                sMid[i * 36 + t_lo + 16] = sTv[i * 36 + t_lo + 16] - acc[r][1];
            }
        }
        __syncthreads();

        // O = gamma_i * (Q @ S^T) + attn @ mid
        {
            float acc1[4][2], acc2[4][2];
#pragma unroll
            for (int r = 0; r < 4; r++) {
                acc1[r][0] = acc1[r][1] = 0.f;
                acc2[r][0] = acc2[r][1] = 0.f;
            }
            for (int d = 0; d < 128; d += 4) {
                float4 av[4], bv[2];
#pragma unroll
                for (int r = 0; r < 4; r++)
                    av[r] = *(const float4*)&sQ[(t_hi + 16 * r) * SKT + d];
                bv[0] = *(const float4*)&sS[t_lo * SKT + d];
                bv[1] = *(const float4*)&sS[(t_lo + 16) * SKT + d];
#pragma unroll
                for (int r = 0; r < 4; r++) {
                    acc1[r][0] += dot4(av[r], bv[0]);
                    acc1[r][1] += dot4(av[r], bv[1]);
                }
            }
            for (int j = 0; j < 64; j++) {
                float b0 = sMid[j * 36 + t_lo];
                float b1 = sMid[j * 36 + t_lo + 16];
#pragma unroll
                for (int r = 0; r < 4; r++) {
                    float a = sAt[(t_hi + 16 * r) * 68 + j];
                    acc2[r][0] += a * b0;
                    acc2[r][1] += a * b1;
                }
            }
#pragma unroll
            for (int r = 0; r < 4; r++) {
                int i = t_hi + 16 * r;
                float g = sgam[i];
                size_t go = (((size_t)(b * Lq + l0 + i)) * Hq + h) * Dh + dv0;
                o[go + t_lo] = g * acc1[r][0] + acc2[r][0];
                o[go + t_lo + 16] = g * acc1[r][1] + acc2[r][1];
            }
        }
        __syncthreads();

        // S = gammaC * S + (mid_i * gCr_i)^T @ K
        {
            const int dkb = t_lo * 8;
            float acc[2][8];
#pragma unroll
            for (int r = 0; r < 2; r++)
#pragma unroll
                for (int c = 0; c < 8; c++) acc[r][c] = 0.f;
            for (int i = 0; i < 64; i++) {
                float gc = sgCr[i];
                float a0 = sMid[i * 36 + t_hi] * gc;
                float a1 = sMid[i * 36 + t_hi + 16] * gc;
                float4 k0 = *(const float4*)&sK[i * SKT + dkb];
                float4 k1 = *(const float4*)&sK[i * SKT + dkb + 4];
                acc[0][0] += a0 * k0.x; acc[0][1] += a0 * k0.y;
                acc[0][2] += a0 * k0.z; acc[0][3] += a0 * k0.w;
                acc[0][4] += a0 * k1.x; acc[0][5] += a0 * k1.y;
                acc[0][6] += a0 * k1.z; acc[0][7] += a0 * k1.w;
                acc[1][0] += a1 * k0.x; acc[1][1] += a1 * k0.y;
                acc[1][2] += a1 * k0.z; acc[1][3] += a1 * k0.w;
                acc[1][4] += a1 * k1.x; acc[1][5] += a1 * k1.y;
                acc[1][6] += a1 * k1.z; acc[1][7] += a1 * k1.w;
            }
#pragma unroll
            for (int r = 0; r < 2; r++) {
                int dv = t_hi + 16 * r;
#pragma unroll
                for (int c = 0; c < 8; c++) {
                    float* p = &sS[dv * SKT + dkb + c];
                    *p = gammaC * *p + acc[r][c];
                }
            }
        }
        __syncthreads();
    }

    for (int idx = tid; idx < 32 * 128; idx += 256) {
        int dv = idx >> 7, dk = idx & 127;
        Sout[((size_t)bh * 128 + dv0 + dv) * 128 + dk] = sS[dv * SKT + dk];
    }
}

// ---------------- RMSNorm + gate (silu) -> fp16 ----------------
__global__ void gate_kernel(const float* __restrict__ o, const float* __restrict__ proj,
                            const float* __restrict__ norm_w,
                            __half* __restrict__ oh)
{
    const size_t base = (size_t)blockIdx.x * Dh + threadIdx.x;
    const size_t row = blockIdx.x >> 4;
    const size_t inner = (size_t)(blockIdx.x & 15) * Dh + threadIdx.x;
    float ov = o[base];
    float s = ov * ov;
#pragma unroll
    for (int off = 16; off > 0; off >>= 1) s += __shfl_xor_sync(0xffffffffu, s, off);
    __shared__ float sh[4];
    const int wid = threadIdx.x >> 5;
    if ((threadIdx.x & 31) == 0) sh[wid] = s;
    __syncthreads();
    float mean = (sh[0] + sh[1] + sh[2] + sh[3]) * (1.f / 128.f);
    float rs = rsqrtf(mean + EPSq);
    float gv = proj[row * (4 * Dq) + 3 * Dq + inner];
    float sig = gv / (1.f + expf(-gv));
    float val = ov * rs * norm_w[threadIdx.x] * sig;
    oh[base] = __float2half_rn(val);
}

// ---------------- launch ----------------
extern "C" void kernel_launch(void* const* d_in, const int* in_sizes, int n_in,
                              void* d_out, int out_size)
{
    const float* x = (const float*)d_in[0];
    const float* Wq = (const float*)d_in[1];
    const float* Wk = (const float*)d_in[2];
    const float* Wv = (const float*)d_in[3];
    const float* Wb = (const float*)d_in[4];
    const float* Wa = (const float*)d_in[5];
    const float* A_log = (const float*)d_in[6];
    const float* dt_bias = (const float*)d_in[7];
    const float* conv_q = (const float*)d_in[8];
    const float* conv_k = (const float*)d_in[9];
    const float* conv_v = (const float*)d_in[10];
    const float* Wg = (const float*)d_in[11];
    const float* norm_w = (const float*)d_in[12];
    const float* Wo = (const float*)d_in[13];
    const float* S0 = (const float*)d_in[14];

    float* out = (float*)d_out;
    float* Sout = out + (size_t)BLD;

    float *proj, *obuf, *qn, *kn, *vn, *beta, *gdec;
    float *Tg, *At, *Tv, *Gams, *GamC;
    __half *xh, *whi, *wlo;
    cudaGetSymbolAddress((void**)&proj, g_proj);
    cudaGetSymbolAddress((void**)&obuf, g_obuf);
    cudaGetSymbolAddress((void**)&qn, g_qn);
    cudaGetSymbolAddress((void**)&kn, g_kn);
    cudaGetSymbolAddress((void**)&vn, g_vn);
    cudaGetSymbolAddress((void**)&beta, g_beta);
    cudaGetSymbolAddress((void**)&gdec, g_gdec);
    cudaGetSymbolAddress((void**)&Tg, g_Tg);
    cudaGetSymbolAddress((void**)&At, g_At);
    cudaGetSymbolAddress((void**)&Tv, g_Tv);
    cudaGetSymbolAddress((void**)&Gams, g_Gams);
    cudaGetSymbolAddress((void**)&GamC, g_GamC);
    cudaGetSymbolAddress((void**)&xh, g_xh);
    cudaGetSymbolAddress((void**)&whi, g_whi);
    cudaGetSymbolAddress((void**)&wlo, g_wlo);

    cudaFuncSetAttribute(scan_kernel, cudaFuncAttributeMaxDynamicSharedMemorySize,
                         SCAN_SMEM_BYTES);
    cudaFuncSetAttribute(prep_kernel, cudaFuncAttributeMaxDynamicSharedMemorySize,
                         PREP_SMEM_BYTES);
    cudaFuncSetAttribute(hmma_gemm, cudaFuncAttributeMaxDynamicSharedMemorySize,
                         GEMM_SMEM_BYTES);

    const size_t WSZ = (size_t)Dq * Dq;

    cast_f16<<<BLD / 1024, 256>>>((const float4*)x, (__half2*)xh);
    W4 w4 = { (const float4*)Wq, (const float4*)Wk, (const float4*)Wv, (const float4*)Wg };
    split4_f16<<<4 * WBLK, 256>>>(w4, (__half2*)whi, (__half2*)wlo);

    dim3 pgrid(BLq / 128, 4 * Dq / 128);
    hmma_gemm<<<pgrid, 256, GEMM_SMEM_BYTES>>>(xh, whi, wlo, proj, 4 * Dq, 0b0110);

    betag_gemm<<<BLq / 32, 256>>>(x, Wb, Wa, A_log, dt_bias, beta, gdec);

    conv_kernel<<<(BLq / 8) * Hq, 128>>>(proj, conv_q, conv_k, conv_v, qn, kn, vn);

    // parallel chunk prep (state-independent)
    prep_kernel<<<NCHK, 256, PREP_SMEM_BYTES>>>(qn, kn, vn, beta, gdec,
                                                Tg, At, Tv, Gams, GamC);

    // sequential scan (state-dependent only)
    scan_kernel<<<Bq * Hq * 4, 256, SCAN_SMEM_BYTES>>>(qn, kn, Tg, At, Tv, Gams,
                                                       GamC, S0, obuf, Sout);

    gate_kernel<<<BLq * Hq, 128>>>(obuf, proj, norm_w, xh);

    cast_f16<<<WSZ / 1024, 256>>>((const float4*)Wo, (__half2*)(whi + 4 * WSZ));
    dim3 ogrid(BLq / 128, Dq / 128);
    hmma_gemm<<<ogrid, 256, GEMM_SMEM_BYTES>>>(xh, whi + 4 * WSZ, whi + 4 * WSZ,
                                               out, Dq, 0);
}

// round 16
// speedup vs baseline: 1.4299x; 1.1547x over previous
#include <cuda_runtime.h>
#include <cuda_bf16.h>
#include <cuda_fp16.h>
#include <cstdint>
#include <cstddef>

#define Bq 2
#define Lq 4096
#define Dq 2048
#define Hq 16
#define Dh 128
#define Cq 64
#define Nq (Lq / Cq)
#define KW 4
#define BLq (Bq * Lq)
#define EPSq 1e-5f

#define GNC 64

// ---------------- device scratch buffers ----------------
#define BLD (BLq * Dq)
#define BHL (Bq * Hq * Lq)
#define WROWS (5 * Dq)
#define NBH (Bq * Hq)
#define NCHK (NBH * Nq)

__device__ float g_proj[(size_t)BLq * 4 * Dq];
__device__ float g_obuf[BLD];
__device__ float g_qn[BLD];
__device__ float g_kn[BLD];
__device__ float g_vn[BLD];
__device__ float g_beta[BHL];
__device__ float g_gdec[BHL];

__device__ float g_Tg[(size_t)NCHK * 4096];
__device__ float g_At[(size_t)NCHK * 4096];
__device__ float g_Tv[(size_t)NCHK * 8192];
__device__ float g_Gams[(size_t)NCHK * 128];
__device__ float g_GamC[NCHK];

__device__ __half g_xh[(size_t)BLq * Dq];
__device__ __half g_whi[(size_t)WROWS * Dq];
__device__ __half g_wlo[(size_t)WROWS * Dq];

// ================= helpers =================
__device__ __forceinline__ uint32_t smem_u32(const void* p) {
    uint32_t a;
    asm("{ .reg .u64 t; cvta.to.shared.u64 t, %1; cvt.u32.u64 %0, t; }" : "=r"(a) : "l"(p));
    return a;
}
#define SWZ(x) ((x) ^ (((x) >> 3) & 0x70))

__device__ __forceinline__ void cp16(uint32_t dst, const void* src) {
    asm volatile("cp.async.cg.shared.global [%0], [%1], 16;" :: "r"(dst), "l"(src));
}
__device__ __forceinline__ void ldsm_x4(uint32_t& r0, uint32_t& r1, uint32_t& r2,
                                        uint32_t& r3, uint32_t a) {
    asm volatile("ldmatrix.sync.aligned.m8n8.x4.shared.b16 {%0,%1,%2,%3}, [%4];"
                 : "=r"(r0), "=r"(r1), "=r"(r2), "=r"(r3) : "r"(a));
}
__device__ __forceinline__ void mma16816(float* d, const uint32_t* a, const uint32_t* b) {
    asm volatile("mma.sync.aligned.m16n8k16.row.col.f32.f16.f16.f32 "
                 "{%0,%1,%2,%3}, {%4,%5,%6,%7}, {%8,%9}, {%0,%1,%2,%3};"
                 : "+f"(d[0]), "+f"(d[1]), "+f"(d[2]), "+f"(d[3])
                 : "r"(a[0]), "r"(a[1]), "r"(a[2]), "r"(a[3]), "r"(b[0]), "r"(b[1]));
}
__device__ __forceinline__ float dot4(float4 a, float4 b) {
    return a.x * b.x + a.y * b.y + a.z * b.z + a.w * b.w;
}

// ---------------- fp32 -> fp16 cast ----------------
__global__ void cast_f16(const float4* __restrict__ in, __half2* __restrict__ out)
{
    size_t idx = (size_t)blockIdx.x * blockDim.x + threadIdx.x;
    float4 a = in[idx];
    out[idx * 2]     = __floats2half2_rn(a.x, a.y);
    out[idx * 2 + 1] = __floats2half2_rn(a.z, a.w);
}

// ---------------- batched fp32 -> fp16 hi+lo for 4 weights ----------------
struct W4 { const float4* w0; const float4* w1; const float4* w2; const float4* w3; };

#define WBLK ((Dq * Dq) / 1024)

__global__ void split4_f16(W4 ws, __half2* __restrict__ hi, __half2* __restrict__ lo)
{
    int which = blockIdx.x / WBLK;
    int blk = blockIdx.x % WBLK;
    const float4* in = (which == 0) ? ws.w0 : (which == 1) ? ws.w1
                       : (which == 2) ? ws.w2 : ws.w3;
    size_t idx = (size_t)blk * blockDim.x + threadIdx.x;
    size_t base = (size_t)which * ((size_t)Dq * Dq / 2);
    float4 a = in[idx];
    __half2 h0 = __floats2half2_rn(a.x, a.y);
    __half2 h1 = __floats2half2_rn(a.z, a.w);
    hi[base + idx * 2]     = h0;
    hi[base + idx * 2 + 1] = h1;
    lo[base + idx * 2]     = __floats2half2_rn(a.x - __low2float(h0), a.y - __high2float(h0));
    lo[base + idx * 2 + 1] = __floats2half2_rn(a.z - __low2float(h1), a.w - __high2float(h1));
}

// ---------------- HMMA GEMM -----------
#define STAGE_B 32768
#define GEMM_SMEM_BYTES (3 * STAGE_B)

__global__ __launch_bounds__(256, 2)
void hmma_gemm(const __half* __restrict__ A,
               const __half* __restrict__ Bhi, const __half* __restrict__ Blo,
               float* __restrict__ C, int ldc, int lomask)
{
    extern __shared__ __align__(128) char smem[];
    const uint32_t sb = smem_u32(smem);
    const int tid = threadIdx.x;
    const int warp = tid >> 5, lane = tid & 31;
    const int wm = warp & 1, wn = warp >> 1;
    const int bm = blockIdx.x * 128, bn = blockIdx.y * 128;
    const int nc = ((lomask >> (bn >> 11)) & 1) ? GNC : 32;

    float acc[4][4][4];
#pragma unroll
    for (int i = 0; i < 4; i++)
#pragma unroll
        for (int j = 0; j < 4; j++)
#pragma unroll
            for (int r = 0; r < 4; r++) acc[i][j][r] = 0.f;

    const int lrow = tid >> 3;
    const int lseg = tid & 7;
    const uint32_t loff = SWZ(lrow * 128 + lseg * 16);

#define LOAD_STAGE(s, kc) do { \
        int _k0 = ((kc) & 31) * 64; \
        const __half* _Bb = ((kc) >= 32) ? Blo : Bhi; \
        uint32_t _as = sb + (s) * STAGE_B; \
        uint32_t _bs = _as + 16384; \
        const __half* _ap = A + (size_t)(bm + lrow) * Dq + _k0 + lseg * 8; \
        const __half* _bp = _Bb + (size_t)(bn + lrow) * Dq + _k0 + lseg * 8; \
        _Pragma("unroll") \
        for (int _i = 0; _i < 4; _i++) { \
            cp16(_as + loff + _i * 4096, _ap + (size_t)_i * 32 * Dq); \
            cp16(_bs + loff + _i * 4096, _bp + (size_t)_i * 32 * Dq); \
        } \
        asm volatile("cp.async.commit_group;" ::: "memory"); \
    } while (0)

    const int aq = lane >> 3;
    const int am = (lane & 7) + (aq & 1) * 8;
    const int akb = (aq >> 1) * 8;
    const int bln = lane & 7;
    const int bsel = lane >> 3;
    const int bnrow = (bsel >> 1) * 8 + bln;
    const int bkoff = (bsel & 1) * 8;

    LOAD_STAGE(0, 0);
    LOAD_STAGE(1, 1);

    for (int c = 0; c < nc; c++) {
        if (c == nc - 1) {
            asm volatile("cp.async.wait_group 0;" ::: "memory");
        } else {
            asm volatile("cp.async.wait_group 1;" ::: "memory");
        }
        __syncthreads();
        if (c + 2 < nc) LOAD_STAGE((c + 2) % 3, c + 2);

        const uint32_t As = sb + (c % 3) * STAGE_B;
        const uint32_t Bs = As + 16384;
#pragma unroll
        for (int ks = 0; ks < 4; ks++) {
            const int k0 = ks * 16;
            uint32_t af[4][4];
#pragma unroll
            for (int mt = 0; mt < 4; mt++) {
                int m = wm * 64 + mt * 16 + am;
                ldsm_x4(af[mt][0], af[mt][1], af[mt][2], af[mt][3],
                        As + SWZ(m * 128 + (k0 + akb) * 2));
            }
            uint32_t bf[4][2];
#pragma unroll
            for (int ntp = 0; ntp < 2; ntp++) {
                int n = wn * 32 + ntp * 16 + bnrow;
                ldsm_x4(bf[2 * ntp][0], bf[2 * ntp][1],
                        bf[2 * ntp + 1][0], bf[2 * ntp + 1][1],
                        Bs + SWZ(n * 128 + (k0 + bkoff) * 2));
            }
#pragma unroll
            for (int mt = 0; mt < 4; mt++)
#pragma unroll
                for (int nt = 0; nt < 4; nt++)
                    mma16816(acc[mt][nt], af[mt], bf[nt]);
        }
    }

    const int r0 = bm + wm * 64 + (lane >> 2);
    const int c0 = bn + wn * 32 + (lane & 3) * 2;
#pragma unroll
    for (int mt = 0; mt < 4; mt++) {
#pragma unroll
        for (int nt = 0; nt < 4; nt++) {
            float2* p0 = (float2*)(C + (size_t)(r0 + mt * 16) * ldc + c0 + nt * 8);
            float2* p1 = (float2*)(C + (size_t)(r0 + mt * 16 + 8) * ldc + c0 + nt * 8);
            *p0 = make_float2(acc[mt][nt][0], acc[mt][nt][1]);
            *p1 = make_float2(acc[mt][nt][2], acc[mt][nt][3]);
        }
    }
}

// ---------------- beta / g mini-GEMM ----------------
#define BGK 128
__global__ __launch_bounds__(256)
void betag_gemm(const float* __restrict__ x,
                const float* __restrict__ Wb,
                const float* __restrict__ Wa,
                const float* __restrict__ A_log,
                const float* __restrict__ dt_bias,
                float* __restrict__ beta,
                float* __restrict__ gdec)
{
    __shared__ float xs[32 * (BGK + 4)];
    __shared__ float wsm[32 * (BGK + 4)];
    const int tid = threadIdx.x;
    const int rows32 = blockIdx.x * 32;
    const int t_hi = tid >> 4;
    const int t_lo = tid & 15;

    float acc[2][2] = {{0.f, 0.f}, {0.f, 0.f}};

    for (int k0 = 0; k0 < Dq; k0 += BGK) {
        for (int idx = tid; idx < 32 * (BGK / 4); idx += 256) {
            int row = idx / (BGK / 4);
            int col4 = idx % (BGK / 4);
            *(float4*)&xs[row * (BGK + 4) + col4 * 4] =
                *(const float4*)&x[(size_t)(rows32 + row) * Dq + k0 + col4 * 4];
            const float* wsrc = (row < 16) ? (Wb + (size_t)row * Dq)
                                           : (Wa + (size_t)(row - 16) * Dq);
            *(float4*)&wsm[row * (BGK + 4) + col4 * 4] =
                *(const float4*)&wsrc[k0 + col4 * 4];
        }
        __syncthreads();
#pragma unroll 4
        for (int d = 0; d < BGK; d += 4) {
            float4 a0 = *(const float4*)&xs[t_hi * (BGK + 4) + d];
            float4 a1 = *(const float4*)&xs[(t_hi + 16) * (BGK + 4) + d];
            float4 b0 = *(const float4*)&wsm[t_lo * (BGK + 4) + d];
            float4 b1 = *(const float4*)&wsm[(t_lo + 16) * (BGK + 4) + d];
            acc[0][0] += dot4(a0, b0);
            acc[0][1] += dot4(a0, b1);
            acc[1][0] += dot4(a1, b0);
            acc[1][1] += dot4(a1, b1);
        }
        __syncthreads();
    }

    const float dtb = dt_bias[t_lo];
    const float al = expf(A_log[t_lo]);
#pragma unroll
    for (int r = 0; r < 2; r++) {
        int grow = rows32 + t_hi + 16 * r;
        int b = grow >> 12;
        int l = grow & (Lq - 1);
        float sb = acc[r][0];
        float sa = acc[r][1];
        beta[((size_t)(b * Hq + t_lo)) * Lq + l] = 1.f / (1.f + expf(-sb));
        float z = sa + dtb;
        float sp = (z > 15.f) ? z : log1pf(expf(z));
        gdec[((size_t)(b * Hq + t_lo)) * Lq + l] = -al * sp;
    }
}

// ---------------- conv ------------
__global__ void conv_kernel(const float* __restrict__ proj,
                            const float* __restrict__ wq, const float* __restrict__ wk,
                            const float* __restrict__ wv,
                            float* __restrict__ oq, float* __restrict__ ok,
                            float* __restrict__ ov)
{
    const int blk = blockIdx.x;
    const int h = blk % Hq;
    const int bl8 = blk / Hq;
    const int bl0 = bl8 * 8;
    const int l0 = bl0 % Lq;
    const int d = threadIdx.x;
    const int c = h * Dh + d;
    const int wid = threadIdx.x >> 5;
    const int lane = threadIdx.x & 31;

    const float wq0 = wq[c * KW], wq1 = wq[c * KW + 1], wq2 = wq[c * KW + 2], wq3 = wq[c * KW + 3];
    const float wk0 = wk[c * KW], wk1 = wk[c * KW + 1], wk2 = wk[c * KW + 2], wk3 = wk[c * KW + 3];
    const float wv0 = wv[c * KW], wv1 = wv[c * KW + 1], wv2 = wv[c * KW + 2], wv3 = wv[c * KW + 3];

    float xq0 = 0.f, xq1 = 0.f, xq2 = 0.f;
    float xk0 = 0.f, xk1 = 0.f, xk2 = 0.f;
    float xv0 = 0.f, xv1 = 0.f, xv2 = 0.f;
#pragma unroll
    for (int j = 0; j < 3; j++) {
        int ll = l0 - 3 + j;
        if (ll >= 0) {
            size_t idx = (size_t)(bl0 - l0 + ll) * (4 * Dq) + c;
            float q_ = proj[idx], k_ = proj[idx + Dq], v_ = proj[idx + 2 * Dq];
            if (j == 0) { xq0 = q_; xk0 = k_; xv0 = v_; }
            else if (j == 1) { xq1 = q_; xk1 = k_; xv1 = v_; }
            else { xq2 = q_; xk2 = k_; xv2 = v_; }
        }
    }

    __shared__ float shq[4], shk[4];
#pragma unroll 1
    for (int s = 0; s < 8; s++) {
        size_t idx = (size_t)(bl0 + s) * (4 * Dq) + c;
        float xq3 = proj[idx], xk3 = proj[idx + Dq], xv3 = proj[idx + 2 * Dq];

        float aq = wq0 * xq0 + wq1 * xq1 + wq2 * xq2 + wq3 * xq3;
        float ak = wk0 * xk0 + wk1 * xk1 + wk2 * xk2 + wk3 * xk3;
        float av = wv0 * xv0 + wv1 * xv1 + wv2 * xv2 + wv3 * xv3;
        aq = aq / (1.f + expf(-aq));
        ak = ak / (1.f + expf(-ak));
        av = av / (1.f + expf(-av));

        float sq = aq * aq, sk = ak * ak;
#pragma unroll
        for (int off = 16; off > 0; off >>= 1) {
            sq += __shfl_xor_sync(0xffffffffu, sq, off);
            sk += __shfl_xor_sync(0xffffffffu, sk, off);
        }
        __syncthreads();
        if (lane == 0) { shq[wid] = sq; shk[wid] = sk; }
        __syncthreads();
        float sumq = shq[0] + shq[1] + shq[2] + shq[3];
        float sumk = shk[0] + shk[1] + shk[2] + shk[3];
        float invq = 1.f / fmaxf(sqrtf(sumq), 1e-12f);
        float invk = 1.f / fmaxf(sqrtf(sumk), 1e-12f);

        size_t base = (size_t)(bl0 + s) * Dq + c;
        oq[base] = aq * invq * 0.08838834764831845f;
        ok[base] = ak * invk;
        ov[base] = av;

        xq0 = xq1; xq1 = xq2; xq2 = xq3;
        xk0 = xk1; xk1 = xk2; xk2 = xk3;
        xv0 = xv1; xv1 = xv2; xv2 = xv3;
    }
}

// ============ chunk prep (unchanged) ============
#define PKT 132
#define PK_K   0
#define PK_Q   8448
#define PK_A   16896
#define PK_T   21248
#define PK_C   25600
#define PREP_SMEM_FLOATS (PK_C + 320)
#define PREP_SMEM_BYTES (PREP_SMEM_FLOATS * 4)

__global__ __launch_bounds__(256, 1)
void prep_kernel(const float* __restrict__ q, const float* __restrict__ k,
                 const float* __restrict__ v, const float* __restrict__ beta,
                 const float* __restrict__ gdec,
                 float* __restrict__ Tg, float* __restrict__ At,
                 float* __restrict__ Tv, float* __restrict__ Gams,
                 float* __restrict__ GamC)
{
    extern __shared__ float sm[];
    float* sK = sm + PK_K;
    float* sQ = sm + PK_Q;
    float* sA = sm + PK_A;
    float* sT = sm + PK_T;
    float* slg = sm + PK_C;
    float* sgam = slg + 64;
    float* sbet = sgam + 64;
    float* sgg = sbet + 64;

    const int bhn = blockIdx.x;
    const int bh = bhn >> 6;
    const int n = bhn & 63;
    const int b = bh >> 4;
    const int h = bh & 15;
    const int l0 = n * Cq;
    const int tid = threadIdx.x;
    const int t_hi = tid >> 4;
    const int t_lo = tid & 15;

    for (int idx = tid; idx < 64 * 128; idx += 256) {
        int i = idx >> 7, d = idx & 127;
        size_t gi = (((size_t)(b * Lq + l0 + i)) * Hq + h) * Dh + d;
        sK[i * PKT + d] = k[gi];
        sQ[i * PKT + d] = q[gi];
    }
    if (tid < 64) {
        sbet[tid] = beta[(size_t)bh * Lq + l0 + tid];
        sgg[tid] = gdec[(size_t)bh * Lq + l0 + tid];
    }
    __syncthreads();
    if (tid < 64) {
        float vv = sgg[tid];
#pragma unroll
        for (int oo = 1; oo < 32; oo <<= 1) {
            float t = __shfl_up_sync(0xffffffffu, vv, oo);
            if ((tid & 31) >= oo) vv += t;
        }
        slg[tid] = vv;
    }
    __syncthreads();
    if (tid >= 32 && tid < 64) slg[tid] += slg[31];
    __syncthreads();
    const float lgC = slg[63];
    if (tid < 64) {
        float gam = expf(slg[tid]);
        sgam[tid] = gam;
        Gams[(size_t)bhn * 128 + tid] = gam;
        Gams[(size_t)bhn * 128 + 64 + tid] = expf(lgC - slg[tid]);
    }
    if (tid == 0) GamC[bhn] = expf(lgC);
    __syncthreads();

    {
        float acc[4][4];
#pragma unroll
        for (int r = 0; r < 4; r++)
#pragma unroll
            for (int c = 0; c < 4; c++) acc[r][c] = 0.f;
        for (int d = 0; d < 128; d += 4) {
            float4 av[4], bv[4];
#pragma unroll
            for (int r = 0; r < 4; r++)
                av[r] = *(const float4*)&sK[(t_hi + 16 * r) * PKT + d];
#pragma unroll
            for (int c = 0; c < 4; c++)
                bv[c] = *(const float4*)&sK[(t_lo + 16 * c) * PKT + d];
#pragma unroll
            for (int r = 0; r < 4; r++)
#pragma unroll
                for (int c = 0; c < 4; c++) acc[r][c] += dot4(av[r], bv[c]);
        }
#pragma unroll
        for (int r = 0; r < 4; r++) {
            int i = t_hi + 16 * r;
#pragma unroll
            for (int c = 0; c < 4; c++) {
                int j = t_lo + 16 * c;
                float val;
                if (j < i) val = sbet[i] * expf(slg[i] - slg[j]) * acc[r][c];
                else val = (i == j) ? 1.f : 0.f;
                sA[i * 68 + j] = val;
            }
        }
    }

    {
        float acc[4][4];
#pragma unroll
        for (int r = 0; r < 4; r++)
#pragma unroll
            for (int c = 0; c < 4; c++) acc[r][c] = 0.f;
        for (int d = 0; d < 128; d += 4) {
            float4 av[4], bv[4];
#pragma unroll
            for (int r = 0; r < 4; r++)
                av[r] = *(const float4*)&sQ[(t_hi + 16 * r) * PKT + d];
#pragma unroll
            for (int c = 0; c < 4; c++)
                bv[c] = *(const float4*)&sK[(t_lo + 16 * c) * PKT + d];
#pragma unroll
            for (int r = 0; r < 4; r++)
#pragma unroll
                for (int c = 0; c < 4; c++) acc[r][c] += dot4(av[r], bv[c]);
        }
        float* dstA = At + (size_t)bhn * 4096;
#pragma unroll
        for (int r = 0; r < 4; r++) {
            int i = t_hi + 16 * r;
#pragma unroll
            for (int c = 0; c < 4; c++) {
                int j = t_lo + 16 * c;
                dstA[i * 64 + j] = (j <= i) ? expf(slg[i] - slg[j]) * acc[r][c] : 0.f;
            }
        }
    }
    __syncthreads();

    if (tid < 64) {
        const int j = tid;
        for (int i = 0; i < 64; i++) {
            float s;
            if (i < j) s = 0.f;
            else if (i == j) s = 1.f;
            else {
                s = 0.f;
                for (int m = j; m < i; m++) s -= sA[i * 68 + m] * sT[m * 68 + j];
            }
            sT[i * 68 + j] = s;
        }
    }
    __syncthreads();

    for (int idx = tid; idx < 4096; idx += 256) {
        int i = idx >> 6, j = idx & 63;
        float tb = sT[i * 68 + j] * sbet[j];
        sT[i * 68 + j] = tb;
        Tg[(size_t)bhn * 4096 + idx] = tb * sgam[j];
    }
    for (int idx = tid; idx < 64 * 128; idx += 256) {
        int i = idx >> 7, d = idx & 127;
        sQ[i * PKT + d] = v[(((size_t)(b * Lq + l0 + i)) * Hq + h) * Dh + d];
    }
    __syncthreads();

    {
        float acc[4][8];
#pragma unroll
        for (int r = 0; r < 4; r++)
#pragma unroll
            for (int c = 0; c < 8; c++) acc[r][c] = 0.f;
        for (int j = 0; j < 64; j++) {
            float a[4];
#pragma unroll
            for (int r = 0; r < 4; r++) a[r] = sT[(t_hi + 16 * r) * 68 + j];
#pragma unroll
            for (int c = 0; c < 8; c++) {
                float bvv = sQ[j * PKT + t_lo + 16 * c];
#pragma unroll
                for (int r = 0; r < 4; r++) acc[r][c] += a[r] * bvv;
            }
        }
        float* dstT = Tv + (size_t)bhn * 8192;
#pragma unroll
        for (int r = 0; r < 4; r++) {
            int i = t_hi + 16 * r;
#pragma unroll
            for (int c = 0; c < 8; c++)
                dstT[i * 128 + t_lo + 16 * c] = acc[r][c];
        }
    }
}

// ============ sequential scan with cp.async K/Q double-buffering ============
#define SKT 132
#define KQBUF 8448
#define SS_K   0
#define SS_Q   16896
#define SS_S   33792
#define SS_TG  38016
#define SS_AT  42368
#define SS_TV  46720
#define SS_MID 49024
#define SS_KS  51328
#define SS_C   53632
#define SCAN_SMEM_FLOATS (SS_C + 192)
#define SCAN_SMEM_BYTES (SCAN_SMEM_FLOATS * 4)

__global__ __launch_bounds__(256, 1)
void scan_kernel(const float* __restrict__ q, const float* __restrict__ k,
                 const float* __restrict__ Tg, const float* __restrict__ At,
                 const float* __restrict__ Tv, const float* __restrict__ Gams,
                 const float* __restrict__ GamC, const float* __restrict__ S0,
                 float* __restrict__ o, float* __restrict__ Sout)
{
    extern __shared__ float sm[];
    const uint32_t sb = smem_u32(sm);
    float* sS = sm + SS_S;
    float* sTg = sm + SS_TG;
    float* sAt = sm + SS_AT;
    float* sTv = sm + SS_TV;
    float* sMid = sm + SS_MID;
    float* sKS = sm + SS_KS;
    float* sgam = sm + SS_C;
    float* sgCr = sgam + 64;

    const int bh = blockIdx.x >> 2;
    const int grp = blockIdx.x & 3;
    const int b = bh >> 4;
    const int h = bh & 15;
    const int dv0 = grp * 32;
    const int tid = threadIdx.x;
    const int t_hi = tid >> 4;
    const int t_lo = tid & 15;

#define LOAD_KQ(bufi, nn) do { \
        size_t _gb = (((size_t)(b * Lq + (nn) * Cq)) * Hq + h) * (size_t)Dh; \
        uint32_t _kd = sb + (SS_K + (bufi) * KQBUF) * 4; \
        uint32_t _qd = sb + (SS_Q + (bufi) * KQBUF) * 4; \
        _Pragma("unroll") \
        for (int _it = 0; _it < 8; _it++) { \
            int _e = tid + _it * 256; \
            int _i = _e >> 5; \
            int _sg = _e & 31; \
            uint32_t _o = _i * (SKT * 4) + _sg * 16; \
            size_t _g = _gb + (size_t)_i * (Hq * Dh) + _sg * 4; \
            cp16(_kd + _o, k + _g); \
            cp16(_qd + _o, q + _g); \
        } \
        asm volatile("cp.async.commit_group;" ::: "memory"); \
    } while (0)

    for (int idx = tid; idx < 32 * 128; idx += 256) {
        int dv = idx >> 7, dk = idx & 127;
        sS[dv * SKT + dk] = S0[((size_t)bh * 128 + dv0 + dv) * 128 + dk];
    }

    LOAD_KQ(0, 0);

    for (int n = 0; n < Nq; n++) {
        const int buf = n & 1;
        const int l0 = n * Cq;
        const int bhn = bh * Nq + n;
        float* sK = sm + SS_K + buf * KQBUF;
        float* sQ = sm + SS_Q + buf * KQBUF;

        // sync loads of per-chunk prep data
        for (int idx = tid; idx < 4096; idx += 256) {
            int i = idx >> 6, j = idx & 63;
            sTg[i * 68 + j] = Tg[(size_t)bhn * 4096 + idx];
            sAt[i * 68 + j] = At[(size_t)bhn * 4096 + idx];
        }
        for (int idx = tid; idx < 64 * 32; idx += 256) {
            int i = idx >> 5, dv = idx & 31;
            sTv[i * 36 + dv] = Tv[(size_t)bhn * 8192 + i * 128 + dv0 + dv];
        }
        if (tid < 64) {
            sgam[tid] = Gams[(size_t)bhn * 128 + tid];
            sgCr[tid] = Gams[(size_t)bhn * 128 + 64 + tid];
        }
        const float gammaC = GamC[bhn];

        asm volatile("cp.async.wait_group 0;" ::: "memory");
        __syncthreads();
        if (n + 1 < Nq) LOAD_KQ(buf ^ 1, n + 1);

        // KS[i][dv] = K_i . S_dv
        {
            float acc[4][2];
#pragma unroll
            for (int r = 0; r < 4; r++) { acc[r][0] = 0.f; acc[r][1] = 0.f; }
            for (int d = 0; d < 128; d += 4) {
                float4 av[4], bv[2];
#pragma unroll
                for (int r = 0; r < 4; r++)
                    av[r] = *(const float4*)&sK[(t_hi + 16 * r) * SKT + d];
                bv[0] = *(const float4*)&sS[t_lo * SKT + d];
                bv[1] = *(const float4*)&sS[(t_lo + 16) * SKT + d];
#pragma unroll
                for (int r = 0; r < 4; r++) {
                    acc[r][0] += dot4(av[r], bv[0]);
                    acc[r][1] += dot4(av[r], bv[1]);
                }
            }
#pragma unroll
            for (int r = 0; r < 4; r++) {
                int i = t_hi + 16 * r;
                sKS[i * 36 + t_lo] = acc[r][0];
                sKS[i * 36 + t_lo + 16] = acc[r][1];
            }
        }
        __syncthreads();

        // mid = Tv - Tg @ KS
        {
            float acc[4][2];
#pragma unroll
            for (int r = 0; r < 4; r++) { acc[r][0] = 0.f; acc[r][1] = 0.f; }
            for (int j = 0; j < 64; j++) {
                float b0 = sKS[j * 36 + t_lo];
                float b1 = sKS[j * 36 + t_lo + 16];
#pragma unroll
                for (int r = 0; r < 4; r++) {
                    float a = sTg[(t_hi + 16 * r) * 68 + j];
                    acc[r][0] += a * b0;
                    acc[r][1] += a * b1;
                }
            }
#pragma unroll
            for (int r = 0; r < 4; r++) {
                int i = t_hi + 16 * r;
                sMid[i * 36 + t_lo] = sTv[i * 36 + t_lo] - acc[r][0];
                sMid[i * 36 + t_lo + 16] = sTv[i * 36 + t_lo + 16] - acc[r][1];
            }
        }
        __syncthreads();

        // O = gamma_i * (Q @ S^T) + attn @ mid
        {
            float acc1[4][2], acc2[4][2];
#pragma unroll
            for (int r = 0; r < 4; r++) {
                acc1[r][0] = acc1[r][1] = 0.f;
                acc2[r][0] = acc2[r][1] = 0.f;
            }
            for (int d = 0; d < 128; d += 4) {
                float4 av[4], bv[2];
#pragma unroll
                for (int r = 0; r < 4; r++)
                    av[r] = *(const float4*)&sQ[(t_hi + 16 * r) * SKT + d];
                bv[0] = *(const float4*)&sS[t_lo * SKT + d];
                bv[1] = *(const float4*)&sS[(t_lo + 16) * SKT + d];
#pragma unroll
                for (int r = 0; r < 4; r++) {
                    acc1[r][0] += dot4(av[r], bv[0]);
                    acc1[r][1] += dot4(av[r], bv[1]);
                }
            }
            for (int j = 0; j < 64; j++) {
                float b0 = sMid[j * 36 + t_lo];
                float b1 = sMid[j * 36 + t_lo + 16];
#pragma unroll
                for (int r = 0; r < 4; r++) {
                    float a = sAt[(t_hi + 16 * r) * 68 + j];
                    acc2[r][0] += a * b0;
                    acc2[r][1] += a * b1;
                }
            }
#pragma unroll
            for (int r = 0; r < 4; r++) {
                int i = t_hi + 16 * r;
                float g = sgam[i];
                size_t go = (((size_t)(b * Lq + l0 + i)) * Hq + h) * Dh + dv0;
                o[go + t_lo] = g * acc1[r][0] + acc2[r][0];
                o[go + t_lo + 16] = g * acc1[r][1] + acc2[r][1];
            }
        }
        __syncthreads();

        // S = gammaC * S + (mid_i * gCr_i)^T @ K
        {
            const int dkb = t_lo * 8;
            float acc[2][8];
#pragma unroll
            for (int r = 0; r < 2; r++)
#pragma unroll
                for (int c = 0; c < 8; c++) acc[r][c] = 0.f;
            for (int i = 0; i < 64; i++) {
                float gc = sgCr[i];
                float a0 = sMid[i * 36 + t_hi] * gc;
                float a1 = sMid[i * 36 + t_hi + 16] * gc;
                float4 k0 = *(const float4*)&sK[i * SKT + dkb];
                float4 k1 = *(const float4*)&sK[i * SKT + dkb + 4];
                acc[0][0] += a0 * k0.x; acc[0][1] += a0 * k0.y;
                acc[0][2] += a0 * k0.z; acc[0][3] += a0 * k0.w;
                acc[0][4] += a0 * k1.x; acc[0][5] += a0 * k1.y;
                acc[0][6] += a0 * k1.z; acc[0][7] += a0 * k1.w;
                acc[1][0] += a1 * k0.x; acc[1][1] += a1 * k0.y;
                acc[1][2] += a1 * k0.z; acc[1][3] += a1 * k0.w;
                acc[1][4] += a1 * k1.x; acc[1][5] += a1 * k1.y;
                acc[1][6] += a1 * k1.z; acc[1][7] += a1 * k1.w;
            }
#pragma unroll
            for (int r = 0; r < 2; r++) {
                int dv = t_hi + 16 * r;
#pragma unroll
                for (int c = 0; c < 8; c++) {
                    float* p = &sS[dv * SKT + dkb + c];
                    *p = gammaC * *p + acc[r][c];
                }
            }
        }
        __syncthreads();
    }

    for (int idx = tid; idx < 32 * 128; idx += 256) {
        int dv = idx >> 7, dk = idx & 127;
        Sout[((size_t)bh * 128 + dv0 + dv) * 128 + dk] = sS[dv * SKT + dk];
    }
}

// ---------------- RMSNorm + gate (silu) -> fp16 ----------------
__global__ void gate_kernel(const float* __restrict__ o, const float* __restrict__ proj,
                            const float* __restrict__ norm_w,
                            __half* __restrict__ oh)
{
    const size_t base = (size_t)blockIdx.x * Dh + threadIdx.x;
    const size_t row = blockIdx.x >> 4;
    const size_t inner = (size_t)(blockIdx.x & 15) * Dh + threadIdx.x;
    float ov = o[base];
    float s = ov * ov;
#pragma unroll
    for (int off = 16; off > 0; off >>= 1) s += __shfl_xor_sync(0xffffffffu, s, off);
    __shared__ float sh[4];
    const int wid = threadIdx.x >> 5;
    if ((threadIdx.x & 31) == 0) sh[wid] = s;
    __syncthreads();
    float mean = (sh[0] + sh[1] + sh[2] + sh[3]) * (1.f / 128.f);
    float rs = rsqrtf(mean + EPSq);
    float gv = proj[row * (4 * Dq) + 3 * Dq + inner];
    float sig = gv / (1.f + expf(-gv));
    float val = ov * rs * norm_w[threadIdx.x] * sig;
    oh[base] = __float2half_rn(val);
}

// ---------------- launch ----------------
extern "C" void kernel_launch(void* const* d_in, const int* in_sizes, int n_in,
                              void* d_out, int out_size)
{
    const float* x = (const float*)d_in[0];
    const float* Wq = (const float*)d_in[1];
    const float* Wk = (const float*)d_in[2];
    const float* Wv = (const float*)d_in[3];
    const float* Wb = (const float*)d_in[4];
    const float* Wa = (const float*)d_in[5];
    const float* A_log = (const float*)d_in[6];
    const float* dt_bias = (const float*)d_in[7];
    const float* conv_q = (const float*)d_in[8];
    const float* conv_k = (const float*)d_in[9];
    const float* conv_v = (const float*)d_in[10];
    const float* Wg = (const float*)d_in[11];
    const float* norm_w = (const float*)d_in[12];
    const float* Wo = (const float*)d_in[13];
    const float* S0 = (const float*)d_in[14];

    float* out = (float*)d_out;
    float* Sout = out + (size_t)BLD;

    float *proj, *obuf, *qn, *kn, *vn, *beta, *gdec;
    float *Tg, *At, *Tv, *Gams, *GamC;
    __half *xh, *whi, *wlo;
    cudaGetSymbolAddress((void**)&proj, g_proj);
    cudaGetSymbolAddress((void**)&obuf, g_obuf);
    cudaGetSymbolAddress((void**)&qn, g_qn);
    cudaGetSymbolAddress((void**)&kn, g_kn);
    cudaGetSymbolAddress((void**)&vn, g_vn);
    cudaGetSymbolAddress((void**)&beta, g_beta);
    cudaGetSymbolAddress((void**)&gdec, g_gdec);
    cudaGetSymbolAddress((void**)&Tg, g_Tg);
    cudaGetSymbolAddress((void**)&At, g_At);
    cudaGetSymbolAddress((void**)&Tv, g_Tv);
    cudaGetSymbolAddress((void**)&Gams, g_Gams);
    cudaGetSymbolAddress((void**)&GamC, g_GamC);
    cudaGetSymbolAddress((void**)&xh, g_xh);
    cudaGetSymbolAddress((void**)&whi, g_whi);
    cudaGetSymbolAddress((void**)&wlo, g_wlo);

    cudaFuncSetAttribute(scan_kernel, cudaFuncAttributeMaxDynamicSharedMemorySize,
                         SCAN_SMEM_BYTES);
    cudaFuncSetAttribute(prep_kernel, cudaFuncAttributeMaxDynamicSharedMemorySize,
                         PREP_SMEM_BYTES);
    cudaFuncSetAttribute(hmma_gemm, cudaFuncAttributeMaxDynamicSharedMemorySize,
                         GEMM_SMEM_BYTES);

    const size_t WSZ = (size_t)Dq * Dq;

    cast_f16<<<BLD / 1024, 256>>>((const float4*)x, (__half2*)xh);
    W4 w4 = { (const float4*)Wq, (const float4*)Wk, (const float4*)Wv, (const float4*)Wg };
    split4_f16<<<4 * WBLK, 256>>>(w4, (__half2*)whi, (__half2*)wlo);

    // merged projection GEMM: lo correction only for Wk (region 1)
    dim3 pgrid(BLq / 128, 4 * Dq / 128);
    hmma_gemm<<<pgrid, 256, GEMM_SMEM_BYTES>>>(xh, whi, wlo, proj, 4 * Dq, 0b0010);

    betag_gemm<<<BLq / 32, 256>>>(x, Wb, Wa, A_log, dt_bias, beta, gdec);

    conv_kernel<<<(BLq / 8) * Hq, 128>>>(proj, conv_q, conv_k, conv_v, qn, kn, vn);

    prep_kernel<<<NCHK, 256, PREP_SMEM_BYTES>>>(qn, kn, vn, beta, gdec,
                                                Tg, At, Tv, Gams, GamC);

    scan_kernel<<<Bq * Hq * 4, 256, SCAN_SMEM_BYTES>>>(qn, kn, Tg, At, Tv, Gams,
                                                       GamC, S0, obuf, Sout);

    gate_kernel<<<BLq * Hq, 128>>>(obuf, proj, norm_w, xh);

    cast_f16<<<WSZ / 1024, 256>>>((const float4*)Wo, (__half2*)(whi + 4 * WSZ));
    dim3 ogrid(BLq / 128, Dq / 128);
    hmma_gemm<<<ogrid, 256, GEMM_SMEM_BYTES>>>(xh, whi + 4 * WSZ, whi + 4 * WSZ,
                                               out, Dq, 0);
}

// round 17
// speedup vs baseline: 1.6394x; 1.1465x over previous
#include <cuda_runtime.h>
#include <cuda_bf16.h>
#include <cuda_fp16.h>
#include <cstdint>
#include <cstddef>

#define Bq 2
#define Lq 4096
#define Dq 2048
#define Hq 16
#define Dh 128
#define Cq 64
#define Nq (Lq / Cq)
#define KW 4
#define BLq (Bq * Lq)
#define EPSq 1e-5f

#define GNC 64

// ---------------- device scratch buffers ----------------
#define BLD (BLq * Dq)
#define BHL (Bq * Hq * Lq)
#define WROWS (5 * Dq)
#define NBH (Bq * Hq)
#define NCHK (NBH * Nq)

__device__ float g_proj[(size_t)BLq * 4 * Dq];
__device__ float g_obuf[BLD];
__device__ float g_qn[BLD];
__device__ float g_kn[BLD];
__device__ float g_vn[BLD];
__device__ float g_beta[BHL];
__device__ float g_gdec[BHL];

__device__ float g_Tg[(size_t)NCHK * 4096];
__device__ float g_At[(size_t)NCHK * 4096];
__device__ float g_Tv[(size_t)NCHK * 8192];
__device__ float g_Gams[(size_t)NCHK * 128];
__device__ float g_GamC[NCHK];

__device__ __half g_xh[(size_t)BLq * Dq];
__device__ __half g_whi[(size_t)WROWS * Dq];
__device__ __half g_wlo[(size_t)WROWS * Dq];   // unused now (kept for layout stability)

// ================= helpers =================
__device__ __forceinline__ uint32_t smem_u32(const void* p) {
    uint32_t a;
    asm("{ .reg .u64 t; cvta.to.shared.u64 t, %1; cvt.u32.u64 %0, t; }" : "=r"(a) : "l"(p));
    return a;
}
#define SWZ(x) ((x) ^ (((x) >> 3) & 0x70))

__device__ __forceinline__ void cp16(uint32_t dst, const void* src) {
    asm volatile("cp.async.cg.shared.global [%0], [%1], 16;" :: "r"(dst), "l"(src));
}
__device__ __forceinline__ void ldsm_x4(uint32_t& r0, uint32_t& r1, uint32_t& r2,
                                        uint32_t& r3, uint32_t a) {
    asm volatile("ldmatrix.sync.aligned.m8n8.x4.shared.b16 {%0,%1,%2,%3}, [%4];"
                 : "=r"(r0), "=r"(r1), "=r"(r2), "=r"(r3) : "r"(a));
}
__device__ __forceinline__ void mma16816(float* d, const uint32_t* a, const uint32_t* b) {
    asm volatile("mma.sync.aligned.m16n8k16.row.col.f32.f16.f16.f32 "
                 "{%0,%1,%2,%3}, {%4,%5,%6,%7}, {%8,%9}, {%0,%1,%2,%3};"
                 : "+f"(d[0]), "+f"(d[1]), "+f"(d[2]), "+f"(d[3])
                 : "r"(a[0]), "r"(a[1]), "r"(a[2]), "r"(a[3]), "r"(b[0]), "r"(b[1]));
}
__device__ __forceinline__ float dot4(float4 a, float4 b) {
    return a.x * b.x + a.y * b.y + a.z * b.z + a.w * b.w;
}

// ---------------- fp32 -> fp16 cast ----------------
__global__ void cast_f16(const float4* __restrict__ in, __half2* __restrict__ out)
{
    size_t idx = (size_t)blockIdx.x * blockDim.x + threadIdx.x;
    float4 a = in[idx];
    out[idx * 2]     = __floats2half2_rn(a.x, a.y);
    out[idx * 2 + 1] = __floats2half2_rn(a.z, a.w);
}

// ---------------- batched fp32 -> fp16 cast for 4 weights (hi only) ----------------
struct W4 { const float4* w0; const float4* w1; const float4* w2; const float4* w3; };

#define WBLK ((Dq * Dq) / 1024)

__global__ void cast4_f16(W4 ws, __half2* __restrict__ hi)
{
    int which = blockIdx.x / WBLK;
    int blk = blockIdx.x % WBLK;
    const float4* in = (which == 0) ? ws.w0 : (which == 1) ? ws.w1
                       : (which == 2) ? ws.w2 : ws.w3;
    size_t idx = (size_t)blk * blockDim.x + threadIdx.x;
    size_t base = (size_t)which * ((size_t)Dq * Dq / 2);
    float4 a = in[idx];
    hi[base + idx * 2]     = __floats2half2_rn(a.x, a.y);
    hi[base + idx * 2 + 1] = __floats2half2_rn(a.z, a.w);
}

// ---------------- HMMA GEMM (all-hi, 32 chunks) -----------
#define STAGE_B 32768
#define GEMM_SMEM_BYTES (3 * STAGE_B)

__global__ __launch_bounds__(256, 2)
void hmma_gemm(const __half* __restrict__ A,
               const __half* __restrict__ Bhi,
               float* __restrict__ C, int ldc)
{
    extern __shared__ __align__(128) char smem[];
    const uint32_t sb = smem_u32(smem);
    const int tid = threadIdx.x;
    const int warp = tid >> 5, lane = tid & 31;
    const int wm = warp & 1, wn = warp >> 1;
    const int bm = blockIdx.x * 128, bn = blockIdx.y * 128;
    const int nc = 32;

    float acc[4][4][4];
#pragma unroll
    for (int i = 0; i < 4; i++)
#pragma unroll
        for (int j = 0; j < 4; j++)
#pragma unroll
            for (int r = 0; r < 4; r++) acc[i][j][r] = 0.f;

    const int lrow = tid >> 3;
    const int lseg = tid & 7;
    const uint32_t loff = SWZ(lrow * 128 + lseg * 16);

#define LOAD_STAGE(s, kc) do { \
        int _k0 = (kc) * 64; \
        uint32_t _as = sb + (s) * STAGE_B; \
        uint32_t _bs = _as + 16384; \
        const __half* _ap = A + (size_t)(bm + lrow) * Dq + _k0 + lseg * 8; \
        const __half* _bp = Bhi + (size_t)(bn + lrow) * Dq + _k0 + lseg * 8; \
        _Pragma("unroll") \
        for (int _i = 0; _i < 4; _i++) { \
            cp16(_as + loff + _i * 4096, _ap + (size_t)_i * 32 * Dq); \
            cp16(_bs + loff + _i * 4096, _bp + (size_t)_i * 32 * Dq); \
        } \
        asm volatile("cp.async.commit_group;" ::: "memory"); \
    } while (0)

    const int aq = lane >> 3;
    const int am = (lane & 7) + (aq & 1) * 8;
    const int akb = (aq >> 1) * 8;
    const int bln = lane & 7;
    const int bsel = lane >> 3;
    const int bnrow = (bsel >> 1) * 8 + bln;
    const int bkoff = (bsel & 1) * 8;

    LOAD_STAGE(0, 0);
    LOAD_STAGE(1, 1);

    for (int c = 0; c < nc; c++) {
        if (c == nc - 1) {
            asm volatile("cp.async.wait_group 0;" ::: "memory");
        } else {
            asm volatile("cp.async.wait_group 1;" ::: "memory");
        }
        __syncthreads();
        if (c + 2 < nc) LOAD_STAGE((c + 2) % 3, c + 2);

        const uint32_t As = sb + (c % 3) * STAGE_B;
        const uint32_t Bs = As + 16384;
#pragma unroll
        for (int ks = 0; ks < 4; ks++) {
            const int k0 = ks * 16;
            uint32_t af[4][4];
#pragma unroll
            for (int mt = 0; mt < 4; mt++) {
                int m = wm * 64 + mt * 16 + am;
                ldsm_x4(af[mt][0], af[mt][1], af[mt][2], af[mt][3],
                        As + SWZ(m * 128 + (k0 + akb) * 2));
            }
            uint32_t bf[4][2];
#pragma unroll
            for (int ntp = 0; ntp < 2; ntp++) {
                int n = wn * 32 + ntp * 16 + bnrow;
                ldsm_x4(bf[2 * ntp][0], bf[2 * ntp][1],
                        bf[2 * ntp + 1][0], bf[2 * ntp + 1][1],
                        Bs + SWZ(n * 128 + (k0 + bkoff) * 2));
            }
#pragma unroll
            for (int mt = 0; mt < 4; mt++)
#pragma unroll
                for (int nt = 0; nt < 4; nt++)
                    mma16816(acc[mt][nt], af[mt], bf[nt]);
        }
    }

    const int r0 = bm + wm * 64 + (lane >> 2);
    const int c0 = bn + wn * 32 + (lane & 3) * 2;
#pragma unroll
    for (int mt = 0; mt < 4; mt++) {
#pragma unroll
        for (int nt = 0; nt < 4; nt++) {
            float2* p0 = (float2*)(C + (size_t)(r0 + mt * 16) * ldc + c0 + nt * 8);
            float2* p1 = (float2*)(C + (size_t)(r0 + mt * 16 + 8) * ldc + c0 + nt * 8);
            *p0 = make_float2(acc[mt][nt][0], acc[mt][nt][1]);
            *p1 = make_float2(acc[mt][nt][2], acc[mt][nt][3]);
        }
    }
}

// ---------------- beta / g mini-GEMM, 16 rows/block ----------------
#define BGK 128
__global__ __launch_bounds__(256)
void betag_gemm(const float* __restrict__ x,
                const float* __restrict__ Wb,
                const float* __restrict__ Wa,
                const float* __restrict__ A_log,
                const float* __restrict__ dt_bias,
                float* __restrict__ beta,
                float* __restrict__ gdec)
{
    __shared__ float xs[16 * (BGK + 4)];
    __shared__ float wsm[32 * (BGK + 4)];
    const int tid = threadIdx.x;
    const int rows16 = blockIdx.x * 16;
    const int t_hi = tid >> 4;    // row 0..15
    const int t_lo = tid & 15;    // head 0..15

    float accB = 0.f, accA = 0.f;

    for (int k0 = 0; k0 < Dq; k0 += BGK) {
        for (int idx = tid; idx < 16 * (BGK / 4); idx += 256) {
            int row = idx / (BGK / 4);
            int col4 = idx % (BGK / 4);
            *(float4*)&xs[row * (BGK + 4) + col4 * 4] =
                *(const float4*)&x[(size_t)(rows16 + row) * Dq + k0 + col4 * 4];
        }
        for (int idx = tid; idx < 32 * (BGK / 4); idx += 256) {
            int row = idx / (BGK / 4);
            int col4 = idx % (BGK / 4);
            const float* wsrc = (row < 16) ? (Wb + (size_t)row * Dq)
                                           : (Wa + (size_t)(row - 16) * Dq);
            *(float4*)&wsm[row * (BGK + 4) + col4 * 4] =
                *(const float4*)&wsrc[k0 + col4 * 4];
        }
        __syncthreads();
#pragma unroll 4
        for (int d = 0; d < BGK; d += 4) {
            float4 a0 = *(const float4*)&xs[t_hi * (BGK + 4) + d];
            float4 b0 = *(const float4*)&wsm[t_lo * (BGK + 4) + d];
            float4 b1 = *(const float4*)&wsm[(t_lo + 16) * (BGK + 4) + d];
            accB += dot4(a0, b0);
            accA += dot4(a0, b1);
        }
        __syncthreads();
    }

    const float dtb = dt_bias[t_lo];
    const float al = expf(A_log[t_lo]);
    int grow = rows16 + t_hi;
    int b = grow >> 12;
    int l = grow & (Lq - 1);
    beta[((size_t)(b * Hq + t_lo)) * Lq + l] = 1.f / (1.f + expf(-accB));
    float z = accA + dtb;
    float sp = (z > 15.f) ? z : log1pf(expf(z));
    gdec[((size_t)(b * Hq + t_lo)) * Lq + l] = -al * sp;
}

// ---------------- conv ------------
__global__ void conv_kernel(const float* __restrict__ proj,
                            const float* __restrict__ wq, const float* __restrict__ wk,
                            const float* __restrict__ wv,
                            float* __restrict__ oq, float* __restrict__ ok,
                            float* __restrict__ ov)
{
    const int blk = blockIdx.x;
    const int h = blk % Hq;
    const int bl8 = blk / Hq;
    const int bl0 = bl8 * 8;
    const int l0 = bl0 % Lq;
    const int d = threadIdx.x;
    const int c = h * Dh + d;
    const int wid = threadIdx.x >> 5;
    const int lane = threadIdx.x & 31;

    const float wq0 = wq[c * KW], wq1 = wq[c * KW + 1], wq2 = wq[c * KW + 2], wq3 = wq[c * KW + 3];
    const float wk0 = wk[c * KW], wk1 = wk[c * KW + 1], wk2 = wk[c * KW + 2], wk3 = wk[c * KW + 3];
    const float wv0 = wv[c * KW], wv1 = wv[c * KW + 1], wv2 = wv[c * KW + 2], wv3 = wv[c * KW + 3];

    float xq0 = 0.f, xq1 = 0.f, xq2 = 0.f;
    float xk0 = 0.f, xk1 = 0.f, xk2 = 0.f;
    float xv0 = 0.f, xv1 = 0.f, xv2 = 0.f;
#pragma unroll
    for (int j = 0; j < 3; j++) {
        int ll = l0 - 3 + j;
        if (ll >= 0) {
            size_t idx = (size_t)(bl0 - l0 + ll) * (4 * Dq) + c;
            float q_ = proj[idx], k_ = proj[idx + Dq], v_ = proj[idx + 2 * Dq];
            if (j == 0) { xq0 = q_; xk0 = k_; xv0 = v_; }
            else if (j == 1) { xq1 = q_; xk1 = k_; xv1 = v_; }
            else { xq2 = q_; xk2 = k_; xv2 = v_; }
        }
    }

    __shared__ float shq[4], shk[4];
#pragma unroll 1
    for (int s = 0; s < 8; s++) {
        size_t idx = (size_t)(bl0 + s) * (4 * Dq) + c;
        float xq3 = proj[idx], xk3 = proj[idx + Dq], xv3 = proj[idx + 2 * Dq];

        float aq = wq0 * xq0 + wq1 * xq1 + wq2 * xq2 + wq3 * xq3;
        float ak = wk0 * xk0 + wk1 * xk1 + wk2 * xk2 + wk3 * xk3;
        float av = wv0 * xv0 + wv1 * xv1 + wv2 * xv2 + wv3 * xv3;
        aq = aq / (1.f + expf(-aq));
        ak = ak / (1.f + expf(-ak));
        av = av / (1.f + expf(-av));

        float sq = aq * aq, sk = ak * ak;
#pragma unroll
        for (int off = 16; off > 0; off >>= 1) {
            sq += __shfl_xor_sync(0xffffffffu, sq, off);
            sk += __shfl_xor_sync(0xffffffffu, sk, off);
        }
        __syncthreads();
        if (lane == 0) { shq[wid] = sq; shk[wid] = sk; }
        __syncthreads();
        float sumq = shq[0] + shq[1] + shq[2] + shq[3];
        float sumk = shk[0] + shk[1] + shk[2] + shk[3];
        float invq = 1.f / fmaxf(sqrtf(sumq), 1e-12f);
        float invk = 1.f / fmaxf(sqrtf(sumk), 1e-12f);

        size_t base = (size_t)(bl0 + s) * Dq + c;
        oq[base] = aq * invq * 0.08838834764831845f;
        ok[base] = ak * invk;
        ov[base] = av;

        xq0 = xq1; xq1 = xq2; xq2 = xq3;
        xk0 = xk1; xk1 = xk2; xk2 = xk3;
        xv0 = xv1; xv1 = xv2; xv2 = xv3;
    }
}

// ============ chunk prep ============
#define PKT 132
#define PK_K   0
#define PK_Q   8448
#define PK_A   16896
#define PK_T   21248
#define PK_C   25600
#define PREP_SMEM_FLOATS (PK_C + 320)
#define PREP_SMEM_BYTES (PREP_SMEM_FLOATS * 4)

__global__ __launch_bounds__(256, 1)
void prep_kernel(const float* __restrict__ q, const float* __restrict__ k,
                 const float* __restrict__ v, const float* __restrict__ beta,
                 const float* __restrict__ gdec,
                 float* __restrict__ Tg, float* __restrict__ At,
                 float* __restrict__ Tv, float* __restrict__ Gams,
                 float* __restrict__ GamC)
{
    extern __shared__ float sm[];
    float* sK = sm + PK_K;
    float* sQ = sm + PK_Q;
    float* sA = sm + PK_A;
    float* sT = sm + PK_T;
    float* slg = sm + PK_C;
    float* sgam = slg + 64;
    float* sbet = sgam + 64;
    float* sgg = sbet + 64;

    const int bhn = blockIdx.x;
    const int bh = bhn >> 6;
    const int n = bhn & 63;
    const int b = bh >> 4;
    const int h = bh & 15;
    const int l0 = n * Cq;
    const int tid = threadIdx.x;
    const int t_hi = tid >> 4;
    const int t_lo = tid & 15;

    for (int idx = tid; idx < 64 * 128; idx += 256) {
        int i = idx >> 7, d = idx & 127;
        size_t gi = (((size_t)(b * Lq + l0 + i)) * Hq + h) * Dh + d;
        sK[i * PKT + d] = k[gi];
        sQ[i * PKT + d] = q[gi];
    }
    if (tid < 64) {
        sbet[tid] = beta[(size_t)bh * Lq + l0 + tid];
        sgg[tid] = gdec[(size_t)bh * Lq + l0 + tid];
    }
    __syncthreads();
    if (tid < 64) {
        float vv = sgg[tid];
#pragma unroll
        for (int oo = 1; oo < 32; oo <<= 1) {
            float t = __shfl_up_sync(0xffffffffu, vv, oo);
            if ((tid & 31) >= oo) vv += t;
        }
        slg[tid] = vv;
    }
    __syncthreads();
    if (tid >= 32 && tid < 64) slg[tid] += slg[31];
    __syncthreads();
    const float lgC = slg[63];
    if (tid < 64) {
        float gam = expf(slg[tid]);
        sgam[tid] = gam;
        Gams[(size_t)bhn * 128 + tid] = gam;
        Gams[(size_t)bhn * 128 + 64 + tid] = expf(lgC - slg[tid]);
    }
    if (tid == 0) GamC[bhn] = expf(lgC);
    __syncthreads();

    {
        float acc[4][4];
#pragma unroll
        for (int r = 0; r < 4; r++)
#pragma unroll
            for (int c = 0; c < 4; c++) acc[r][c] = 0.f;
        for (int d = 0; d < 128; d += 4) {
            float4 av[4], bv[4];
#pragma unroll
            for (int r = 0; r < 4; r++)
                av[r] = *(const float4*)&sK[(t_hi + 16 * r) * PKT + d];
#pragma unroll
            for (int c = 0; c < 4; c++)
                bv[c] = *(const float4*)&sK[(t_lo + 16 * c) * PKT + d];
#pragma unroll
            for (int r = 0; r < 4; r++)
#pragma unroll
                for (int c = 0; c < 4; c++) acc[r][c] += dot4(av[r], bv[c]);
        }
#pragma unroll
        for (int r = 0; r < 4; r++) {
            int i = t_hi + 16 * r;
#pragma unroll
            for (int c = 0; c < 4; c++) {
                int j = t_lo + 16 * c;
                float val;
                if (j < i) val = sbet[i] * expf(slg[i] - slg[j]) * acc[r][c];
                else val = (i == j) ? 1.f : 0.f;
                sA[i * 68 + j] = val;
            }
        }
    }

    {
        float acc[4][4];
#pragma unroll
        for (int r = 0; r < 4; r++)
#pragma unroll
            for (int c = 0; c < 4; c++) acc[r][c] = 0.f;
        for (int d = 0; d < 128; d += 4) {
            float4 av[4], bv[4];
#pragma unroll
            for (int r = 0; r < 4; r++)
                av[r] = *(const float4*)&sQ[(t_hi + 16 * r) * PKT + d];
#pragma unroll
            for (int c = 0; c < 4; c++)
                bv[c] = *(const float4*)&sK[(t_lo + 16 * c) * PKT + d];
#pragma unroll
            for (int r = 0; r < 4; r++)
#pragma unroll
                for (int c = 0; c < 4; c++) acc[r][c] += dot4(av[r], bv[c]);
        }
        float* dstA = At + (size_t)bhn * 4096;
#pragma unroll
        for (int r = 0; r < 4; r++) {
            int i = t_hi + 16 * r;
#pragma unroll
            for (int c = 0; c < 4; c++) {
                int j = t_lo + 16 * c;
                dstA[i * 64 + j] = (j <= i) ? expf(slg[i] - slg[j]) * acc[r][c] : 0.f;
            }
        }
    }
    __syncthreads();

    if (tid < 64) {
        const int j = tid;
        for (int i = 0; i < 64; i++) {
            float s;
            if (i < j) s = 0.f;
            else if (i == j) s = 1.f;
            else {
                s = 0.f;
                for (int m = j; m < i; m++) s -= sA[i * 68 + m] * sT[m * 68 + j];
            }
            sT[i * 68 + j] = s;
        }
    }
    __syncthreads();

    for (int idx = tid; idx < 4096; idx += 256) {
        int i = idx >> 6, j = idx & 63;
        float tb = sT[i * 68 + j] * sbet[j];
        sT[i * 68 + j] = tb;
        Tg[(size_t)bhn * 4096 + idx] = tb * sgam[j];
    }
    for (int idx = tid; idx < 64 * 128; idx += 256) {
        int i = idx >> 7, d = idx & 127;
        sQ[i * PKT + d] = v[(((size_t)(b * Lq + l0 + i)) * Hq + h) * Dh + d];
    }
    __syncthreads();

    {
        float acc[4][8];
#pragma unroll
        for (int r = 0; r < 4; r++)
#pragma unroll
            for (int c = 0; c < 8; c++) acc[r][c] = 0.f;
        for (int j = 0; j < 64; j++) {
            float a[4];
#pragma unroll
            for (int r = 0; r < 4; r++) a[r] = sT[(t_hi + 16 * r) * 68 + j];
#pragma unroll
            for (int c = 0; c < 8; c++) {
                float bvv = sQ[j * PKT + t_lo + 16 * c];
#pragma unroll
                for (int r = 0; r < 4; r++) acc[r][c] += a[r] * bvv;
            }
        }
        float* dstT = Tv + (size_t)bhn * 8192;
#pragma unroll
        for (int r = 0; r < 4; r++) {
            int i = t_hi + 16 * r;
#pragma unroll
            for (int c = 0; c < 8; c++)
                dstT[i * 128 + t_lo + 16 * c] = acc[r][c];
        }
    }
}

// ============ sequential scan, fully cp.async-fed ============
#define SKT 132
#define KQBUF 8448
#define SS_K   0
#define SS_Q   16896
#define SS_S   33792
#define SS_TG  38016
#define SS_AT  42368
#define SS_TV  46720
#define SS_MID 49024
#define SS_KS  51328
#define SS_C   53632
#define SCAN_SMEM_FLOATS (SS_C + 192)
#define SCAN_SMEM_BYTES (SCAN_SMEM_FLOATS * 4)

__global__ __launch_bounds__(256, 1)
void scan_kernel(const float* __restrict__ q, const float* __restrict__ k,
                 const float* __restrict__ Tg, const float* __restrict__ At,
                 const float* __restrict__ Tv, const float* __restrict__ Gams,
                 const float* __restrict__ GamC, const float* __restrict__ S0,
                 float* __restrict__ o, float* __restrict__ Sout)
{
    extern __shared__ float sm[];
    const uint32_t sb = smem_u32(sm);
    float* sS = sm + SS_S;
    float* sTg = sm + SS_TG;
    float* sAt = sm + SS_AT;
    float* sTv = sm + SS_TV;
    float* sMid = sm + SS_MID;
    float* sKS = sm + SS_KS;
    float* sgam = sm + SS_C;
    float* sgCr = sgam + 64;

    const int bh = blockIdx.x >> 2;
    const int grp = blockIdx.x & 3;
    const int b = bh >> 4;
    const int h = bh & 15;
    const int dv0 = grp * 32;
    const int tid = threadIdx.x;
    const int t_hi = tid >> 4;
    const int t_lo = tid & 15;

#define LOAD_KQ(bufi, nn) do { \
        size_t _gb = (((size_t)(b * Lq + (nn) * Cq)) * Hq + h) * (size_t)Dh; \
        uint32_t _kd = sb + (SS_K + (bufi) * KQBUF) * 4; \
        uint32_t _qd = sb + (SS_Q + (bufi) * KQBUF) * 4; \
        _Pragma("unroll") \
        for (int _it = 0; _it < 8; _it++) { \
            int _e = tid + _it * 256; \
            int _i = _e >> 5; \
            int _sg = _e & 31; \
            uint32_t _o = _i * (SKT * 4) + _sg * 16; \
            size_t _g = _gb + (size_t)_i * (Hq * Dh) + _sg * 4; \
            cp16(_kd + _o, k + _g); \
            cp16(_qd + _o, q + _g); \
        } \
        asm volatile("cp.async.commit_group;" ::: "memory"); \
    } while (0)

    for (int idx = tid; idx < 32 * 128; idx += 256) {
        int dv = idx >> 7, dk = idx & 127;
        sS[dv * SKT + dk] = S0[((size_t)bh * 128 + dv0 + dv) * 128 + dk];
    }

    LOAD_KQ(0, 0);

    for (int n = 0; n < Nq; n++) {
        const int buf = n & 1;
        const int l0 = n * Cq;
        const int bhn = bh * Nq + n;
        float* sK = sm + SS_K + buf * KQBUF;
        float* sQ = sm + SS_Q + buf * KQBUF;

        // async loads of per-chunk prep data (same buffers; safe after loop-end sync)
        {
            const float* srcTg = Tg + (size_t)bhn * 4096;
            const float* srcAt = At + (size_t)bhn * 4096;
#pragma unroll
            for (int it = 0; it < 4; it++) {
                int e = tid + it * 256;            // 0..1023
                int row = e >> 4, seg = e & 15;
                uint32_t off = (row * 68 + seg * 4) * 4;
                cp16(sb + SS_TG * 4 + off, srcTg + row * 64 + seg * 4);
                cp16(sb + SS_AT * 4 + off, srcAt + row * 64 + seg * 4);
            }
            const float* srcTv = Tv + (size_t)bhn * 8192 + dv0;
#pragma unroll
            for (int it = 0; it < 2; it++) {
                int e = tid + it * 256;            // 0..511
                int row = e >> 3, seg = e & 7;
                cp16(sb + (SS_TV + row * 36 + seg * 4) * 4, srcTv + row * 128 + seg * 4);
            }
            if (tid < 32)
                cp16(sb + (SS_C + tid * 4) * 4, Gams + (size_t)bhn * 128 + tid * 4);
            asm volatile("cp.async.commit_group;" ::: "memory");
        }
        const float gammaC = GamC[bhn];

        asm volatile("cp.async.wait_group 0;" ::: "memory");
        __syncthreads();
        if (n + 1 < Nq) LOAD_KQ(buf ^ 1, n + 1);

        // KS[i][dv] = K_i . S_dv
        {
            float acc[4][2];
#pragma unroll
            for (int r = 0; r < 4; r++) { acc[r][0] = 0.f; acc[r][1] = 0.f; }
            for (int d = 0; d < 128; d += 4) {
                float4 av[4], bv[2];
#pragma unroll
                for (int r = 0; r < 4; r++)
                    av[r] = *(const float4*)&sK[(t_hi + 16 * r) * SKT + d];
                bv[0] = *(const float4*)&sS[t_lo * SKT + d];
                bv[1] = *(const float4*)&sS[(t_lo + 16) * SKT + d];
#pragma unroll
                for (int r = 0; r < 4; r++) {
                    acc[r][0] += dot4(av[r], bv[0]);
                    acc[r][1] += dot4(av[r], bv[1]);
                }
            }
#pragma unroll
            for (int r = 0; r < 4; r++) {
                int i = t_hi + 16 * r;
                sKS[i * 36 + t_lo] = acc[r][0];
                sKS[i * 36 + t_lo + 16] = acc[r][1];
            }
        }
        __syncthreads();

        // mid = Tv - Tg @ KS
        {
            float acc[4][2];
#pragma unroll
            for (int r = 0; r < 4; r++) { acc[r][0] = 0.f; acc[r][1] = 0.f; }
            for (int j = 0; j < 64; j++) {
                float b0 = sKS[j * 36 + t_lo];
                float b1 = sKS[j * 36 + t_lo + 16];
#pragma unroll
                for (int r = 0; r < 4; r++) {
                    float a = sTg[(t_hi + 16 * r) * 68 + j];
                    acc[r][0] += a * b0;
                    acc[r][1] += a * b1;
                }
            }
#pragma unroll
            for (int r = 0; r < 4; r++) {
                int i = t_hi + 16 * r;
                sMid[i * 36 + t_lo] = sTv[i * 36 + t_lo] - acc[r][0];
                sMid[i * 36 + t_lo + 16] = sTv[i * 36 + t_lo + 16] - acc[r][1];
            }
        }
        __syncthreads();

        // O = gamma_i * (Q @ S^T) + attn @ mid
        {
            float acc1[4][2], acc2[4][2];
#pragma unroll
            for (int r = 0; r < 4; r++) {
                acc1[r][0] = acc1[r][1] = 0.f;
                acc2[r][0] = acc2[r][1] = 0.f;
            }
            for (int d = 0; d < 128; d += 4) {
                float4 av[4], bv[2];
#pragma unroll
                for (int r = 0; r < 4; r++)
                    av[r] = *(const float4*)&sQ[(t_hi + 16 * r) * SKT + d];
                bv[0] = *(const float4*)&sS[t_lo * SKT + d];
                bv[1] = *(const float4*)&sS[(t_lo + 16) * SKT + d];
#pragma unroll
                for (int r = 0; r < 4; r++) {
                    acc1[r][0] += dot4(av[r], bv[0]);
                    acc1[r][1] += dot4(av[r], bv[1]);
                }
            }
            for (int j = 0; j < 64; j++) {
                float b0 = sMid[j * 36 + t_lo];
                float b1 = sMid[j * 36 + t_lo + 16];
#pragma unroll
                for (int r = 0; r < 4; r++) {
                    float a = sAt[(t_hi + 16 * r) * 68 + j];
                    acc2[r][0] += a * b0;
                    acc2[r][1] += a * b1;
                }
            }
#pragma unroll
            for (int r = 0; r < 4; r++) {
                int i = t_hi + 16 * r;
                float g = sgam[i];
                size_t go = (((size_t)(b * Lq + l0 + i)) * Hq + h) * Dh + dv0;
                o[go + t_lo] = g * acc1[r][0] + acc2[r][0];
                o[go + t_lo + 16] = g * acc1[r][1] + acc2[r][1];
            }
        }
        __syncthreads();

        // S = gammaC * S + (mid_i * gCr_i)^T @ K
        {
            const int dkb = t_lo * 8;
            float acc[2][8];
#pragma unroll
            for (int r = 0; r < 2; r++)
#pragma unroll
                for (int c = 0; c < 8; c++) acc[r][c] = 0.f;
            for (int i = 0; i < 64; i++) {
                float gc = sgCr[i];
                float a0 = sMid[i * 36 + t_hi] * gc;
                float a1 = sMid[i * 36 + t_hi + 16] * gc;
                float4 k0 = *(const float4*)&sK[i * SKT + dkb];
                float4 k1 = *(const float4*)&sK[i * SKT + dkb + 4];
                acc[0][0] += a0 * k0.x; acc[0][1] += a0 * k0.y;
                acc[0][2] += a0 * k0.z; acc[0][3] += a0 * k0.w;
                acc[0][4] += a0 * k1.x; acc[0][5] += a0 * k1.y;
                acc[0][6] += a0 * k1.z; acc[0][7] += a0 * k1.w;
                acc[1][0] += a1 * k0.x; acc[1][1] += a1 * k0.y;
                acc[1][2] += a1 * k0.z; acc[1][3] += a1 * k0.w;
                acc[1][4] += a1 * k1.x; acc[1][5] += a1 * k1.y;
                acc[1][6] += a1 * k1.z; acc[1][7] += a1 * k1.w;
            }
#pragma unroll
            for (int r = 0; r < 2; r++) {
                int dv = t_hi + 16 * r;
#pragma unroll
                for (int c = 0; c < 8; c++) {
                    float* p = &sS[dv * SKT + dkb + c];
                    *p = gammaC * *p + acc[r][c];
                }
            }
        }
        __syncthreads();
    }

    for (int idx = tid; idx < 32 * 128; idx += 256) {
        int dv = idx >> 7, dk = idx & 127;
        Sout[((size_t)bh * 128 + dv0 + dv) * 128 + dk] = sS[dv * SKT + dk];
    }
}

// ---------------- RMSNorm + gate (silu) -> fp16 ----------------
__global__ void gate_kernel(const float* __restrict__ o, const float* __restrict__ proj,
                            const float* __restrict__ norm_w,
                            __half* __restrict__ oh)
{
    const size_t base = (size_t)blockIdx.x * Dh + threadIdx.x;
    const size_t row = blockIdx.x >> 4;
    const size_t inner = (size_t)(blockIdx.x & 15) * Dh + threadIdx.x;
    float ov = o[base];
    float s = ov * ov;
#pragma unroll
    for (int off = 16; off > 0; off >>= 1) s += __shfl_xor_sync(0xffffffffu, s, off);
    __shared__ float sh[4];
    const int wid = threadIdx.x >> 5;
    if ((threadIdx.x & 31) == 0) sh[wid] = s;
    __syncthreads();
    float mean = (sh[0] + sh[1] + sh[2] + sh[3]) * (1.f / 128.f);
    float rs = rsqrtf(mean + EPSq);
    float gv = proj[row * (4 * Dq) + 3 * Dq + inner];
    float sig = gv / (1.f + expf(-gv));
    float val = ov * rs * norm_w[threadIdx.x] * sig;
    oh[base] = __float2half_rn(val);
}

// ---------------- launch ----------------
extern "C" void kernel_launch(void* const* d_in, const int* in_sizes, int n_in,
                              void* d_out, int out_size)
{
    const float* x = (const float*)d_in[0];
    const float* Wq = (const float*)d_in[1];
    const float* Wk = (const float*)d_in[2];
    const float* Wv = (const float*)d_in[3];
    const float* Wb = (const float*)d_in[4];
    const float* Wa = (const float*)d_in[5];
    const float* A_log = (const float*)d_in[6];
    const float* dt_bias = (const float*)d_in[7];
    const float* conv_q = (const float*)d_in[8];
    const float* conv_k = (const float*)d_in[9];
    const float* conv_v = (const float*)d_in[10];
    const float* Wg = (const float*)d_in[11];
    const float* norm_w = (const float*)d_in[12];
    const float* Wo = (const float*)d_in[13];
    const float* S0 = (const float*)d_in[14];

    float* out = (float*)d_out;
    float* Sout = out + (size_t)BLD;

    float *proj, *obuf, *qn, *kn, *vn, *beta, *gdec;
    float *Tg, *At, *Tv, *Gams, *GamC;
    __half *xh, *whi;
    cudaGetSymbolAddress((void**)&proj, g_proj);
    cudaGetSymbolAddress((void**)&obuf, g_obuf);
    cudaGetSymbolAddress((void**)&qn, g_qn);
    cudaGetSymbolAddress((void**)&kn, g_kn);
    cudaGetSymbolAddress((void**)&vn, g_vn);
    cudaGetSymbolAddress((void**)&beta, g_beta);
    cudaGetSymbolAddress((void**)&gdec, g_gdec);
    cudaGetSymbolAddress((void**)&Tg, g_Tg);
    cudaGetSymbolAddress((void**)&At, g_At);
    cudaGetSymbolAddress((void**)&Tv, g_Tv);
    cudaGetSymbolAddress((void**)&Gams, g_Gams);
    cudaGetSymbolAddress((void**)&GamC, g_GamC);
    cudaGetSymbolAddress((void**)&xh, g_xh);
    cudaGetSymbolAddress((void**)&whi, g_whi);

    cudaFuncSetAttribute(scan_kernel, cudaFuncAttributeMaxDynamicSharedMemorySize,
                         SCAN_SMEM_BYTES);
    cudaFuncSetAttribute(prep_kernel, cudaFuncAttributeMaxDynamicSharedMemorySize,
                         PREP_SMEM_BYTES);
    cudaFuncSetAttribute(hmma_gemm, cudaFuncAttributeMaxDynamicSharedMemorySize,
                         GEMM_SMEM_BYTES);

    const size_t WSZ = (size_t)Dq * Dq;

    cast_f16<<<BLD / 1024, 256>>>((const float4*)x, (__half2*)xh);
    W4 w4 = { (const float4*)Wq, (const float4*)Wk, (const float4*)Wv, (const float4*)Wg };
    cast4_f16<<<4 * WBLK, 256>>>(w4, (__half2*)whi);

    // merged projection GEMM (pure fp16, 32 chunks)
    dim3 pgrid(BLq / 128, 4 * Dq / 128);
    hmma_gemm<<<pgrid, 256, GEMM_SMEM_BYTES>>>(xh, whi, proj, 4 * Dq);

    betag_gemm<<<BLq / 16, 256>>>(x, Wb, Wa, A_log, dt_bias, beta, gdec);

    conv_kernel<<<(BLq / 8) * Hq, 128>>>(proj, conv_q, conv_k, conv_v, qn, kn, vn);

    prep_kernel<<<NCHK, 256, PREP_SMEM_BYTES>>>(qn, kn, vn, beta, gdec,
                                                Tg, At, Tv, Gams, GamC);

    scan_kernel<<<Bq * Hq * 4, 256, SCAN_SMEM_BYTES>>>(qn, kn, Tg, At, Tv, Gams,
                                                       GamC, S0, obuf, Sout);

    gate_kernel<<<BLq * Hq, 128>>>(obuf, proj, norm_w, xh);

    cast_f16<<<WSZ / 1024, 256>>>((const float4*)Wo, (__half2*)(whi + 4 * WSZ));
    dim3 ogrid(BLq / 128, Dq / 128);
    hmma_gemm<<<ogrid, 256, GEMM_SMEM_BYTES>>>(xh, whi + 4 * WSZ, out, Dq);
}